// round 11
// baseline (speedup 1.0000x reference)
#include <cuda_runtime.h>
#include <cuda_bf16.h>
#include <cstdint>

// Problem constants
#define Bq 4
#define Sq 8192
#define Fq 32
#define Dq 512
#define Hq 8
#define Lq 4
#define FDq 128
#define WINq 256
#define CFq 4
#define HDq 64
#define NTq (Bq * Sq)          // 32768 tokens
#define NBq (Sq / WINq)        // 32 windows
#define NCq (Sq / CFq)         // 2048 compressed steps per batch

// -------------------- scratch (device globals; no allocation allowed) -----
__device__ float g_cat[NTq * 2 * FDq];
__device__ float g_h  [NTq * Dq];
__device__ float g_mem[NTq * Dq];
__device__ float g_qkv[NTq * 3 * Dq];
__device__ float g_ap [NTq * Dq];
__device__ float g_a  [NTq * Dq];
__device__ float g_gu [NTq * 2 * Dq];
__device__ float g_c  [Bq * NCq * Dq];
__device__ float g_c2 [Bq * NCq * Dq];
__device__ float g_wc [CFq * Dq * Dq];         // conv weight^T [512][2048]
__device__ float g_wqkvT[Lq * 3 * Dq * Dq];    // per-layer [1536][512]
__device__ float g_bqkv [Lq * 3 * Dq];
__device__ float g_wguT [Lq * 2 * Dq * 2 * Dq];// per-layer [1024][1024]
__device__ float g_bgu  [Lq * 2 * Dq];
__device__ float g_woT  [Lq * Dq * Dq];        // per-layer [512][512]
__device__ float g_wembT[2 * FDq * Dq];        // [512][256]

// ==================== helpers =============================================
__device__ __forceinline__ uint32_t smem_u32(const void* p) {
    uint32_t a;
    asm("{ .reg .u64 t; cvta.to.shared.u64 t, %1; cvt.u32.u64 %0, t; }"
        : "=r"(a) : "l"(p));
    return a;
}
__device__ __forceinline__ uint32_t f2tf(float f) {
    uint32_t u;
    asm("cvt.rna.tf32.f32 %0, %1;" : "=r"(u) : "f"(f));
    return u;
}
__device__ __forceinline__ float roundtf(float f) {
    return __uint_as_float(f2tf(f));
}
__device__ __forceinline__ void mma_tf32(float* d, const uint32_t* a,
                                         const uint32_t* b) {
    asm volatile(
        "mma.sync.aligned.m16n8k8.row.col.f32.tf32.tf32.f32 "
        "{%0,%1,%2,%3}, {%4,%5,%6,%7}, {%8,%9}, {%0,%1,%2,%3};"
        : "+f"(d[0]), "+f"(d[1]), "+f"(d[2]), "+f"(d[3])
        : "r"(a[0]), "r"(a[1]), "r"(a[2]), "r"(a[3]), "r"(b[0]), "r"(b[1]));
}
__device__ __forceinline__ void cpa16(uint32_t dst, const float* src) {
    asm volatile("cp.async.cg.shared.global [%0], [%1], 16;"
                 :: "r"(dst), "l"(src));
}
__device__ __forceinline__ void ldsm4(uint32_t* r, uint32_t addr) {
    asm volatile("ldmatrix.sync.aligned.m8n8.x4.shared.b16 {%0,%1,%2,%3}, [%4];"
                 : "=r"(r[0]), "=r"(r[1]), "=r"(r[2]), "=r"(r[3]) : "r"(addr));
}
__device__ __forceinline__ float warp_sum(float v) {
#pragma unroll
    for (int o = 16; o > 0; o >>= 1)
        v += __shfl_xor_sync(0xffffffffu, v, o);
    return v;
}
#define CPA_COMMIT() asm volatile("cp.async.commit_group;" ::: "memory")
#define CPA_WAIT1()  asm volatile("cp.async.wait_group 1;" ::: "memory")

// ==================== tf32 tensor-core GEMM ===============================
// C[M,N] = A[M,K] @ B[K,N] + bias, B transposed ([N][K] k-major).
// *** CTA tile 256x128 (25% less L2 traffic than 128x128) ***
// 512 threads / 16 warps (warpM 0..7, warpN 0..1); per-warp 32x64 tile
// identical to prior rounds (same mma order => identical numerics).
// K-chunk 32, 3 stages, single barrier per chunk (R9 pattern), 1 CTA/SM.
#define ASTR 36
#define AST_W (256 * ASTR)          // 9216 words per A stage
#define BST_W (128 * ASTR)          // 4608 words per B stage
#define SMEM_TC ((3 * AST_W + 3 * BST_W) * 4)   // 165888 bytes

__global__ __launch_bounds__(512, 1)
void gemm_tc_kernel(const float* __restrict__ A0, const float* __restrict__ A1,
                    int scChunks, int lda0, int lda1,
                    const float* __restrict__ BmT, int ldbt,
                    const float* __restrict__ bias,
                    float* __restrict__ C, int ldc, int nChunks, int roundOut) {
    extern __shared__ float smem[];
    uint32_t sbase = smem_u32(smem);

    int tid = threadIdx.x;
    int lane = tid & 31, wid = tid >> 5;
    int warpM = wid & 7, warpN = wid >> 3;
    int g = lane >> 2, c4 = lane & 3;
    int rowbase = blockIdx.y * 256;
    int colbase = blockIdx.x * 128;

    int rowA = warpM * 32 + (lane & 15);
    uint32_t aOff = (uint32_t)(rowA * ASTR + (lane >> 4) * 4) * 4;
    int rowB = warpN * 64 + ((lane >> 4) << 3) + (lane & 7);
    uint32_t bOff = (uint32_t)(rowB * ASTR + ((lane >> 3) & 1) * 4) * 4;

    float acc[2][8][4];
#pragma unroll
    for (int mi = 0; mi < 2; mi++)
#pragma unroll
        for (int nj = 0; nj < 8; nj++)
#pragma unroll
            for (int r = 0; r < 4; r++) acc[mi][nj][r] = 0.f;

#define ISSUE(ch) do { \
        int _st = (ch) % 3; \
        uint32_t _sa = sbase + (uint32_t)(_st * AST_W) * 4; \
        uint32_t _sb = sbase + (uint32_t)(3 * AST_W + _st * BST_W) * 4; \
        const float* Ap; int kc, lda; \
        if ((ch) < scChunks) { Ap = A0; kc = (ch); lda = lda0; } \
        else { Ap = A1; kc = (ch) - scChunks; lda = lda1; } \
        _Pragma("unroll") \
        for (int i = 0; i < 4; i++) { \
            int id = tid + i * 512; int r = id >> 3, sg = id & 7; \
            cpa16(_sa + (uint32_t)(r * ASTR + sg * 4) * 4, \
                  Ap + (size_t)(rowbase + r) * lda + kc * 32 + sg * 4); \
        } \
        _Pragma("unroll") \
        for (int i = 0; i < 2; i++) { \
            int id = tid + i * 512; int r = id >> 3, sg = id & 7; \
            cpa16(_sb + (uint32_t)(r * ASTR + sg * 4) * 4, \
                  BmT + (size_t)(colbase + r) * ldbt + (ch) * 32 + sg * 4); \
        } \
    } while (0)

    ISSUE(0); CPA_COMMIT();
    ISSUE(1); CPA_COMMIT();

    for (int ch = 0; ch < nChunks; ch++) {
        int st = ch % 3;
        CPA_WAIT1();               // chunk ch resident
        __syncthreads();           // all warps done with chunk ch-1's stage
        if (ch + 2 < nChunks) ISSUE(ch + 2);   // writes stage (ch-1)%3 — safe
        CPA_COMMIT();

        uint32_t aBase = sbase + (uint32_t)(st * AST_W) * 4 + aOff;
        uint32_t bBase = sbase + (uint32_t)(3 * AST_W + st * BST_W) * 4 + bOff;
#pragma unroll
        for (int kk = 0; kk < 4; kk++) {
            uint32_t af[2][4], bf[4][4];
            ldsm4(af[0], aBase + kk * 32);
            ldsm4(af[1], aBase + 16 * ASTR * 4 + kk * 32);
#pragma unroll
            for (int pr = 0; pr < 4; pr++)
                ldsm4(bf[pr], bBase + pr * 16 * ASTR * 4 + kk * 32);
#pragma unroll
            for (int mi = 0; mi < 2; mi++)
#pragma unroll
                for (int pr = 0; pr < 4; pr++) {
                    mma_tf32(acc[mi][2 * pr],     af[mi], &bf[pr][0]);
                    mma_tf32(acc[mi][2 * pr + 1], af[mi], &bf[pr][2]);
                }
        }
    }
#undef ISSUE

    // ---- epilogue: bias (+ optional tf32 rounding) + store ----
#pragma unroll
    for (int mi = 0; mi < 2; mi++) {
        int r0 = rowbase + warpM * 32 + mi * 16 + g;
#pragma unroll
        for (int nj = 0; nj < 8; nj++) {
            int col = colbase + warpN * 64 + nj * 8 + 2 * c4;
            float b0 = bias[col], b1 = bias[col + 1];
            float o0 = acc[mi][nj][0] + b0, o1 = acc[mi][nj][1] + b1;
            float o2 = acc[mi][nj][2] + b0, o3 = acc[mi][nj][3] + b1;
            if (roundOut) {
                o0 = roundtf(o0); o1 = roundtf(o1);
                o2 = roundtf(o2); o3 = roundtf(o3);
            }
            *(float2*)(C + (size_t)r0 * ldc + col) = make_float2(o0, o1);
            *(float2*)(C + (size_t)(r0 + 8) * ldc + col) = make_float2(o2, o3);
        }
    }
}

static inline void launch_tc(const float* A0, const float* A1, int sc,
                             int lda0, int lda1, const float* BmT, int ldbt,
                             const float* bias, float* C, int ldc,
                             int M, int N, int K, int roundOut) {
    dim3 grid(N / 128, M / 256);
    gemm_tc_kernel<<<grid, 512, SMEM_TC>>>(A0, A1, sc, lda0, lda1, BmT, ldbt,
                                           bias, C, ldc, K / 32, roundOut);
}

// ==================== tensor-core windowed attention ======================
// (unchanged from R10 — passing)
#define KSTR 68
#define VSTR 72
#define PSTR 36
#define SMA_K(s) ((s) * 32 * KSTR)
#define SMA_VB   (3 * 32 * KSTR)
#define SMA_V(s) (SMA_VB + (s) * 32 * VSTR)
#define SMA_P    (3 * 32 * KSTR + 3 * 32 * VSTR)
#define SMEM_ATT ((SMA_P + 256 * PSTR) * 4)

__global__ __launch_bounds__(256)
void attn_tc_kernel(const float* __restrict__ qkv, float* __restrict__ out) {
    extern __shared__ float sm[];
    int blk = blockIdx.x, head = blockIdx.y, b = blockIdx.z;
    int tid = threadIdx.x, lane = tid & 31, w = tid >> 5;
    int g = lane >> 2, c4 = lane & 3;
    const int LD = 3 * Dq;
    const int qbase = b * Sq + blk * WINq;
    uint32_t sbase = smem_u32(sm);

    {
        const float4* src = (const float4*)(qkv + (size_t)(qbase + tid) * LD + head * HDq);
        float* dst = sm + tid * KSTR;
#pragma unroll
        for (int j = 0; j < 16; j++) *(float4*)(dst + j * 4) = src[j];
    }
    __syncthreads();
    uint32_t qf[2][8][4];
#pragma unroll
    for (int mi = 0; mi < 2; mi++) {
        int r = w * 32 + mi * 16 + g;
#pragma unroll
        for (int kt = 0; kt < 8; kt++) {
            qf[mi][kt][0] = __float_as_uint(sm[r * KSTR + kt * 8 + c4]);
            qf[mi][kt][1] = __float_as_uint(sm[(r + 8) * KSTR + kt * 8 + c4]);
            qf[mi][kt][2] = __float_as_uint(sm[r * KSTR + kt * 8 + c4 + 4]);
            qf[mi][kt][3] = __float_as_uint(sm[(r + 8) * KSTR + kt * 8 + c4 + 4]);
        }
    }
    __syncthreads();

    float o[2][8][4];
#pragma unroll
    for (int mi = 0; mi < 2; mi++)
#pragma unroll
        for (int nt = 0; nt < 8; nt++)
#pragma unroll
            for (int j = 0; j < 4; j++) o[mi][nt][j] = 0.f;
    float m_run[2][2] = {{-1e30f, -1e30f}, {-1e30f, -1e30f}};
    float l_run[2][2] = {{0.f, 0.f}, {0.f, 0.f}};

    const int ktok0 = b * Sq + (blk - 1) * WINq;
    const int c0 = (blk == 0) ? 8 : 0;

#define AISSUE(ci) do { \
        int _st = (ci) % 3; \
        int r = tid >> 3, sg = tid & 7; \
        const float* kv = qkv + (size_t)(ktok0 + (ci) * 32 + r) * LD + head * HDq; \
        uint32_t kd = sbase + (uint32_t)(SMA_K(_st) + r * KSTR) * 4; \
        uint32_t vd = sbase + (uint32_t)(SMA_V(_st) + r * VSTR) * 4; \
        cpa16(kd + sg * 16,        kv + Dq + sg * 4); \
        cpa16(kd + (sg + 8) * 16,  kv + Dq + (sg + 8) * 4); \
        cpa16(vd + sg * 16,        kv + 2 * Dq + sg * 4); \
        cpa16(vd + (sg + 8) * 16,  kv + 2 * Dq + (sg + 8) * 4); \
    } while (0)

    AISSUE(c0);     CPA_COMMIT();
    AISSUE(c0 + 1); CPA_COMMIT();

    float* Pt = sm + SMA_P;
    for (int ci = c0; ci < 16; ci++) {
        CPA_WAIT1();
        __syncthreads();
        if (ci + 2 < 16) AISSUE(ci + 2);
        CPA_COMMIT();
        const float* Kt = sm + SMA_K(ci % 3);
        const float* Vt = sm + SMA_V(ci % 3);

#pragma unroll
        for (int mi = 0; mi < 2; mi++) {
            float s[4][4];
#pragma unroll
            for (int nt = 0; nt < 4; nt++)
#pragma unroll
                for (int j = 0; j < 4; j++) s[nt][j] = 0.f;
#pragma unroll
            for (int kt = 0; kt < 8; kt++) {
                uint32_t bb[4][2];
#pragma unroll
                for (int nt = 0; nt < 4; nt++) {
                    bb[nt][0] = __float_as_uint(Kt[(nt * 8 + g) * KSTR + kt * 8 + c4]);
                    bb[nt][1] = __float_as_uint(Kt[(nt * 8 + g) * KSTR + kt * 8 + c4 + 4]);
                }
#pragma unroll
                for (int nt = 0; nt < 4; nt++)
                    mma_tf32(s[nt], qf[mi][kt], bb[nt]);
            }
#pragma unroll
            for (int nt = 0; nt < 4; nt++)
#pragma unroll
                for (int j = 0; j < 4; j++) s[nt][j] *= 0.125f;

            float ml0 = s[0][0], ml1 = s[0][2];
#pragma unroll
            for (int nt = 0; nt < 4; nt++) {
                ml0 = fmaxf(ml0, fmaxf(s[nt][0], s[nt][1]));
                ml1 = fmaxf(ml1, fmaxf(s[nt][2], s[nt][3]));
            }
            ml0 = fmaxf(ml0, __shfl_xor_sync(0xffffffffu, ml0, 1));
            ml0 = fmaxf(ml0, __shfl_xor_sync(0xffffffffu, ml0, 2));
            ml1 = fmaxf(ml1, __shfl_xor_sync(0xffffffffu, ml1, 1));
            ml1 = fmaxf(ml1, __shfl_xor_sync(0xffffffffu, ml1, 2));

            float mn0 = fmaxf(m_run[mi][0], ml0);
            float mn1 = fmaxf(m_run[mi][1], ml1);
            float sc0 = __expf(m_run[mi][0] - mn0);
            float sc1 = __expf(m_run[mi][1] - mn1);
            m_run[mi][0] = mn0; m_run[mi][1] = mn1;

            float ps0 = 0.f, ps1 = 0.f;
#pragma unroll
            for (int nt = 0; nt < 4; nt++) {
                s[nt][0] = roundtf(__expf(s[nt][0] - mn0)); ps0 += s[nt][0];
                s[nt][1] = roundtf(__expf(s[nt][1] - mn0)); ps0 += s[nt][1];
                s[nt][2] = roundtf(__expf(s[nt][2] - mn1)); ps1 += s[nt][2];
                s[nt][3] = roundtf(__expf(s[nt][3] - mn1)); ps1 += s[nt][3];
            }
            ps0 += __shfl_xor_sync(0xffffffffu, ps0, 1);
            ps0 += __shfl_xor_sync(0xffffffffu, ps0, 2);
            ps1 += __shfl_xor_sync(0xffffffffu, ps1, 1);
            ps1 += __shfl_xor_sync(0xffffffffu, ps1, 2);
            l_run[mi][0] = l_run[mi][0] * sc0 + ps0;
            l_run[mi][1] = l_run[mi][1] * sc1 + ps1;

#pragma unroll
            for (int nt = 0; nt < 8; nt++) {
                o[mi][nt][0] *= sc0; o[mi][nt][1] *= sc0;
                o[mi][nt][2] *= sc1; o[mi][nt][3] *= sc1;
            }
            int r = w * 32 + mi * 16 + g;
#pragma unroll
            for (int nt = 0; nt < 4; nt++) {
                *(float2*)&Pt[r * PSTR + nt * 8 + 2 * c4] = make_float2(s[nt][0], s[nt][1]);
                *(float2*)&Pt[(r + 8) * PSTR + nt * 8 + 2 * c4] = make_float2(s[nt][2], s[nt][3]);
            }
        }
        __syncwarp();

#pragma unroll
        for (int kt = 0; kt < 4; kt++) {
            uint32_t pa[2][4];
#pragma unroll
            for (int mi = 0; mi < 2; mi++) {
                int r = w * 32 + mi * 16 + g;
                pa[mi][0] = __float_as_uint(Pt[r * PSTR + kt * 8 + c4]);
                pa[mi][1] = __float_as_uint(Pt[(r + 8) * PSTR + kt * 8 + c4]);
                pa[mi][2] = __float_as_uint(Pt[r * PSTR + kt * 8 + c4 + 4]);
                pa[mi][3] = __float_as_uint(Pt[(r + 8) * PSTR + kt * 8 + c4 + 4]);
            }
#pragma unroll
            for (int nt = 0; nt < 8; nt++) {
                uint32_t bv[2];
                bv[0] = __float_as_uint(Vt[(kt * 8 + c4) * VSTR + nt * 8 + g]);
                bv[1] = __float_as_uint(Vt[(kt * 8 + c4 + 4) * VSTR + nt * 8 + g]);
                mma_tf32(o[0][nt], pa[0], bv);
                mma_tf32(o[1][nt], pa[1], bv);
            }
        }
    }
#undef AISSUE

#pragma unroll
    for (int mi = 0; mi < 2; mi++) {
        float inv0 = 1.f / l_run[mi][0];
        float inv1 = 1.f / l_run[mi][1];
        int r = qbase + w * 32 + mi * 16 + g;
#pragma unroll
        for (int nt = 0; nt < 8; nt++) {
            int col = head * HDq + nt * 8 + 2 * c4;
            *(float2*)&out[(size_t)r * Dq + col] =
                make_float2(roundtf(o[mi][nt][0] * inv0), roundtf(o[mi][nt][1] * inv0));
            *(float2*)&out[(size_t)(r + 8) * Dq + col] =
                make_float2(roundtf(o[mi][nt][2] * inv1), roundtf(o[mi][nt][3] * inv1));
        }
    }
}

// -------------------- bulk weight packing (all layers, once) --------------
__global__ void pack3_all_kernel(const float* __restrict__ Wq, const float* __restrict__ Wk,
                                 const float* __restrict__ Wv, const float* __restrict__ bq,
                                 const float* __restrict__ bk, const float* __restrict__ bv,
                                 float* __restrict__ BpT, float* __restrict__ bp) {
    int i = blockIdx.x * 256 + threadIdx.x;
    if (i < Lq * Dq * Dq) {
        int l = i >> 18;
        int r = i & (Dq * Dq - 1);
        int n = r >> 9, k = r & 511;
        size_t so = (size_t)l * Dq * Dq + (size_t)k * Dq + n;
        float* dst = BpT + (size_t)l * 3 * Dq * Dq;
        dst[(size_t)n * Dq + k] = roundtf(Wq[so]);
        dst[(size_t)(Dq + n) * Dq + k] = roundtf(Wk[so]);
        dst[(size_t)(2 * Dq + n) * Dq + k] = roundtf(Wv[so]);
    }
    if (i < Lq * Dq) {
        int l = i >> 9, n = i & 511;
        bp[l * 3 * Dq + n] = bq[l * Dq + n];
        bp[l * 3 * Dq + Dq + n] = bk[l * Dq + n];
        bp[l * 3 * Dq + 2 * Dq + n] = bv[l * Dq + n];
    }
}
__global__ void pack2_all_kernel(const float* __restrict__ Wg, const float* __restrict__ Wu,
                                 const float* __restrict__ bg, const float* __restrict__ bu,
                                 float* __restrict__ BpT, float* __restrict__ bp) {
    int i = blockIdx.x * 256 + threadIdx.x;
    if (i < Lq * 2 * Dq * Dq) {
        int l = i >> 19;
        int r = i & (2 * Dq * Dq - 1);
        int n = r >> 10, k = r & 1023;
        size_t so = (size_t)l * 2 * Dq * Dq + (size_t)k * Dq + n;
        float* dst = BpT + (size_t)l * 2 * Dq * 2 * Dq;
        dst[(size_t)n * 2 * Dq + k] = roundtf(Wg[so]);
        dst[(size_t)(Dq + n) * 2 * Dq + k] = roundtf(Wu[so]);
    }
    if (i < Lq * Dq) {
        int l = i >> 9, n = i & 511;
        bp[l * 2 * Dq + n] = bg[l * Dq + n];
        bp[l * 2 * Dq + Dq + n] = bu[l * Dq + n];
    }
}
__global__ void packo_all_kernel(const float* __restrict__ Wo, float* __restrict__ dst) {
    int i = blockIdx.x * 256 + threadIdx.x;
    if (i < Lq * Dq * Dq) {
        int l = i >> 18;
        int r = i & (Dq * Dq - 1);
        int n = r >> 9, k = r & 511;
        dst[(size_t)l * Dq * Dq + (size_t)n * Dq + k] =
            roundtf(Wo[(size_t)l * Dq * Dq + (size_t)k * Dq + n]);
    }
}
__global__ void roundcpy_t_kernel(const float* __restrict__ src,
                                  float* __restrict__ dst, int K, int N) {
    int i = blockIdx.x * 256 + threadIdx.x;
    if (i < K * N) {
        int n = i / K, k = i - n * K;
        dst[i] = roundtf(src[(size_t)k * N + n]);
    }
}
__global__ void convw_kernel(const float* __restrict__ w, float* __restrict__ wcT) {
    int i = blockIdx.x * 256 + threadIdx.x;
    if (i < CFq * Dq * Dq) {
        int o = i >> 11, r = i & 2047;
        int j = r >> 9, c = r & 511;
        wcT[i] = roundtf(w[(size_t)o * (Dq * CFq) + c * CFq + j]);
    }
}

// -------------------- embedding: cat = [x@W_feat + b_feat, emb[ts]] -------
__global__ __launch_bounds__(128)
void build_cat_kernel(const float* __restrict__ x, const int* __restrict__ ts,
                      const float* __restrict__ Wf, const float* __restrict__ bf,
                      const float* __restrict__ emb, float* __restrict__ cat) {
    int t = blockIdx.x;
    int d = threadIdx.x;
    __shared__ float xr[Fq];
    if (d < Fq) xr[d] = x[t * Fq + d];
    __syncthreads();
    float s = bf[d];
#pragma unroll
    for (int i = 0; i < Fq; i++) s += xr[i] * Wf[i * FDq + d];
    cat[t * 2 * FDq + d] = roundtf(s);
    cat[t * 2 * FDq + FDq + d] = roundtf(emb[ts[t] * FDq + d]);
}

// -------------------- fp32 SGEMM (small final projection only) ------------
#define BM 64
#define BN 64
#define BKq 16
__global__ __launch_bounds__(256)
void gemm_kernel(const float* __restrict__ A0,
                 const float* __restrict__ Bm, const float* __restrict__ bias,
                 float* __restrict__ C, int M, int N, int K) {
    __shared__ float As[BKq][BM];
    __shared__ float Bs[BKq][BN];
    int tid = threadIdx.x;
    int tx = tid & 15, ty = tid >> 4;
    int row0 = blockIdx.y * BM;
    int col0 = blockIdx.x * BN;
    float acc[4][4];
#pragma unroll
    for (int i = 0; i < 4; i++)
#pragma unroll
        for (int j = 0; j < 4; j++) acc[i][j] = 0.f;

    for (int k0 = 0; k0 < K; k0 += BKq) {
#pragma unroll
        for (int it = 0; it < 4; it++) {
            int idx = tid + it * 256;
            int m = idx >> 4, kk = idx & 15;
            int r = row0 + m;
            As[kk][m] = (r < M) ? A0[(size_t)r * K + k0 + kk] : 0.f;
        }
#pragma unroll
        for (int it = 0; it < 4; it++) {
            int idx = tid + it * 256;
            int kk = idx >> 6, n = idx & 63;
            int gn = col0 + n;
            Bs[kk][n] = (gn < N) ? Bm[(size_t)(k0 + kk) * N + gn] : 0.f;
        }
        __syncthreads();
#pragma unroll
        for (int kk = 0; kk < BKq; kk++) {
            float4 a4 = *reinterpret_cast<const float4*>(&As[kk][ty * 4]);
            float4 b4 = *reinterpret_cast<const float4*>(&Bs[kk][tx * 4]);
            float a[4] = {a4.x, a4.y, a4.z, a4.w};
            float b[4] = {b4.x, b4.y, b4.z, b4.w};
#pragma unroll
            for (int i = 0; i < 4; i++)
#pragma unroll
                for (int j = 0; j < 4; j++) acc[i][j] += a[i] * b[j];
        }
        __syncthreads();
    }
#pragma unroll
    for (int i = 0; i < 4; i++) {
        int r = row0 + ty * 4 + i;
        if (r >= M) continue;
#pragma unroll
        for (int j = 0; j < 4; j++) {
            int cc = col0 + tx * 4 + j;
            if (cc < N) C[(size_t)r * N + cc] = acc[i][j] + bias[cc];
        }
    }
}

// -------------------- fused gate + memory + LayerNorm (warp/token) --------
__global__ __launch_bounds__(256)
void gate_ln_kernel(const float* __restrict__ a, const float* __restrict__ gu,
                    float* __restrict__ mem,
                    const float* __restrict__ g, const float* __restrict__ bta,
                    float* __restrict__ hout, int first) {
    int w = threadIdx.x >> 5, lane = threadIdx.x & 31;
    int t = blockIdx.x * 8 + w;
    size_t base = (size_t)t * Dq;
    size_t gbase = (size_t)t * 2 * Dq;

    float y[16];
    float sum = 0.f;
#pragma unroll
    for (int j = 0; j < 4; j++) {
        int d = (lane + 32 * j) * 4;
        float4 gg = *(const float4*)&gu[gbase + d];
        float4 uu = *(const float4*)&gu[gbase + Dq + d];
        float4 av = *(const float4*)&a[base + d];
        float4 mm = first ? make_float4(0.f, 0.f, 0.f, 0.f)
                          : *(const float4*)&mem[base + d];
        float g0 = 1.f / (1.f + __expf(-gg.x));
        float g1 = 1.f / (1.f + __expf(-gg.y));
        float g2 = 1.f / (1.f + __expf(-gg.z));
        float g3 = 1.f / (1.f + __expf(-gg.w));
        float nm0 = g0 * uu.x + (1.f - g0) * mm.x;
        float nm1 = g1 * uu.y + (1.f - g1) * mm.y;
        float nm2 = g2 * uu.z + (1.f - g2) * mm.z;
        float nm3 = g3 * uu.w + (1.f - g3) * mm.w;
        *(float4*)&mem[base + d] = make_float4(roundtf(nm0), roundtf(nm1),
                                               roundtf(nm2), roundtf(nm3));
        y[j * 4 + 0] = av.x + nm0;
        y[j * 4 + 1] = av.y + nm1;
        y[j * 4 + 2] = av.z + nm2;
        y[j * 4 + 3] = av.w + nm3;
        sum += y[j * 4] + y[j * 4 + 1] + y[j * 4 + 2] + y[j * 4 + 3];
    }
    float mean = warp_sum(sum) * (1.f / Dq);
    float vs = 0.f;
#pragma unroll
    for (int i = 0; i < 16; i++) {
        float dv = y[i] - mean;
        vs += dv * dv;
    }
    float rs = rsqrtf(warp_sum(vs) * (1.f / Dq) + 1e-5f);
#pragma unroll
    for (int j = 0; j < 4; j++) {
        int d = (lane + 32 * j) * 4;
        float4 gv = *(const float4*)&g[d];
        float4 bv = *(const float4*)&bta[d];
        float4 ov;
        ov.x = roundtf((y[j * 4 + 0] - mean) * rs * gv.x + bv.x);
        ov.y = roundtf((y[j * 4 + 1] - mean) * rs * gv.y + bv.y);
        ov.z = roundtf((y[j * 4 + 2] - mean) * rs * gv.z + bv.z);
        ov.w = roundtf((y[j * 4 + 3] - mean) * rs * gv.w + bv.w);
        *(float4*)&hout[base + d] = ov;
    }
}

// -------------------- double LayerNorm (warp/token) -----------------------
__global__ __launch_bounds__(256)
void double_ln_kernel(const float* __restrict__ c, const float* __restrict__ cg,
                      const float* __restrict__ cb, const float* __restrict__ og,
                      const float* __restrict__ ob, float* __restrict__ out) {
    int w = threadIdx.x >> 5, lane = threadIdx.x & 31;
    int t = blockIdx.x * 8 + w;
    size_t base = (size_t)t * Dq;

    float y[16];
    float sum = 0.f;
#pragma unroll
    for (int j = 0; j < 4; j++) {
        int d = (lane + 32 * j) * 4;
        float4 v = *(const float4*)&c[base + d];
        y[j * 4 + 0] = v.x; y[j * 4 + 1] = v.y;
        y[j * 4 + 2] = v.z; y[j * 4 + 3] = v.w;
        sum += v.x + v.y + v.z + v.w;
    }
    float mean = warp_sum(sum) * (1.f / Dq);
    float vs = 0.f;
#pragma unroll
    for (int i = 0; i < 16; i++) {
        float dv = y[i] - mean;
        vs += dv * dv;
    }
    float rs = rsqrtf(warp_sum(vs) * (1.f / Dq) + 1e-5f);

    float z[16];
    float sum2 = 0.f;
#pragma unroll
    for (int j = 0; j < 4; j++) {
        int d = (lane + 32 * j) * 4;
        float4 gv = *(const float4*)&cg[d];
        float4 bv = *(const float4*)&cb[d];
        z[j * 4 + 0] = (y[j * 4 + 0] - mean) * rs * gv.x + bv.x;
        z[j * 4 + 1] = (y[j * 4 + 1] - mean) * rs * gv.y + bv.y;
        z[j * 4 + 2] = (y[j * 4 + 2] - mean) * rs * gv.z + bv.z;
        z[j * 4 + 3] = (y[j * 4 + 3] - mean) * rs * gv.w + bv.w;
        sum2 += z[j * 4] + z[j * 4 + 1] + z[j * 4 + 2] + z[j * 4 + 3];
    }
    float mean2 = warp_sum(sum2) * (1.f / Dq);
    float vs2 = 0.f;
#pragma unroll
    for (int i = 0; i < 16; i++) {
        float dv = z[i] - mean2;
        vs2 += dv * dv;
    }
    float rs2 = rsqrtf(warp_sum(vs2) * (1.f / Dq) + 1e-5f);
#pragma unroll
    for (int j = 0; j < 4; j++) {
        int d = (lane + 32 * j) * 4;
        float4 gv = *(const float4*)&og[d];
        float4 bv = *(const float4*)&ob[d];
        float4 ov;
        ov.x = roundtf((z[j * 4 + 0] - mean2) * rs2 * gv.x + bv.x);
        ov.y = roundtf((z[j * 4 + 1] - mean2) * rs2 * gv.y + bv.y);
        ov.z = roundtf((z[j * 4 + 2] - mean2) * rs2 * gv.z + bv.z);
        ov.w = roundtf((z[j * 4 + 3] - mean2) * rs2 * gv.w + bv.w);
        *(float4*)&out[base + d] = ov;
    }
}

// ==========================================================================
extern "C" void kernel_launch(void* const* d_in, const int* in_sizes, int n_in,
                              void* d_out, int out_size) {
    const float* x       = (const float*)d_in[0];
    const int*   ts      = (const int*)d_in[1];
    const float* W_feat  = (const float*)d_in[2];
    const float* b_feat  = (const float*)d_in[3];
    const float* emb     = (const float*)d_in[4];
    const float* W_emb   = (const float*)d_in[5];
    const float* b_emb   = (const float*)d_in[6];
    const float* Wq      = (const float*)d_in[7];
    const float* bq      = (const float*)d_in[8];
    const float* Wk      = (const float*)d_in[9];
    const float* bk      = (const float*)d_in[10];
    const float* Wv      = (const float*)d_in[11];
    const float* bv      = (const float*)d_in[12];
    const float* Wo      = (const float*)d_in[13];
    const float* bo      = (const float*)d_in[14];
    const float* Wg      = (const float*)d_in[15];
    const float* bg      = (const float*)d_in[16];
    const float* Wu      = (const float*)d_in[17];
    const float* bu      = (const float*)d_in[18];
    const float* ln_g    = (const float*)d_in[19];
    const float* ln_b    = (const float*)d_in[20];
    const float* conv_w  = (const float*)d_in[21];
    const float* conv_b  = (const float*)d_in[22];
    const float* cn_g    = (const float*)d_in[23];
    const float* cn_b    = (const float*)d_in[24];
    const float* on_g    = (const float*)d_in[25];
    const float* on_b    = (const float*)d_in[26];
    const float* W_out   = (const float*)d_in[27];
    const float* b_out   = (const float*)d_in[28];
    float* out = (float*)d_out;

    float *cat, *h, *mem, *qkv, *ap, *a, *gu, *c, *c2, *wc;
    float *wqkvT, *bqkv, *wguT, *bgu, *woT, *wembT;
    cudaGetSymbolAddress((void**)&cat, g_cat);
    cudaGetSymbolAddress((void**)&h,   g_h);
    cudaGetSymbolAddress((void**)&mem, g_mem);
    cudaGetSymbolAddress((void**)&qkv, g_qkv);
    cudaGetSymbolAddress((void**)&ap,  g_ap);
    cudaGetSymbolAddress((void**)&a,   g_a);
    cudaGetSymbolAddress((void**)&gu,  g_gu);
    cudaGetSymbolAddress((void**)&c,   g_c);
    cudaGetSymbolAddress((void**)&c2,  g_c2);
    cudaGetSymbolAddress((void**)&wc,  g_wc);
    cudaGetSymbolAddress((void**)&wqkvT, g_wqkvT);
    cudaGetSymbolAddress((void**)&bqkv,  g_bqkv);
    cudaGetSymbolAddress((void**)&wguT,  g_wguT);
    cudaGetSymbolAddress((void**)&bgu,   g_bgu);
    cudaGetSymbolAddress((void**)&woT,   g_woT);
    cudaGetSymbolAddress((void**)&wembT, g_wembT);

    static int smem_set = 0;
    if (!smem_set) {
        cudaFuncSetAttribute(gemm_tc_kernel,
                             cudaFuncAttributeMaxDynamicSharedMemorySize, SMEM_TC);
        cudaFuncSetAttribute(attn_tc_kernel,
                             cudaFuncAttributeMaxDynamicSharedMemorySize, SMEM_ATT);
        smem_set = 1;
    }

    // 0. bulk weight pre-pack (all layers, 5 launches total)
    pack3_all_kernel<<<(Lq * Dq * Dq + 255) / 256, 256>>>(Wq, Wk, Wv, bq, bk, bv,
                                                          wqkvT, bqkv);
    pack2_all_kernel<<<(Lq * 2 * Dq * Dq + 255) / 256, 256>>>(Wg, Wu, bg, bu,
                                                              wguT, bgu);
    packo_all_kernel<<<(Lq * Dq * Dq + 255) / 256, 256>>>(Wo, woT);
    roundcpy_t_kernel<<<(2 * FDq * Dq + 255) / 256, 256>>>(W_emb, wembT, 2 * FDq, Dq);
    convw_kernel<<<(CFq * Dq * Dq + 255) / 256, 256>>>(conv_w, wc);

    // 1. embedding
    build_cat_kernel<<<NTq, 128>>>(x, ts, W_feat, b_feat, emb, cat);
    launch_tc(cat, cat, 8, 2 * FDq, 2 * FDq, wembT, 2 * FDq, b_emb, h, Dq,
              NTq, Dq, 2 * FDq, 1);

    // 2. layers (mem implicitly zero in layer 0)
    for (int l = 0; l < Lq; l++) {
        launch_tc(h, h, 16, Dq, Dq, wqkvT + (size_t)l * 3 * Dq * Dq, Dq,
                  bqkv + l * 3 * Dq, qkv, 3 * Dq, NTq, 3 * Dq, Dq, 1);

        attn_tc_kernel<<<dim3(NBq, Hq, Bq), 256, SMEM_ATT>>>(qkv, ap);

        launch_tc(ap, ap, 16, Dq, Dq, woT + (size_t)l * Dq * Dq, Dq,
                  bo + l * Dq, a, Dq, NTq, Dq, Dq, 1);

        if (l == 0)
            launch_tc(a, a, 16, Dq, Dq, wguT + (size_t)l * 2 * Dq * 2 * Dq, 2 * Dq,
                      bgu + l * 2 * Dq, gu, 2 * Dq, NTq, 2 * Dq, Dq, 0);
        else
            launch_tc(a, mem, 16, Dq, Dq, wguT + (size_t)l * 2 * Dq * 2 * Dq, 2 * Dq,
                      bgu + l * 2 * Dq, gu, 2 * Dq, NTq, 2 * Dq, 2 * Dq, 0);

        gate_ln_kernel<<<NTq / 8, 256>>>(a, gu, mem, ln_g + l * Dq,
                                         ln_b + l * Dq, h, l == 0);
    }

    // 3. temporal compression (conv as GEMM; weight transposed [512][2048])
    launch_tc(h, h, 64, CFq * Dq, CFq * Dq, wc, CFq * Dq, conv_b, c, Dq,
              Bq * NCq, Dq, CFq * Dq, 0);

    // 4. double LayerNorm
    double_ln_kernel<<<Bq * NCq / 8, 256>>>(c, cn_g, cn_b, on_g, on_b, c2);

    // 5. output projection (small: fp32 path)
    {
        dim3 grid((Fq + BN - 1) / BN, (Bq * NCq + BM - 1) / BM);
        gemm_kernel<<<grid, 256>>>(c2, W_out, b_out, out, Bq * NCq, Fq, Dq);
    }
}

// round 12
// speedup vs baseline: 1.0687x; 1.0687x over previous
#include <cuda_runtime.h>
#include <cuda_bf16.h>
#include <cstdint>

// Problem constants
#define Bq 4
#define Sq 8192
#define Fq 32
#define Dq 512
#define Hq 8
#define Lq 4
#define FDq 128
#define WINq 256
#define CFq 4
#define HDq 64
#define NTq (Bq * Sq)          // 32768 tokens
#define NBq (Sq / WINq)        // 32 windows
#define NCq (Sq / CFq)         // 2048 compressed steps per batch

// -------------------- scratch (device globals; no allocation allowed) -----
__device__ float g_cat[NTq * 2 * FDq];
__device__ float g_h  [NTq * Dq];
__device__ float g_mem[NTq * Dq];
__device__ float g_qkv[NTq * 3 * Dq];
__device__ float g_ap [NTq * Dq];
__device__ float g_a  [NTq * Dq];
__device__ float g_gu [NTq * 2 * Dq];
__device__ float g_c  [Bq * NCq * Dq];
__device__ float g_c2 [Bq * NCq * Dq];
__device__ float g_wc [CFq * Dq * Dq];         // conv weight^T [512][2048]
__device__ float g_wqkvT[Lq * 3 * Dq * Dq];    // per-layer [1536][512]
__device__ float g_bqkv [Lq * 3 * Dq];
__device__ float g_wguT [Lq * 2 * Dq * 2 * Dq];// per-layer [1024][1024]
__device__ float g_bgu  [Lq * 2 * Dq];
__device__ float g_woT  [Lq * Dq * Dq];        // per-layer [512][512]
__device__ float g_wembT[2 * FDq * Dq];        // [512][256]

// ==================== helpers =============================================
__device__ __forceinline__ uint32_t smem_u32(const void* p) {
    uint32_t a;
    asm("{ .reg .u64 t; cvta.to.shared.u64 t, %1; cvt.u32.u64 %0, t; }"
        : "=r"(a) : "l"(p));
    return a;
}
__device__ __forceinline__ uint32_t f2tf(float f) {
    uint32_t u;
    asm("cvt.rna.tf32.f32 %0, %1;" : "=r"(u) : "f"(f));
    return u;
}
__device__ __forceinline__ float roundtf(float f) {
    return __uint_as_float(f2tf(f));
}
__device__ __forceinline__ void mma_tf32(float* d, const uint32_t* a,
                                         const uint32_t* b) {
    asm volatile(
        "mma.sync.aligned.m16n8k8.row.col.f32.tf32.tf32.f32 "
        "{%0,%1,%2,%3}, {%4,%5,%6,%7}, {%8,%9}, {%0,%1,%2,%3};"
        : "+f"(d[0]), "+f"(d[1]), "+f"(d[2]), "+f"(d[3])
        : "r"(a[0]), "r"(a[1]), "r"(a[2]), "r"(a[3]), "r"(b[0]), "r"(b[1]));
}
__device__ __forceinline__ void cpa16(uint32_t dst, const float* src) {
    asm volatile("cp.async.cg.shared.global [%0], [%1], 16;"
                 :: "r"(dst), "l"(src));
}
__device__ __forceinline__ void ldsm4(uint32_t* r, uint32_t addr) {
    asm volatile("ldmatrix.sync.aligned.m8n8.x4.shared.b16 {%0,%1,%2,%3}, [%4];"
                 : "=r"(r[0]), "=r"(r[1]), "=r"(r[2]), "=r"(r[3]) : "r"(addr));
}
__device__ __forceinline__ float warp_sum(float v) {
#pragma unroll
    for (int o = 16; o > 0; o >>= 1)
        v += __shfl_xor_sync(0xffffffffu, v, o);
    return v;
}
#define CPA_COMMIT() asm volatile("cp.async.commit_group;" ::: "memory")
#define CPA_WAIT1()  asm volatile("cp.async.wait_group 1;" ::: "memory")

// ==================== tf32 tensor-core GEMM ===============================
// R10 config (128x128 tile, 256 thr, 2 CTA/SM, single barrier per chunk,
// 3 stages) + PERSISTENT TILE LOOP: grid = min(ntiles, 296); each CTA
// iterates tiles with a grid stride, killing wave-quantization tails.
// Tile-internal math identical to R10 => identical numerics.
#define ASTR 36
#define ST_W (128 * ASTR)
#define SMEM_TC (6 * ST_W * 4)     // 110592 bytes

__global__ __launch_bounds__(256, 2)
void gemm_tc_kernel(const float* __restrict__ A0, const float* __restrict__ A1,
                    int scChunks, int lda0, int lda1,
                    const float* __restrict__ BmT, int ldbt,
                    const float* __restrict__ bias,
                    float* __restrict__ C, int ldc, int nChunks, int roundOut,
                    int gridN, int nTiles) {
    extern __shared__ float smem[];
    uint32_t sbase = smem_u32(smem);

    int tid = threadIdx.x;
    int lane = tid & 31, wid = tid >> 5;
    int warpM = wid & 3, warpN = wid >> 2;
    int g = lane >> 2, c4 = lane & 3;

    int rowA = warpM * 32 + (lane & 15);
    uint32_t aOff = (uint32_t)(rowA * ASTR + (lane >> 4) * 4) * 4;
    int rowB = warpN * 64 + ((lane >> 4) << 3) + (lane & 7);
    uint32_t bOff = (uint32_t)(rowB * ASTR + ((lane >> 3) & 1) * 4) * 4;

#define ISSUE(ch) do { \
        int _st = (ch) % 3; \
        uint32_t _sa = sbase + (uint32_t)(_st * ST_W) * 4; \
        uint32_t _sb = sbase + (uint32_t)((3 + _st) * ST_W) * 4; \
        const float* Ap; int kc, lda; \
        if ((ch) < scChunks) { Ap = A0; kc = (ch); lda = lda0; } \
        else { Ap = A1; kc = (ch) - scChunks; lda = lda1; } \
        _Pragma("unroll") \
        for (int i = 0; i < 4; i++) { \
            int id = tid + i * 256; int r = id >> 3, sg = id & 7; \
            cpa16(_sa + (uint32_t)(r * ASTR + sg * 4) * 4, \
                  Ap + (size_t)(rowbase + r) * lda + kc * 32 + sg * 4); \
            cpa16(_sb + (uint32_t)(r * ASTR + sg * 4) * 4, \
                  BmT + (size_t)(colbase + r) * ldbt + (ch) * 32 + sg * 4); \
        } \
    } while (0)

    for (int tile = blockIdx.x; tile < nTiles; tile += gridDim.x) {
        int rowbase = (tile / gridN) * 128;
        int colbase = (tile % gridN) * 128;

        float acc[2][8][4];
#pragma unroll
        for (int mi = 0; mi < 2; mi++)
#pragma unroll
            for (int nj = 0; nj < 8; nj++)
#pragma unroll
                for (int r = 0; r < 4; r++) acc[mi][nj][r] = 0.f;

        ISSUE(0); CPA_COMMIT();
        ISSUE(1); CPA_COMMIT();

        for (int ch = 0; ch < nChunks; ch++) {
            int st = ch % 3;
            CPA_WAIT1();               // chunk ch resident
            __syncthreads();           // all warps done with chunk ch-1's stage
            if (ch + 2 < nChunks) ISSUE(ch + 2);
            CPA_COMMIT();

            uint32_t aBase = sbase + (uint32_t)(st * ST_W) * 4 + aOff;
            uint32_t bBase = sbase + (uint32_t)((3 + st) * ST_W) * 4 + bOff;
#pragma unroll
            for (int kk = 0; kk < 4; kk++) {
                uint32_t af[2][4], bf[4][4];
                ldsm4(af[0], aBase + kk * 32);
                ldsm4(af[1], aBase + 16 * ASTR * 4 + kk * 32);
#pragma unroll
                for (int pr = 0; pr < 4; pr++)
                    ldsm4(bf[pr], bBase + pr * 16 * ASTR * 4 + kk * 32);
#pragma unroll
                for (int mi = 0; mi < 2; mi++)
#pragma unroll
                    for (int pr = 0; pr < 4; pr++) {
                        mma_tf32(acc[mi][2 * pr],     af[mi], &bf[pr][0]);
                        mma_tf32(acc[mi][2 * pr + 1], af[mi], &bf[pr][2]);
                    }
            }
        }

        // ---- epilogue: bias (+ optional tf32 rounding) + store ----
#pragma unroll
        for (int mi = 0; mi < 2; mi++) {
            int r0 = rowbase + warpM * 32 + mi * 16 + g;
#pragma unroll
            for (int nj = 0; nj < 8; nj++) {
                int col = colbase + warpN * 64 + nj * 8 + 2 * c4;
                float b0 = bias[col], b1 = bias[col + 1];
                float o0 = acc[mi][nj][0] + b0, o1 = acc[mi][nj][1] + b1;
                float o2 = acc[mi][nj][2] + b0, o3 = acc[mi][nj][3] + b1;
                if (roundOut) {
                    o0 = roundtf(o0); o1 = roundtf(o1);
                    o2 = roundtf(o2); o3 = roundtf(o3);
                }
                *(float2*)(C + (size_t)r0 * ldc + col) = make_float2(o0, o1);
                *(float2*)(C + (size_t)(r0 + 8) * ldc + col) = make_float2(o2, o3);
            }
        }
        // protect smem stages before next tile's prologue overwrites them
        __syncthreads();
    }
#undef ISSUE
}

static inline void launch_tc(const float* A0, const float* A1, int sc,
                             int lda0, int lda1, const float* BmT, int ldbt,
                             const float* bias, float* C, int ldc,
                             int M, int N, int K, int roundOut) {
    int gridN = N / 128;
    int nTiles = gridN * (M / 128);
    int grid = nTiles < 296 ? nTiles : 296;
    gemm_tc_kernel<<<grid, 256, SMEM_TC>>>(A0, A1, sc, lda0, lda1, BmT, ldbt,
                                           bias, C, ldc, K / 32, roundOut,
                                           gridN, nTiles);
}

// ==================== tensor-core windowed attention ======================
// (unchanged from R10 — passing)
#define KSTR 68
#define VSTR 72
#define PSTR 36
#define SMA_K(s) ((s) * 32 * KSTR)
#define SMA_VB   (3 * 32 * KSTR)
#define SMA_V(s) (SMA_VB + (s) * 32 * VSTR)
#define SMA_P    (3 * 32 * KSTR + 3 * 32 * VSTR)
#define SMEM_ATT ((SMA_P + 256 * PSTR) * 4)

__global__ __launch_bounds__(256)
void attn_tc_kernel(const float* __restrict__ qkv, float* __restrict__ out) {
    extern __shared__ float sm[];
    int blk = blockIdx.x, head = blockIdx.y, b = blockIdx.z;
    int tid = threadIdx.x, lane = tid & 31, w = tid >> 5;
    int g = lane >> 2, c4 = lane & 3;
    const int LD = 3 * Dq;
    const int qbase = b * Sq + blk * WINq;
    uint32_t sbase = smem_u32(sm);

    {
        const float4* src = (const float4*)(qkv + (size_t)(qbase + tid) * LD + head * HDq);
        float* dst = sm + tid * KSTR;
#pragma unroll
        for (int j = 0; j < 16; j++) *(float4*)(dst + j * 4) = src[j];
    }
    __syncthreads();
    uint32_t qf[2][8][4];
#pragma unroll
    for (int mi = 0; mi < 2; mi++) {
        int r = w * 32 + mi * 16 + g;
#pragma unroll
        for (int kt = 0; kt < 8; kt++) {
            qf[mi][kt][0] = __float_as_uint(sm[r * KSTR + kt * 8 + c4]);
            qf[mi][kt][1] = __float_as_uint(sm[(r + 8) * KSTR + kt * 8 + c4]);
            qf[mi][kt][2] = __float_as_uint(sm[r * KSTR + kt * 8 + c4 + 4]);
            qf[mi][kt][3] = __float_as_uint(sm[(r + 8) * KSTR + kt * 8 + c4 + 4]);
        }
    }
    __syncthreads();

    float o[2][8][4];
#pragma unroll
    for (int mi = 0; mi < 2; mi++)
#pragma unroll
        for (int nt = 0; nt < 8; nt++)
#pragma unroll
            for (int j = 0; j < 4; j++) o[mi][nt][j] = 0.f;
    float m_run[2][2] = {{-1e30f, -1e30f}, {-1e30f, -1e30f}};
    float l_run[2][2] = {{0.f, 0.f}, {0.f, 0.f}};

    const int ktok0 = b * Sq + (blk - 1) * WINq;
    const int c0 = (blk == 0) ? 8 : 0;

#define AISSUE(ci) do { \
        int _st = (ci) % 3; \
        int r = tid >> 3, sg = tid & 7; \
        const float* kv = qkv + (size_t)(ktok0 + (ci) * 32 + r) * LD + head * HDq; \
        uint32_t kd = sbase + (uint32_t)(SMA_K(_st) + r * KSTR) * 4; \
        uint32_t vd = sbase + (uint32_t)(SMA_V(_st) + r * VSTR) * 4; \
        cpa16(kd + sg * 16,        kv + Dq + sg * 4); \
        cpa16(kd + (sg + 8) * 16,  kv + Dq + (sg + 8) * 4); \
        cpa16(vd + sg * 16,        kv + 2 * Dq + sg * 4); \
        cpa16(vd + (sg + 8) * 16,  kv + 2 * Dq + (sg + 8) * 4); \
    } while (0)

    AISSUE(c0);     CPA_COMMIT();
    AISSUE(c0 + 1); CPA_COMMIT();

    float* Pt = sm + SMA_P;
    for (int ci = c0; ci < 16; ci++) {
        CPA_WAIT1();
        __syncthreads();
        if (ci + 2 < 16) AISSUE(ci + 2);
        CPA_COMMIT();
        const float* Kt = sm + SMA_K(ci % 3);
        const float* Vt = sm + SMA_V(ci % 3);

#pragma unroll
        for (int mi = 0; mi < 2; mi++) {
            float s[4][4];
#pragma unroll
            for (int nt = 0; nt < 4; nt++)
#pragma unroll
                for (int j = 0; j < 4; j++) s[nt][j] = 0.f;
#pragma unroll
            for (int kt = 0; kt < 8; kt++) {
                uint32_t bb[4][2];
#pragma unroll
                for (int nt = 0; nt < 4; nt++) {
                    bb[nt][0] = __float_as_uint(Kt[(nt * 8 + g) * KSTR + kt * 8 + c4]);
                    bb[nt][1] = __float_as_uint(Kt[(nt * 8 + g) * KSTR + kt * 8 + c4 + 4]);
                }
#pragma unroll
                for (int nt = 0; nt < 4; nt++)
                    mma_tf32(s[nt], qf[mi][kt], bb[nt]);
            }
#pragma unroll
            for (int nt = 0; nt < 4; nt++)
#pragma unroll
                for (int j = 0; j < 4; j++) s[nt][j] *= 0.125f;

            float ml0 = s[0][0], ml1 = s[0][2];
#pragma unroll
            for (int nt = 0; nt < 4; nt++) {
                ml0 = fmaxf(ml0, fmaxf(s[nt][0], s[nt][1]));
                ml1 = fmaxf(ml1, fmaxf(s[nt][2], s[nt][3]));
            }
            ml0 = fmaxf(ml0, __shfl_xor_sync(0xffffffffu, ml0, 1));
            ml0 = fmaxf(ml0, __shfl_xor_sync(0xffffffffu, ml0, 2));
            ml1 = fmaxf(ml1, __shfl_xor_sync(0xffffffffu, ml1, 1));
            ml1 = fmaxf(ml1, __shfl_xor_sync(0xffffffffu, ml1, 2));

            float mn0 = fmaxf(m_run[mi][0], ml0);
            float mn1 = fmaxf(m_run[mi][1], ml1);
            float sc0 = __expf(m_run[mi][0] - mn0);
            float sc1 = __expf(m_run[mi][1] - mn1);
            m_run[mi][0] = mn0; m_run[mi][1] = mn1;

            float ps0 = 0.f, ps1 = 0.f;
#pragma unroll
            for (int nt = 0; nt < 4; nt++) {
                s[nt][0] = roundtf(__expf(s[nt][0] - mn0)); ps0 += s[nt][0];
                s[nt][1] = roundtf(__expf(s[nt][1] - mn0)); ps0 += s[nt][1];
                s[nt][2] = roundtf(__expf(s[nt][2] - mn1)); ps1 += s[nt][2];
                s[nt][3] = roundtf(__expf(s[nt][3] - mn1)); ps1 += s[nt][3];
            }
            ps0 += __shfl_xor_sync(0xffffffffu, ps0, 1);
            ps0 += __shfl_xor_sync(0xffffffffu, ps0, 2);
            ps1 += __shfl_xor_sync(0xffffffffu, ps1, 1);
            ps1 += __shfl_xor_sync(0xffffffffu, ps1, 2);
            l_run[mi][0] = l_run[mi][0] * sc0 + ps0;
            l_run[mi][1] = l_run[mi][1] * sc1 + ps1;

#pragma unroll
            for (int nt = 0; nt < 8; nt++) {
                o[mi][nt][0] *= sc0; o[mi][nt][1] *= sc0;
                o[mi][nt][2] *= sc1; o[mi][nt][3] *= sc1;
            }
            int r = w * 32 + mi * 16 + g;
#pragma unroll
            for (int nt = 0; nt < 4; nt++) {
                *(float2*)&Pt[r * PSTR + nt * 8 + 2 * c4] = make_float2(s[nt][0], s[nt][1]);
                *(float2*)&Pt[(r + 8) * PSTR + nt * 8 + 2 * c4] = make_float2(s[nt][2], s[nt][3]);
            }
        }
        __syncwarp();

#pragma unroll
        for (int kt = 0; kt < 4; kt++) {
            uint32_t pa[2][4];
#pragma unroll
            for (int mi = 0; mi < 2; mi++) {
                int r = w * 32 + mi * 16 + g;
                pa[mi][0] = __float_as_uint(Pt[r * PSTR + kt * 8 + c4]);
                pa[mi][1] = __float_as_uint(Pt[(r + 8) * PSTR + kt * 8 + c4]);
                pa[mi][2] = __float_as_uint(Pt[r * PSTR + kt * 8 + c4 + 4]);
                pa[mi][3] = __float_as_uint(Pt[(r + 8) * PSTR + kt * 8 + c4 + 4]);
            }
#pragma unroll
            for (int nt = 0; nt < 8; nt++) {
                uint32_t bv[2];
                bv[0] = __float_as_uint(Vt[(kt * 8 + c4) * VSTR + nt * 8 + g]);
                bv[1] = __float_as_uint(Vt[(kt * 8 + c4 + 4) * VSTR + nt * 8 + g]);
                mma_tf32(o[0][nt], pa[0], bv);
                mma_tf32(o[1][nt], pa[1], bv);
            }
        }
    }
#undef AISSUE

#pragma unroll
    for (int mi = 0; mi < 2; mi++) {
        float inv0 = 1.f / l_run[mi][0];
        float inv1 = 1.f / l_run[mi][1];
        int r = qbase + w * 32 + mi * 16 + g;
#pragma unroll
        for (int nt = 0; nt < 8; nt++) {
            int col = head * HDq + nt * 8 + 2 * c4;
            *(float2*)&out[(size_t)r * Dq + col] =
                make_float2(roundtf(o[mi][nt][0] * inv0), roundtf(o[mi][nt][1] * inv0));
            *(float2*)&out[(size_t)(r + 8) * Dq + col] =
                make_float2(roundtf(o[mi][nt][2] * inv1), roundtf(o[mi][nt][3] * inv1));
        }
    }
}

// -------------------- bulk weight packing (all layers, once) --------------
__global__ void pack3_all_kernel(const float* __restrict__ Wq, const float* __restrict__ Wk,
                                 const float* __restrict__ Wv, const float* __restrict__ bq,
                                 const float* __restrict__ bk, const float* __restrict__ bv,
                                 float* __restrict__ BpT, float* __restrict__ bp) {
    int i = blockIdx.x * 256 + threadIdx.x;
    if (i < Lq * Dq * Dq) {
        int l = i >> 18;
        int r = i & (Dq * Dq - 1);
        int n = r >> 9, k = r & 511;
        size_t so = (size_t)l * Dq * Dq + (size_t)k * Dq + n;
        float* dst = BpT + (size_t)l * 3 * Dq * Dq;
        dst[(size_t)n * Dq + k] = roundtf(Wq[so]);
        dst[(size_t)(Dq + n) * Dq + k] = roundtf(Wk[so]);
        dst[(size_t)(2 * Dq + n) * Dq + k] = roundtf(Wv[so]);
    }
    if (i < Lq * Dq) {
        int l = i >> 9, n = i & 511;
        bp[l * 3 * Dq + n] = bq[l * Dq + n];
        bp[l * 3 * Dq + Dq + n] = bk[l * Dq + n];
        bp[l * 3 * Dq + 2 * Dq + n] = bv[l * Dq + n];
    }
}
__global__ void pack2_all_kernel(const float* __restrict__ Wg, const float* __restrict__ Wu,
                                 const float* __restrict__ bg, const float* __restrict__ bu,
                                 float* __restrict__ BpT, float* __restrict__ bp) {
    int i = blockIdx.x * 256 + threadIdx.x;
    if (i < Lq * 2 * Dq * Dq) {
        int l = i >> 19;
        int r = i & (2 * Dq * Dq - 1);
        int n = r >> 10, k = r & 1023;
        size_t so = (size_t)l * 2 * Dq * Dq + (size_t)k * Dq + n;
        float* dst = BpT + (size_t)l * 2 * Dq * 2 * Dq;
        dst[(size_t)n * 2 * Dq + k] = roundtf(Wg[so]);
        dst[(size_t)(Dq + n) * 2 * Dq + k] = roundtf(Wu[so]);
    }
    if (i < Lq * Dq) {
        int l = i >> 9, n = i & 511;
        bp[l * 2 * Dq + n] = bg[l * Dq + n];
        bp[l * 2 * Dq + Dq + n] = bu[l * Dq + n];
    }
}
__global__ void packo_all_kernel(const float* __restrict__ Wo, float* __restrict__ dst) {
    int i = blockIdx.x * 256 + threadIdx.x;
    if (i < Lq * Dq * Dq) {
        int l = i >> 18;
        int r = i & (Dq * Dq - 1);
        int n = r >> 9, k = r & 511;
        dst[(size_t)l * Dq * Dq + (size_t)n * Dq + k] =
            roundtf(Wo[(size_t)l * Dq * Dq + (size_t)k * Dq + n]);
    }
}
__global__ void roundcpy_t_kernel(const float* __restrict__ src,
                                  float* __restrict__ dst, int K, int N) {
    int i = blockIdx.x * 256 + threadIdx.x;
    if (i < K * N) {
        int n = i / K, k = i - n * K;
        dst[i] = roundtf(src[(size_t)k * N + n]);
    }
}
__global__ void convw_kernel(const float* __restrict__ w, float* __restrict__ wcT) {
    int i = blockIdx.x * 256 + threadIdx.x;
    if (i < CFq * Dq * Dq) {
        int o = i >> 11, r = i & 2047;
        int j = r >> 9, c = r & 511;
        wcT[i] = roundtf(w[(size_t)o * (Dq * CFq) + c * CFq + j]);
    }
}

// -------------------- embedding: cat = [x@W_feat + b_feat, emb[ts]] -------
__global__ __launch_bounds__(128)
void build_cat_kernel(const float* __restrict__ x, const int* __restrict__ ts,
                      const float* __restrict__ Wf, const float* __restrict__ bf,
                      const float* __restrict__ emb, float* __restrict__ cat) {
    int t = blockIdx.x;
    int d = threadIdx.x;
    __shared__ float xr[Fq];
    if (d < Fq) xr[d] = x[t * Fq + d];
    __syncthreads();
    float s = bf[d];
#pragma unroll
    for (int i = 0; i < Fq; i++) s += xr[i] * Wf[i * FDq + d];
    cat[t * 2 * FDq + d] = roundtf(s);
    cat[t * 2 * FDq + FDq + d] = roundtf(emb[ts[t] * FDq + d]);
}

// -------------------- fp32 SGEMM (small final projection only) ------------
#define BM 64
#define BN 64
#define BKq 16
__global__ __launch_bounds__(256)
void gemm_kernel(const float* __restrict__ A0,
                 const float* __restrict__ Bm, const float* __restrict__ bias,
                 float* __restrict__ C, int M, int N, int K) {
    __shared__ float As[BKq][BM];
    __shared__ float Bs[BKq][BN];
    int tid = threadIdx.x;
    int tx = tid & 15, ty = tid >> 4;
    int row0 = blockIdx.y * BM;
    int col0 = blockIdx.x * BN;
    float acc[4][4];
#pragma unroll
    for (int i = 0; i < 4; i++)
#pragma unroll
        for (int j = 0; j < 4; j++) acc[i][j] = 0.f;

    for (int k0 = 0; k0 < K; k0 += BKq) {
#pragma unroll
        for (int it = 0; it < 4; it++) {
            int idx = tid + it * 256;
            int m = idx >> 4, kk = idx & 15;
            int r = row0 + m;
            As[kk][m] = (r < M) ? A0[(size_t)r * K + k0 + kk] : 0.f;
        }
#pragma unroll
        for (int it = 0; it < 4; it++) {
            int idx = tid + it * 256;
            int kk = idx >> 6, n = idx & 63;
            int gn = col0 + n;
            Bs[kk][n] = (gn < N) ? Bm[(size_t)(k0 + kk) * N + gn] : 0.f;
        }
        __syncthreads();
#pragma unroll
        for (int kk = 0; kk < BKq; kk++) {
            float4 a4 = *reinterpret_cast<const float4*>(&As[kk][ty * 4]);
            float4 b4 = *reinterpret_cast<const float4*>(&Bs[kk][tx * 4]);
            float a[4] = {a4.x, a4.y, a4.z, a4.w};
            float b[4] = {b4.x, b4.y, b4.z, b4.w};
#pragma unroll
            for (int i = 0; i < 4; i++)
#pragma unroll
                for (int j = 0; j < 4; j++) acc[i][j] += a[i] * b[j];
        }
        __syncthreads();
    }
#pragma unroll
    for (int i = 0; i < 4; i++) {
        int r = row0 + ty * 4 + i;
        if (r >= M) continue;
#pragma unroll
        for (int j = 0; j < 4; j++) {
            int cc = col0 + tx * 4 + j;
            if (cc < N) C[(size_t)r * N + cc] = acc[i][j] + bias[cc];
        }
    }
}

// -------------------- fused gate + memory + LayerNorm (warp/token) --------
__global__ __launch_bounds__(256)
void gate_ln_kernel(const float* __restrict__ a, const float* __restrict__ gu,
                    float* __restrict__ mem,
                    const float* __restrict__ g, const float* __restrict__ bta,
                    float* __restrict__ hout, int first) {
    int w = threadIdx.x >> 5, lane = threadIdx.x & 31;
    int t = blockIdx.x * 8 + w;
    size_t base = (size_t)t * Dq;
    size_t gbase = (size_t)t * 2 * Dq;

    float y[16];
    float sum = 0.f;
#pragma unroll
    for (int j = 0; j < 4; j++) {
        int d = (lane + 32 * j) * 4;
        float4 gg = *(const float4*)&gu[gbase + d];
        float4 uu = *(const float4*)&gu[gbase + Dq + d];
        float4 av = *(const float4*)&a[base + d];
        float4 mm = first ? make_float4(0.f, 0.f, 0.f, 0.f)
                          : *(const float4*)&mem[base + d];
        float g0 = 1.f / (1.f + __expf(-gg.x));
        float g1 = 1.f / (1.f + __expf(-gg.y));
        float g2 = 1.f / (1.f + __expf(-gg.z));
        float g3 = 1.f / (1.f + __expf(-gg.w));
        float nm0 = g0 * uu.x + (1.f - g0) * mm.x;
        float nm1 = g1 * uu.y + (1.f - g1) * mm.y;
        float nm2 = g2 * uu.z + (1.f - g2) * mm.z;
        float nm3 = g3 * uu.w + (1.f - g3) * mm.w;
        *(float4*)&mem[base + d] = make_float4(roundtf(nm0), roundtf(nm1),
                                               roundtf(nm2), roundtf(nm3));
        y[j * 4 + 0] = av.x + nm0;
        y[j * 4 + 1] = av.y + nm1;
        y[j * 4 + 2] = av.z + nm2;
        y[j * 4 + 3] = av.w + nm3;
        sum += y[j * 4] + y[j * 4 + 1] + y[j * 4 + 2] + y[j * 4 + 3];
    }
    float mean = warp_sum(sum) * (1.f / Dq);
    float vs = 0.f;
#pragma unroll
    for (int i = 0; i < 16; i++) {
        float dv = y[i] - mean;
        vs += dv * dv;
    }
    float rs = rsqrtf(warp_sum(vs) * (1.f / Dq) + 1e-5f);
#pragma unroll
    for (int j = 0; j < 4; j++) {
        int d = (lane + 32 * j) * 4;
        float4 gv = *(const float4*)&g[d];
        float4 bv = *(const float4*)&bta[d];
        float4 ov;
        ov.x = roundtf((y[j * 4 + 0] - mean) * rs * gv.x + bv.x);
        ov.y = roundtf((y[j * 4 + 1] - mean) * rs * gv.y + bv.y);
        ov.z = roundtf((y[j * 4 + 2] - mean) * rs * gv.z + bv.z);
        ov.w = roundtf((y[j * 4 + 3] - mean) * rs * gv.w + bv.w);
        *(float4*)&hout[base + d] = ov;
    }
}

// -------------------- double LayerNorm (warp/token) -----------------------
__global__ __launch_bounds__(256)
void double_ln_kernel(const float* __restrict__ c, const float* __restrict__ cg,
                      const float* __restrict__ cb, const float* __restrict__ og,
                      const float* __restrict__ ob, float* __restrict__ out) {
    int w = threadIdx.x >> 5, lane = threadIdx.x & 31;
    int t = blockIdx.x * 8 + w;
    size_t base = (size_t)t * Dq;

    float y[16];
    float sum = 0.f;
#pragma unroll
    for (int j = 0; j < 4; j++) {
        int d = (lane + 32 * j) * 4;
        float4 v = *(const float4*)&c[base + d];
        y[j * 4 + 0] = v.x; y[j * 4 + 1] = v.y;
        y[j * 4 + 2] = v.z; y[j * 4 + 3] = v.w;
        sum += v.x + v.y + v.z + v.w;
    }
    float mean = warp_sum(sum) * (1.f / Dq);
    float vs = 0.f;
#pragma unroll
    for (int i = 0; i < 16; i++) {
        float dv = y[i] - mean;
        vs += dv * dv;
    }
    float rs = rsqrtf(warp_sum(vs) * (1.f / Dq) + 1e-5f);

    float z[16];
    float sum2 = 0.f;
#pragma unroll
    for (int j = 0; j < 4; j++) {
        int d = (lane + 32 * j) * 4;
        float4 gv = *(const float4*)&cg[d];
        float4 bv = *(const float4*)&cb[d];
        z[j * 4 + 0] = (y[j * 4 + 0] - mean) * rs * gv.x + bv.x;
        z[j * 4 + 1] = (y[j * 4 + 1] - mean) * rs * gv.y + bv.y;
        z[j * 4 + 2] = (y[j * 4 + 2] - mean) * rs * gv.z + bv.z;
        z[j * 4 + 3] = (y[j * 4 + 3] - mean) * rs * gv.w + bv.w;
        sum2 += z[j * 4] + z[j * 4 + 1] + z[j * 4 + 2] + z[j * 4 + 3];
    }
    float mean2 = warp_sum(sum2) * (1.f / Dq);
    float vs2 = 0.f;
#pragma unroll
    for (int i = 0; i < 16; i++) {
        float dv = z[i] - mean2;
        vs2 += dv * dv;
    }
    float rs2 = rsqrtf(warp_sum(vs2) * (1.f / Dq) + 1e-5f);
#pragma unroll
    for (int j = 0; j < 4; j++) {
        int d = (lane + 32 * j) * 4;
        float4 gv = *(const float4*)&og[d];
        float4 bv = *(const float4*)&ob[d];
        float4 ov;
        ov.x = roundtf((z[j * 4 + 0] - mean2) * rs2 * gv.x + bv.x);
        ov.y = roundtf((z[j * 4 + 1] - mean2) * rs2 * gv.y + bv.y);
        ov.z = roundtf((z[j * 4 + 2] - mean2) * rs2 * gv.z + bv.z);
        ov.w = roundtf((z[j * 4 + 3] - mean2) * rs2 * gv.w + bv.w);
        *(float4*)&out[base + d] = ov;
    }
}

// ==========================================================================
extern "C" void kernel_launch(void* const* d_in, const int* in_sizes, int n_in,
                              void* d_out, int out_size) {
    const float* x       = (const float*)d_in[0];
    const int*   ts      = (const int*)d_in[1];
    const float* W_feat  = (const float*)d_in[2];
    const float* b_feat  = (const float*)d_in[3];
    const float* emb     = (const float*)d_in[4];
    const float* W_emb   = (const float*)d_in[5];
    const float* b_emb   = (const float*)d_in[6];
    const float* Wq      = (const float*)d_in[7];
    const float* bq      = (const float*)d_in[8];
    const float* Wk      = (const float*)d_in[9];
    const float* bk      = (const float*)d_in[10];
    const float* Wv      = (const float*)d_in[11];
    const float* bv      = (const float*)d_in[12];
    const float* Wo      = (const float*)d_in[13];
    const float* bo      = (const float*)d_in[14];
    const float* Wg      = (const float*)d_in[15];
    const float* bg      = (const float*)d_in[16];
    const float* Wu      = (const float*)d_in[17];
    const float* bu      = (const float*)d_in[18];
    const float* ln_g    = (const float*)d_in[19];
    const float* ln_b    = (const float*)d_in[20];
    const float* conv_w  = (const float*)d_in[21];
    const float* conv_b  = (const float*)d_in[22];
    const float* cn_g    = (const float*)d_in[23];
    const float* cn_b    = (const float*)d_in[24];
    const float* on_g    = (const float*)d_in[25];
    const float* on_b    = (const float*)d_in[26];
    const float* W_out   = (const float*)d_in[27];
    const float* b_out   = (const float*)d_in[28];
    float* out = (float*)d_out;

    float *cat, *h, *mem, *qkv, *ap, *a, *gu, *c, *c2, *wc;
    float *wqkvT, *bqkv, *wguT, *bgu, *woT, *wembT;
    cudaGetSymbolAddress((void**)&cat, g_cat);
    cudaGetSymbolAddress((void**)&h,   g_h);
    cudaGetSymbolAddress((void**)&mem, g_mem);
    cudaGetSymbolAddress((void**)&qkv, g_qkv);
    cudaGetSymbolAddress((void**)&ap,  g_ap);
    cudaGetSymbolAddress((void**)&a,   g_a);
    cudaGetSymbolAddress((void**)&gu,  g_gu);
    cudaGetSymbolAddress((void**)&c,   g_c);
    cudaGetSymbolAddress((void**)&c2,  g_c2);
    cudaGetSymbolAddress((void**)&wc,  g_wc);
    cudaGetSymbolAddress((void**)&wqkvT, g_wqkvT);
    cudaGetSymbolAddress((void**)&bqkv,  g_bqkv);
    cudaGetSymbolAddress((void**)&wguT,  g_wguT);
    cudaGetSymbolAddress((void**)&bgu,   g_bgu);
    cudaGetSymbolAddress((void**)&woT,   g_woT);
    cudaGetSymbolAddress((void**)&wembT, g_wembT);

    static int smem_set = 0;
    if (!smem_set) {
        cudaFuncSetAttribute(gemm_tc_kernel,
                             cudaFuncAttributeMaxDynamicSharedMemorySize, SMEM_TC);
        cudaFuncSetAttribute(attn_tc_kernel,
                             cudaFuncAttributeMaxDynamicSharedMemorySize, SMEM_ATT);
        smem_set = 1;
    }

    // 0. bulk weight pre-pack (all layers, 5 launches total)
    pack3_all_kernel<<<(Lq * Dq * Dq + 255) / 256, 256>>>(Wq, Wk, Wv, bq, bk, bv,
                                                          wqkvT, bqkv);
    pack2_all_kernel<<<(Lq * 2 * Dq * Dq + 255) / 256, 256>>>(Wg, Wu, bg, bu,
                                                              wguT, bgu);
    packo_all_kernel<<<(Lq * Dq * Dq + 255) / 256, 256>>>(Wo, woT);
    roundcpy_t_kernel<<<(2 * FDq * Dq + 255) / 256, 256>>>(W_emb, wembT, 2 * FDq, Dq);
    convw_kernel<<<(CFq * Dq * Dq + 255) / 256, 256>>>(conv_w, wc);

    // 1. embedding
    build_cat_kernel<<<NTq, 128>>>(x, ts, W_feat, b_feat, emb, cat);
    launch_tc(cat, cat, 8, 2 * FDq, 2 * FDq, wembT, 2 * FDq, b_emb, h, Dq,
              NTq, Dq, 2 * FDq, 1);

    // 2. layers (mem implicitly zero in layer 0)
    for (int l = 0; l < Lq; l++) {
        launch_tc(h, h, 16, Dq, Dq, wqkvT + (size_t)l * 3 * Dq * Dq, Dq,
                  bqkv + l * 3 * Dq, qkv, 3 * Dq, NTq, 3 * Dq, Dq, 1);

        attn_tc_kernel<<<dim3(NBq, Hq, Bq), 256, SMEM_ATT>>>(qkv, ap);

        launch_tc(ap, ap, 16, Dq, Dq, woT + (size_t)l * Dq * Dq, Dq,
                  bo + l * Dq, a, Dq, NTq, Dq, Dq, 1);

        if (l == 0)
            launch_tc(a, a, 16, Dq, Dq, wguT + (size_t)l * 2 * Dq * 2 * Dq, 2 * Dq,
                      bgu + l * 2 * Dq, gu, 2 * Dq, NTq, 2 * Dq, Dq, 0);
        else
            launch_tc(a, mem, 16, Dq, Dq, wguT + (size_t)l * 2 * Dq * 2 * Dq, 2 * Dq,
                      bgu + l * 2 * Dq, gu, 2 * Dq, NTq, 2 * Dq, 2 * Dq, 0);

        gate_ln_kernel<<<NTq / 8, 256>>>(a, gu, mem, ln_g + l * Dq,
                                         ln_b + l * Dq, h, l == 0);
    }

    // 3. temporal compression (conv as GEMM; weight transposed [512][2048])
    launch_tc(h, h, 64, CFq * Dq, CFq * Dq, wc, CFq * Dq, conv_b, c, Dq,
              Bq * NCq, Dq, CFq * Dq, 0);

    // 4. double LayerNorm
    double_ln_kernel<<<Bq * NCq / 8, 256>>>(c, cn_g, cn_b, on_g, on_b, c2);

    // 5. output projection (small: fp32 path)
    {
        dim3 grid((Fq + BN - 1) / BN, (Bq * NCq + BM - 1) / BM);
        gemm_kernel<<<grid, 256>>>(c2, W_out, b_out, out, Bq * NCq, Fq, Dq);
    }
}

// round 13
// speedup vs baseline: 1.0743x; 1.0052x over previous
#include <cuda_runtime.h>
#include <cuda_bf16.h>
#include <cstdint>

// Problem constants
#define Bq 4
#define Sq 8192
#define Fq 32
#define Dq 512
#define Hq 8
#define Lq 4
#define FDq 128
#define WINq 256
#define CFq 4
#define HDq 64
#define NTq (Bq * Sq)          // 32768 tokens
#define NBq (Sq / WINq)        // 32 windows
#define NCq (Sq / CFq)         // 2048 compressed steps per batch

// -------------------- scratch (device globals; no allocation allowed) -----
__device__ float g_cat[NTq * 2 * FDq];
__device__ float g_h  [NTq * Dq];
__device__ float g_mem[NTq * Dq];
__device__ float g_qkv[NTq * 3 * Dq];
__device__ float g_ap [NTq * Dq];
__device__ float g_a  [NTq * Dq];
__device__ float g_gu [NTq * 2 * Dq];
__device__ float g_c  [Bq * NCq * Dq];
__device__ float g_c2 [Bq * NCq * Dq];
__device__ float g_wc [CFq * Dq * Dq];         // conv weight^T [512][2048]
__device__ float g_wqkvT[Lq * 3 * Dq * Dq];    // per-layer [1536][512]
__device__ float g_bqkv [Lq * 3 * Dq];
__device__ float g_wguT [Lq * 2 * Dq * 2 * Dq];// per-layer [1024][1024]
__device__ float g_bgu  [Lq * 2 * Dq];
__device__ float g_woT  [Lq * Dq * Dq];        // per-layer [512][512]
__device__ float g_wembT[2 * FDq * Dq];        // [512][256]

// ==================== helpers =============================================
__device__ __forceinline__ uint32_t smem_u32(const void* p) {
    uint32_t a;
    asm("{ .reg .u64 t; cvta.to.shared.u64 t, %1; cvt.u32.u64 %0, t; }"
        : "=r"(a) : "l"(p));
    return a;
}
__device__ __forceinline__ uint32_t f2tf(float f) {
    uint32_t u;
    asm("cvt.rna.tf32.f32 %0, %1;" : "=r"(u) : "f"(f));
    return u;
}
__device__ __forceinline__ float roundtf(float f) {
    return __uint_as_float(f2tf(f));
}
__device__ __forceinline__ void mma_tf32(float* d, const uint32_t* a,
                                         const uint32_t* b) {
    asm volatile(
        "mma.sync.aligned.m16n8k8.row.col.f32.tf32.tf32.f32 "
        "{%0,%1,%2,%3}, {%4,%5,%6,%7}, {%8,%9}, {%0,%1,%2,%3};"
        : "+f"(d[0]), "+f"(d[1]), "+f"(d[2]), "+f"(d[3])
        : "r"(a[0]), "r"(a[1]), "r"(a[2]), "r"(a[3]), "r"(b[0]), "r"(b[1]));
}
__device__ __forceinline__ void cpa16(uint32_t dst, const float* src) {
    asm volatile("cp.async.cg.shared.global [%0], [%1], 16;"
                 :: "r"(dst), "l"(src));
}
__device__ __forceinline__ void ldsm4(uint32_t* r, uint32_t addr) {
    asm volatile("ldmatrix.sync.aligned.m8n8.x4.shared.b16 {%0,%1,%2,%3}, [%4];"
                 : "=r"(r[0]), "=r"(r[1]), "=r"(r[2]), "=r"(r[3]) : "r"(addr));
}
__device__ __forceinline__ float warp_sum(float v) {
#pragma unroll
    for (int o = 16; o > 0; o >>= 1)
        v += __shfl_xor_sync(0xffffffffu, v, o);
    return v;
}
#define CPA_COMMIT() asm volatile("cp.async.commit_group;" ::: "memory")
#define CPA_WAIT1()  asm volatile("cp.async.wait_group 1;" ::: "memory")

// ==================== tf32 tensor-core GEMM ===============================
// EXACT R10 configuration (best passing: 4608 us):
// 128x128 tile, 256 thr, 2 CTA/SM, K-chunk 32, 3 stages, single barrier.
#define ASTR 36
#define ST_W (128 * ASTR)
#define SMEM_TC (6 * ST_W * 4)     // 110592 bytes

__global__ __launch_bounds__(256, 2)
void gemm_tc_kernel(const float* __restrict__ A0, const float* __restrict__ A1,
                    int scChunks, int lda0, int lda1,
                    const float* __restrict__ BmT, int ldbt,
                    const float* __restrict__ bias,
                    float* __restrict__ C, int ldc, int nChunks, int roundOut) {
    extern __shared__ float smem[];
    uint32_t sbase = smem_u32(smem);

    int tid = threadIdx.x;
    int lane = tid & 31, wid = tid >> 5;
    int warpM = wid & 3, warpN = wid >> 2;
    int g = lane >> 2, c4 = lane & 3;
    int rowbase = blockIdx.y * 128;
    int colbase = blockIdx.x * 128;

    int rowA = warpM * 32 + (lane & 15);
    uint32_t aOff = (uint32_t)(rowA * ASTR + (lane >> 4) * 4) * 4;
    int rowB = warpN * 64 + ((lane >> 4) << 3) + (lane & 7);
    uint32_t bOff = (uint32_t)(rowB * ASTR + ((lane >> 3) & 1) * 4) * 4;

    float acc[2][8][4];
#pragma unroll
    for (int mi = 0; mi < 2; mi++)
#pragma unroll
        for (int nj = 0; nj < 8; nj++)
#pragma unroll
            for (int r = 0; r < 4; r++) acc[mi][nj][r] = 0.f;

#define ISSUE(ch) do { \
        int _st = (ch) % 3; \
        uint32_t _sa = sbase + (uint32_t)(_st * ST_W) * 4; \
        uint32_t _sb = sbase + (uint32_t)((3 + _st) * ST_W) * 4; \
        const float* Ap; int kc, lda; \
        if ((ch) < scChunks) { Ap = A0; kc = (ch); lda = lda0; } \
        else { Ap = A1; kc = (ch) - scChunks; lda = lda1; } \
        _Pragma("unroll") \
        for (int i = 0; i < 4; i++) { \
            int id = tid + i * 256; int r = id >> 3, sg = id & 7; \
            cpa16(_sa + (uint32_t)(r * ASTR + sg * 4) * 4, \
                  Ap + (size_t)(rowbase + r) * lda + kc * 32 + sg * 4); \
            cpa16(_sb + (uint32_t)(r * ASTR + sg * 4) * 4, \
                  BmT + (size_t)(colbase + r) * ldbt + (ch) * 32 + sg * 4); \
        } \
    } while (0)

    ISSUE(0); CPA_COMMIT();
    ISSUE(1); CPA_COMMIT();

    for (int ch = 0; ch < nChunks; ch++) {
        int st = ch % 3;
        CPA_WAIT1();
        __syncthreads();
        if (ch + 2 < nChunks) ISSUE(ch + 2);
        CPA_COMMIT();

        uint32_t aBase = sbase + (uint32_t)(st * ST_W) * 4 + aOff;
        uint32_t bBase = sbase + (uint32_t)((3 + st) * ST_W) * 4 + bOff;
#pragma unroll
        for (int kk = 0; kk < 4; kk++) {
            uint32_t af[2][4], bf[4][4];
            ldsm4(af[0], aBase + kk * 32);
            ldsm4(af[1], aBase + 16 * ASTR * 4 + kk * 32);
#pragma unroll
            for (int pr = 0; pr < 4; pr++)
                ldsm4(bf[pr], bBase + pr * 16 * ASTR * 4 + kk * 32);
#pragma unroll
            for (int mi = 0; mi < 2; mi++)
#pragma unroll
                for (int pr = 0; pr < 4; pr++) {
                    mma_tf32(acc[mi][2 * pr],     af[mi], &bf[pr][0]);
                    mma_tf32(acc[mi][2 * pr + 1], af[mi], &bf[pr][2]);
                }
        }
    }
#undef ISSUE

#pragma unroll
    for (int mi = 0; mi < 2; mi++) {
        int r0 = rowbase + warpM * 32 + mi * 16 + g;
#pragma unroll
        for (int nj = 0; nj < 8; nj++) {
            int col = colbase + warpN * 64 + nj * 8 + 2 * c4;
            float b0 = bias[col], b1 = bias[col + 1];
            float o0 = acc[mi][nj][0] + b0, o1 = acc[mi][nj][1] + b1;
            float o2 = acc[mi][nj][2] + b0, o3 = acc[mi][nj][3] + b1;
            if (roundOut) {
                o0 = roundtf(o0); o1 = roundtf(o1);
                o2 = roundtf(o2); o3 = roundtf(o3);
            }
            *(float2*)(C + (size_t)r0 * ldc + col) = make_float2(o0, o1);
            *(float2*)(C + (size_t)(r0 + 8) * ldc + col) = make_float2(o2, o3);
        }
    }
}

static inline void launch_tc(const float* A0, const float* A1, int sc,
                             int lda0, int lda1, const float* BmT, int ldbt,
                             const float* bias, float* C, int ldc,
                             int M, int N, int K, int roundOut) {
    dim3 grid(N / 128, M / 128);
    gemm_tc_kernel<<<grid, 256, SMEM_TC>>>(A0, A1, sc, lda0, lda1, BmT, ldbt,
                                           bias, C, ldc, K / 32, roundOut);
}

// ==================== tensor-core windowed attention ======================
// 512 threads / 16 warps, each warp owns 16 q-rows (one m16 A-fragment).
// Per-row arithmetic and op order identical to the 256-thread version.
#define KSTR 68
#define VSTR 72
#define PSTR 36
#define SMA_K(s) ((s) * 32 * KSTR)
#define SMA_VB   (3 * 32 * KSTR)
#define SMA_V(s) (SMA_VB + (s) * 32 * VSTR)
#define SMA_P    (3 * 32 * KSTR + 3 * 32 * VSTR)
#define SMEM_ATT ((SMA_P + 256 * PSTR) * 4)

__global__ __launch_bounds__(512)
void attn_tc_kernel(const float* __restrict__ qkv, float* __restrict__ out) {
    extern __shared__ float sm[];
    int blk = blockIdx.x, head = blockIdx.y, b = blockIdx.z;
    int tid = threadIdx.x, lane = tid & 31, w = tid >> 5;   // w in 0..15
    int g = lane >> 2, c4 = lane & 3;
    const int LD = 3 * Dq;
    const int qbase = b * Sq + blk * WINq;
    uint32_t sbase = smem_u32(sm);

    // ---- stage Q (256 rows x 64 floats); each thread loads half a row ----
    {
        int r = tid >> 1, half = tid & 1;
        const float4* src = (const float4*)(qkv + (size_t)(qbase + r) * LD
                                            + head * HDq + half * 32);
        float* dst = sm + r * KSTR + half * 32;
#pragma unroll
        for (int j = 0; j < 8; j++) *(float4*)(dst + j * 4) = src[j];
    }
    __syncthreads();
    uint32_t qf[8][4];
    {
        int r = w * 16 + g;
#pragma unroll
        for (int kt = 0; kt < 8; kt++) {
            qf[kt][0] = __float_as_uint(sm[r * KSTR + kt * 8 + c4]);
            qf[kt][1] = __float_as_uint(sm[(r + 8) * KSTR + kt * 8 + c4]);
            qf[kt][2] = __float_as_uint(sm[r * KSTR + kt * 8 + c4 + 4]);
            qf[kt][3] = __float_as_uint(sm[(r + 8) * KSTR + kt * 8 + c4 + 4]);
        }
    }
    __syncthreads();

    float o[8][4];
#pragma unroll
    for (int nt = 0; nt < 8; nt++)
#pragma unroll
        for (int j = 0; j < 4; j++) o[nt][j] = 0.f;
    float m_run[2] = {-1e30f, -1e30f};
    float l_run[2] = {0.f, 0.f};

    const int ktok0 = b * Sq + (blk - 1) * WINq;
    const int c0 = (blk == 0) ? 8 : 0;

#define AISSUE(ci) do { \
        int _st = (ci) % 3; \
        int r = tid >> 4, sg = tid & 15; \
        const float* kv = qkv + (size_t)(ktok0 + (ci) * 32 + r) * LD + head * HDq; \
        uint32_t kd = sbase + (uint32_t)(SMA_K(_st) + r * KSTR) * 4; \
        uint32_t vd = sbase + (uint32_t)(SMA_V(_st) + r * VSTR) * 4; \
        cpa16(kd + sg * 16, kv + Dq + sg * 4); \
        cpa16(vd + sg * 16, kv + 2 * Dq + sg * 4); \
    } while (0)

    AISSUE(c0);     CPA_COMMIT();
    AISSUE(c0 + 1); CPA_COMMIT();

    float* Pt = sm + SMA_P;
    for (int ci = c0; ci < 16; ci++) {
        CPA_WAIT1();
        __syncthreads();
        if (ci + 2 < 16) AISSUE(ci + 2);
        CPA_COMMIT();
        const float* Kt = sm + SMA_K(ci % 3);
        const float* Vt = sm + SMA_V(ci % 3);

        // ---- S = Q@K^T for this warp's 16 rows ----
        float s[4][4];
#pragma unroll
        for (int nt = 0; nt < 4; nt++)
#pragma unroll
            for (int j = 0; j < 4; j++) s[nt][j] = 0.f;
#pragma unroll
        for (int kt = 0; kt < 8; kt++) {
            uint32_t bb[4][2];
#pragma unroll
            for (int nt = 0; nt < 4; nt++) {
                bb[nt][0] = __float_as_uint(Kt[(nt * 8 + g) * KSTR + kt * 8 + c4]);
                bb[nt][1] = __float_as_uint(Kt[(nt * 8 + g) * KSTR + kt * 8 + c4 + 4]);
            }
#pragma unroll
            for (int nt = 0; nt < 4; nt++)
                mma_tf32(s[nt], qf[kt], bb[nt]);
        }
#pragma unroll
        for (int nt = 0; nt < 4; nt++)
#pragma unroll
            for (int j = 0; j < 4; j++) s[nt][j] *= 0.125f;

        float ml0 = s[0][0], ml1 = s[0][2];
#pragma unroll
        for (int nt = 0; nt < 4; nt++) {
            ml0 = fmaxf(ml0, fmaxf(s[nt][0], s[nt][1]));
            ml1 = fmaxf(ml1, fmaxf(s[nt][2], s[nt][3]));
        }
        ml0 = fmaxf(ml0, __shfl_xor_sync(0xffffffffu, ml0, 1));
        ml0 = fmaxf(ml0, __shfl_xor_sync(0xffffffffu, ml0, 2));
        ml1 = fmaxf(ml1, __shfl_xor_sync(0xffffffffu, ml1, 1));
        ml1 = fmaxf(ml1, __shfl_xor_sync(0xffffffffu, ml1, 2));

        float mn0 = fmaxf(m_run[0], ml0);
        float mn1 = fmaxf(m_run[1], ml1);
        float sc0 = __expf(m_run[0] - mn0);
        float sc1 = __expf(m_run[1] - mn1);
        m_run[0] = mn0; m_run[1] = mn1;

        float ps0 = 0.f, ps1 = 0.f;
#pragma unroll
        for (int nt = 0; nt < 4; nt++) {
            s[nt][0] = roundtf(__expf(s[nt][0] - mn0)); ps0 += s[nt][0];
            s[nt][1] = roundtf(__expf(s[nt][1] - mn0)); ps0 += s[nt][1];
            s[nt][2] = roundtf(__expf(s[nt][2] - mn1)); ps1 += s[nt][2];
            s[nt][3] = roundtf(__expf(s[nt][3] - mn1)); ps1 += s[nt][3];
        }
        ps0 += __shfl_xor_sync(0xffffffffu, ps0, 1);
        ps0 += __shfl_xor_sync(0xffffffffu, ps0, 2);
        ps1 += __shfl_xor_sync(0xffffffffu, ps1, 1);
        ps1 += __shfl_xor_sync(0xffffffffu, ps1, 2);
        l_run[0] = l_run[0] * sc0 + ps0;
        l_run[1] = l_run[1] * sc1 + ps1;

#pragma unroll
        for (int nt = 0; nt < 8; nt++) {
            o[nt][0] *= sc0; o[nt][1] *= sc0;
            o[nt][2] *= sc1; o[nt][3] *= sc1;
        }
        {
            int r = w * 16 + g;
#pragma unroll
            for (int nt = 0; nt < 4; nt++) {
                *(float2*)&Pt[r * PSTR + nt * 8 + 2 * c4] = make_float2(s[nt][0], s[nt][1]);
                *(float2*)&Pt[(r + 8) * PSTR + nt * 8 + 2 * c4] = make_float2(s[nt][2], s[nt][3]);
            }
        }
        __syncwarp();

        // ---- P @ V ----
#pragma unroll
        for (int kt = 0; kt < 4; kt++) {
            uint32_t pa[4];
            int r = w * 16 + g;
            pa[0] = __float_as_uint(Pt[r * PSTR + kt * 8 + c4]);
            pa[1] = __float_as_uint(Pt[(r + 8) * PSTR + kt * 8 + c4]);
            pa[2] = __float_as_uint(Pt[r * PSTR + kt * 8 + c4 + 4]);
            pa[3] = __float_as_uint(Pt[(r + 8) * PSTR + kt * 8 + c4 + 4]);
#pragma unroll
            for (int nt = 0; nt < 8; nt++) {
                uint32_t bv[2];
                bv[0] = __float_as_uint(Vt[(kt * 8 + c4) * VSTR + nt * 8 + g]);
                bv[1] = __float_as_uint(Vt[(kt * 8 + c4 + 4) * VSTR + nt * 8 + g]);
                mma_tf32(o[nt], pa, bv);
            }
        }
    }
#undef AISSUE

    // ---- normalize + store ----
    {
        float inv0 = 1.f / l_run[0];
        float inv1 = 1.f / l_run[1];
        int r = qbase + w * 16 + g;
#pragma unroll
        for (int nt = 0; nt < 8; nt++) {
            int col = head * HDq + nt * 8 + 2 * c4;
            *(float2*)&out[(size_t)r * Dq + col] =
                make_float2(roundtf(o[nt][0] * inv0), roundtf(o[nt][1] * inv0));
            *(float2*)&out[(size_t)(r + 8) * Dq + col] =
                make_float2(roundtf(o[nt][2] * inv1), roundtf(o[nt][3] * inv1));
        }
    }
}

// -------------------- bulk weight packing (all layers, once) --------------
__global__ void pack3_all_kernel(const float* __restrict__ Wq, const float* __restrict__ Wk,
                                 const float* __restrict__ Wv, const float* __restrict__ bq,
                                 const float* __restrict__ bk, const float* __restrict__ bv,
                                 float* __restrict__ BpT, float* __restrict__ bp) {
    int i = blockIdx.x * 256 + threadIdx.x;
    if (i < Lq * Dq * Dq) {
        int l = i >> 18;
        int r = i & (Dq * Dq - 1);
        int n = r >> 9, k = r & 511;
        size_t so = (size_t)l * Dq * Dq + (size_t)k * Dq + n;
        float* dst = BpT + (size_t)l * 3 * Dq * Dq;
        dst[(size_t)n * Dq + k] = roundtf(Wq[so]);
        dst[(size_t)(Dq + n) * Dq + k] = roundtf(Wk[so]);
        dst[(size_t)(2 * Dq + n) * Dq + k] = roundtf(Wv[so]);
    }
    if (i < Lq * Dq) {
        int l = i >> 9, n = i & 511;
        bp[l * 3 * Dq + n] = bq[l * Dq + n];
        bp[l * 3 * Dq + Dq + n] = bk[l * Dq + n];
        bp[l * 3 * Dq + 2 * Dq + n] = bv[l * Dq + n];
    }
}
__global__ void pack2_all_kernel(const float* __restrict__ Wg, const float* __restrict__ Wu,
                                 const float* __restrict__ bg, const float* __restrict__ bu,
                                 float* __restrict__ BpT, float* __restrict__ bp) {
    int i = blockIdx.x * 256 + threadIdx.x;
    if (i < Lq * 2 * Dq * Dq) {
        int l = i >> 19;
        int r = i & (2 * Dq * Dq - 1);
        int n = r >> 10, k = r & 1023;
        size_t so = (size_t)l * 2 * Dq * Dq + (size_t)k * Dq + n;
        float* dst = BpT + (size_t)l * 2 * Dq * 2 * Dq;
        dst[(size_t)n * 2 * Dq + k] = roundtf(Wg[so]);
        dst[(size_t)(Dq + n) * 2 * Dq + k] = roundtf(Wu[so]);
    }
    if (i < Lq * Dq) {
        int l = i >> 9, n = i & 511;
        bp[l * 2 * Dq + n] = bg[l * Dq + n];
        bp[l * 2 * Dq + Dq + n] = bu[l * Dq + n];
    }
}
__global__ void packo_all_kernel(const float* __restrict__ Wo, float* __restrict__ dst) {
    int i = blockIdx.x * 256 + threadIdx.x;
    if (i < Lq * Dq * Dq) {
        int l = i >> 18;
        int r = i & (Dq * Dq - 1);
        int n = r >> 9, k = r & 511;
        dst[(size_t)l * Dq * Dq + (size_t)n * Dq + k] =
            roundtf(Wo[(size_t)l * Dq * Dq + (size_t)k * Dq + n]);
    }
}
__global__ void roundcpy_t_kernel(const float* __restrict__ src,
                                  float* __restrict__ dst, int K, int N) {
    int i = blockIdx.x * 256 + threadIdx.x;
    if (i < K * N) {
        int n = i / K, k = i - n * K;
        dst[i] = roundtf(src[(size_t)k * N + n]);
    }
}
__global__ void convw_kernel(const float* __restrict__ w, float* __restrict__ wcT) {
    int i = blockIdx.x * 256 + threadIdx.x;
    if (i < CFq * Dq * Dq) {
        int o = i >> 11, r = i & 2047;
        int j = r >> 9, c = r & 511;
        wcT[i] = roundtf(w[(size_t)o * (Dq * CFq) + c * CFq + j]);
    }
}

// -------------------- embedding: cat = [x@W_feat + b_feat, emb[ts]] -------
__global__ __launch_bounds__(128)
void build_cat_kernel(const float* __restrict__ x, const int* __restrict__ ts,
                      const float* __restrict__ Wf, const float* __restrict__ bf,
                      const float* __restrict__ emb, float* __restrict__ cat) {
    int t = blockIdx.x;
    int d = threadIdx.x;
    __shared__ float xr[Fq];
    if (d < Fq) xr[d] = x[t * Fq + d];
    __syncthreads();
    float s = bf[d];
#pragma unroll
    for (int i = 0; i < Fq; i++) s += xr[i] * Wf[i * FDq + d];
    cat[t * 2 * FDq + d] = roundtf(s);
    cat[t * 2 * FDq + FDq + d] = roundtf(emb[ts[t] * FDq + d]);
}

// -------------------- fp32 SGEMM (small final projection only) ------------
#define BM 64
#define BN 64
#define BKq 16
__global__ __launch_bounds__(256)
void gemm_kernel(const float* __restrict__ A0,
                 const float* __restrict__ Bm, const float* __restrict__ bias,
                 float* __restrict__ C, int M, int N, int K) {
    __shared__ float As[BKq][BM];
    __shared__ float Bs[BKq][BN];
    int tid = threadIdx.x;
    int tx = tid & 15, ty = tid >> 4;
    int row0 = blockIdx.y * BM;
    int col0 = blockIdx.x * BN;
    float acc[4][4];
#pragma unroll
    for (int i = 0; i < 4; i++)
#pragma unroll
        for (int j = 0; j < 4; j++) acc[i][j] = 0.f;

    for (int k0 = 0; k0 < K; k0 += BKq) {
#pragma unroll
        for (int it = 0; it < 4; it++) {
            int idx = tid + it * 256;
            int m = idx >> 4, kk = idx & 15;
            int r = row0 + m;
            As[kk][m] = (r < M) ? A0[(size_t)r * K + k0 + kk] : 0.f;
        }
#pragma unroll
        for (int it = 0; it < 4; it++) {
            int idx = tid + it * 256;
            int kk = idx >> 6, n = idx & 63;
            int gn = col0 + n;
            Bs[kk][n] = (gn < N) ? Bm[(size_t)(k0 + kk) * N + gn] : 0.f;
        }
        __syncthreads();
#pragma unroll
        for (int kk = 0; kk < BKq; kk++) {
            float4 a4 = *reinterpret_cast<const float4*>(&As[kk][ty * 4]);
            float4 b4 = *reinterpret_cast<const float4*>(&Bs[kk][tx * 4]);
            float a[4] = {a4.x, a4.y, a4.z, a4.w};
            float b[4] = {b4.x, b4.y, b4.z, b4.w};
#pragma unroll
            for (int i = 0; i < 4; i++)
#pragma unroll
                for (int j = 0; j < 4; j++) acc[i][j] += a[i] * b[j];
        }
        __syncthreads();
    }
#pragma unroll
    for (int i = 0; i < 4; i++) {
        int r = row0 + ty * 4 + i;
        if (r >= M) continue;
#pragma unroll
        for (int j = 0; j < 4; j++) {
            int cc = col0 + tx * 4 + j;
            if (cc < N) C[(size_t)r * N + cc] = acc[i][j] + bias[cc];
        }
    }
}

// -------------------- fused gate + memory + LayerNorm (warp/token) --------
__global__ __launch_bounds__(256)
void gate_ln_kernel(const float* __restrict__ a, const float* __restrict__ gu,
                    float* __restrict__ mem,
                    const float* __restrict__ g, const float* __restrict__ bta,
                    float* __restrict__ hout, int first) {
    int w = threadIdx.x >> 5, lane = threadIdx.x & 31;
    int t = blockIdx.x * 8 + w;
    size_t base = (size_t)t * Dq;
    size_t gbase = (size_t)t * 2 * Dq;

    float y[16];
    float sum = 0.f;
#pragma unroll
    for (int j = 0; j < 4; j++) {
        int d = (lane + 32 * j) * 4;
        float4 gg = *(const float4*)&gu[gbase + d];
        float4 uu = *(const float4*)&gu[gbase + Dq + d];
        float4 av = *(const float4*)&a[base + d];
        float4 mm = first ? make_float4(0.f, 0.f, 0.f, 0.f)
                          : *(const float4*)&mem[base + d];
        float g0 = 1.f / (1.f + __expf(-gg.x));
        float g1 = 1.f / (1.f + __expf(-gg.y));
        float g2 = 1.f / (1.f + __expf(-gg.z));
        float g3 = 1.f / (1.f + __expf(-gg.w));
        float nm0 = g0 * uu.x + (1.f - g0) * mm.x;
        float nm1 = g1 * uu.y + (1.f - g1) * mm.y;
        float nm2 = g2 * uu.z + (1.f - g2) * mm.z;
        float nm3 = g3 * uu.w + (1.f - g3) * mm.w;
        *(float4*)&mem[base + d] = make_float4(roundtf(nm0), roundtf(nm1),
                                               roundtf(nm2), roundtf(nm3));
        y[j * 4 + 0] = av.x + nm0;
        y[j * 4 + 1] = av.y + nm1;
        y[j * 4 + 2] = av.z + nm2;
        y[j * 4 + 3] = av.w + nm3;
        sum += y[j * 4] + y[j * 4 + 1] + y[j * 4 + 2] + y[j * 4 + 3];
    }
    float mean = warp_sum(sum) * (1.f / Dq);
    float vs = 0.f;
#pragma unroll
    for (int i = 0; i < 16; i++) {
        float dv = y[i] - mean;
        vs += dv * dv;
    }
    float rs = rsqrtf(warp_sum(vs) * (1.f / Dq) + 1e-5f);
#pragma unroll
    for (int j = 0; j < 4; j++) {
        int d = (lane + 32 * j) * 4;
        float4 gv = *(const float4*)&g[d];
        float4 bv = *(const float4*)&bta[d];
        float4 ov;
        ov.x = roundtf((y[j * 4 + 0] - mean) * rs * gv.x + bv.x);
        ov.y = roundtf((y[j * 4 + 1] - mean) * rs * gv.y + bv.y);
        ov.z = roundtf((y[j * 4 + 2] - mean) * rs * gv.z + bv.z);
        ov.w = roundtf((y[j * 4 + 3] - mean) * rs * gv.w + bv.w);
        *(float4*)&hout[base + d] = ov;
    }
}

// -------------------- double LayerNorm (warp/token) -----------------------
__global__ __launch_bounds__(256)
void double_ln_kernel(const float* __restrict__ c, const float* __restrict__ cg,
                      const float* __restrict__ cb, const float* __restrict__ og,
                      const float* __restrict__ ob, float* __restrict__ out) {
    int w = threadIdx.x >> 5, lane = threadIdx.x & 31;
    int t = blockIdx.x * 8 + w;
    size_t base = (size_t)t * Dq;

    float y[16];
    float sum = 0.f;
#pragma unroll
    for (int j = 0; j < 4; j++) {
        int d = (lane + 32 * j) * 4;
        float4 v = *(const float4*)&c[base + d];
        y[j * 4 + 0] = v.x; y[j * 4 + 1] = v.y;
        y[j * 4 + 2] = v.z; y[j * 4 + 3] = v.w;
        sum += v.x + v.y + v.z + v.w;
    }
    float mean = warp_sum(sum) * (1.f / Dq);
    float vs = 0.f;
#pragma unroll
    for (int i = 0; i < 16; i++) {
        float dv = y[i] - mean;
        vs += dv * dv;
    }
    float rs = rsqrtf(warp_sum(vs) * (1.f / Dq) + 1e-5f);

    float z[16];
    float sum2 = 0.f;
#pragma unroll
    for (int j = 0; j < 4; j++) {
        int d = (lane + 32 * j) * 4;
        float4 gv = *(const float4*)&cg[d];
        float4 bv = *(const float4*)&cb[d];
        z[j * 4 + 0] = (y[j * 4 + 0] - mean) * rs * gv.x + bv.x;
        z[j * 4 + 1] = (y[j * 4 + 1] - mean) * rs * gv.y + bv.y;
        z[j * 4 + 2] = (y[j * 4 + 2] - mean) * rs * gv.z + bv.z;
        z[j * 4 + 3] = (y[j * 4 + 3] - mean) * rs * gv.w + bv.w;
        sum2 += z[j * 4] + z[j * 4 + 1] + z[j * 4 + 2] + z[j * 4 + 3];
    }
    float mean2 = warp_sum(sum2) * (1.f / Dq);
    float vs2 = 0.f;
#pragma unroll
    for (int i = 0; i < 16; i++) {
        float dv = z[i] - mean2;
        vs2 += dv * dv;
    }
    float rs2 = rsqrtf(warp_sum(vs2) * (1.f / Dq) + 1e-5f);
#pragma unroll
    for (int j = 0; j < 4; j++) {
        int d = (lane + 32 * j) * 4;
        float4 gv = *(const float4*)&og[d];
        float4 bv = *(const float4*)&ob[d];
        float4 ov;
        ov.x = roundtf((z[j * 4 + 0] - mean2) * rs2 * gv.x + bv.x);
        ov.y = roundtf((z[j * 4 + 1] - mean2) * rs2 * gv.y + bv.y);
        ov.z = roundtf((z[j * 4 + 2] - mean2) * rs2 * gv.z + bv.z);
        ov.w = roundtf((z[j * 4 + 3] - mean2) * rs2 * gv.w + bv.w);
        *(float4*)&out[base + d] = ov;
    }
}

// ==========================================================================
extern "C" void kernel_launch(void* const* d_in, const int* in_sizes, int n_in,
                              void* d_out, int out_size) {
    const float* x       = (const float*)d_in[0];
    const int*   ts      = (const int*)d_in[1];
    const float* W_feat  = (const float*)d_in[2];
    const float* b_feat  = (const float*)d_in[3];
    const float* emb     = (const float*)d_in[4];
    const float* W_emb   = (const float*)d_in[5];
    const float* b_emb   = (const float*)d_in[6];
    const float* Wq      = (const float*)d_in[7];
    const float* bq      = (const float*)d_in[8];
    const float* Wk      = (const float*)d_in[9];
    const float* bk      = (const float*)d_in[10];
    const float* Wv      = (const float*)d_in[11];
    const float* bv      = (const float*)d_in[12];
    const float* Wo      = (const float*)d_in[13];
    const float* bo      = (const float*)d_in[14];
    const float* Wg      = (const float*)d_in[15];
    const float* bg      = (const float*)d_in[16];
    const float* Wu      = (const float*)d_in[17];
    const float* bu      = (const float*)d_in[18];
    const float* ln_g    = (const float*)d_in[19];
    const float* ln_b    = (const float*)d_in[20];
    const float* conv_w  = (const float*)d_in[21];
    const float* conv_b  = (const float*)d_in[22];
    const float* cn_g    = (const float*)d_in[23];
    const float* cn_b    = (const float*)d_in[24];
    const float* on_g    = (const float*)d_in[25];
    const float* on_b    = (const float*)d_in[26];
    const float* W_out   = (const float*)d_in[27];
    const float* b_out   = (const float*)d_in[28];
    float* out = (float*)d_out;

    float *cat, *h, *mem, *qkv, *ap, *a, *gu, *c, *c2, *wc;
    float *wqkvT, *bqkv, *wguT, *bgu, *woT, *wembT;
    cudaGetSymbolAddress((void**)&cat, g_cat);
    cudaGetSymbolAddress((void**)&h,   g_h);
    cudaGetSymbolAddress((void**)&mem, g_mem);
    cudaGetSymbolAddress((void**)&qkv, g_qkv);
    cudaGetSymbolAddress((void**)&ap,  g_ap);
    cudaGetSymbolAddress((void**)&a,   g_a);
    cudaGetSymbolAddress((void**)&gu,  g_gu);
    cudaGetSymbolAddress((void**)&c,   g_c);
    cudaGetSymbolAddress((void**)&c2,  g_c2);
    cudaGetSymbolAddress((void**)&wc,  g_wc);
    cudaGetSymbolAddress((void**)&wqkvT, g_wqkvT);
    cudaGetSymbolAddress((void**)&bqkv,  g_bqkv);
    cudaGetSymbolAddress((void**)&wguT,  g_wguT);
    cudaGetSymbolAddress((void**)&bgu,   g_bgu);
    cudaGetSymbolAddress((void**)&woT,   g_woT);
    cudaGetSymbolAddress((void**)&wembT, g_wembT);

    static int smem_set = 0;
    if (!smem_set) {
        cudaFuncSetAttribute(gemm_tc_kernel,
                             cudaFuncAttributeMaxDynamicSharedMemorySize, SMEM_TC);
        cudaFuncSetAttribute(attn_tc_kernel,
                             cudaFuncAttributeMaxDynamicSharedMemorySize, SMEM_ATT);
        smem_set = 1;
    }

    // 0. bulk weight pre-pack (all layers, 5 launches total)
    pack3_all_kernel<<<(Lq * Dq * Dq + 255) / 256, 256>>>(Wq, Wk, Wv, bq, bk, bv,
                                                          wqkvT, bqkv);
    pack2_all_kernel<<<(Lq * 2 * Dq * Dq + 255) / 256, 256>>>(Wg, Wu, bg, bu,
                                                              wguT, bgu);
    packo_all_kernel<<<(Lq * Dq * Dq + 255) / 256, 256>>>(Wo, woT);
    roundcpy_t_kernel<<<(2 * FDq * Dq + 255) / 256, 256>>>(W_emb, wembT, 2 * FDq, Dq);
    convw_kernel<<<(CFq * Dq * Dq + 255) / 256, 256>>>(conv_w, wc);

    // 1. embedding
    build_cat_kernel<<<NTq, 128>>>(x, ts, W_feat, b_feat, emb, cat);
    launch_tc(cat, cat, 8, 2 * FDq, 2 * FDq, wembT, 2 * FDq, b_emb, h, Dq,
              NTq, Dq, 2 * FDq, 1);

    // 2. layers (mem implicitly zero in layer 0)
    for (int l = 0; l < Lq; l++) {
        launch_tc(h, h, 16, Dq, Dq, wqkvT + (size_t)l * 3 * Dq * Dq, Dq,
                  bqkv + l * 3 * Dq, qkv, 3 * Dq, NTq, 3 * Dq, Dq, 1);

        attn_tc_kernel<<<dim3(NBq, Hq, Bq), 512, SMEM_ATT>>>(qkv, ap);

        launch_tc(ap, ap, 16, Dq, Dq, woT + (size_t)l * Dq * Dq, Dq,
                  bo + l * Dq, a, Dq, NTq, Dq, Dq, 1);

        if (l == 0)
            launch_tc(a, a, 16, Dq, Dq, wguT + (size_t)l * 2 * Dq * 2 * Dq, 2 * Dq,
                      bgu + l * 2 * Dq, gu, 2 * Dq, NTq, 2 * Dq, Dq, 0);
        else
            launch_tc(a, mem, 16, Dq, Dq, wguT + (size_t)l * 2 * Dq * 2 * Dq, 2 * Dq,
                      bgu + l * 2 * Dq, gu, 2 * Dq, NTq, 2 * Dq, 2 * Dq, 0);

        gate_ln_kernel<<<NTq / 8, 256>>>(a, gu, mem, ln_g + l * Dq,
                                         ln_b + l * Dq, h, l == 0);
    }

    // 3. temporal compression (conv as GEMM; weight transposed [512][2048])
    launch_tc(h, h, 64, CFq * Dq, CFq * Dq, wc, CFq * Dq, conv_b, c, Dq,
              Bq * NCq, Dq, CFq * Dq, 0);

    // 4. double LayerNorm
    double_ln_kernel<<<Bq * NCq / 8, 256>>>(c, cn_g, cn_b, on_g, on_b, c2);

    // 5. output projection (small: fp32 path)
    {
        dim3 grid((Fq + BN - 1) / BN, (Bq * NCq + BM - 1) / BM);
        gemm_kernel<<<grid, 256>>>(c2, W_out, b_out, out, Bq * NCq, Fq, Dq);
    }
}

// round 14
// speedup vs baseline: 1.0959x; 1.0201x over previous
#include <cuda_runtime.h>
#include <cuda_bf16.h>
#include <cstdint>

// Problem constants
#define Bq 4
#define Sq 8192
#define Fq 32
#define Dq 512
#define Hq 8
#define Lq 4
#define FDq 128
#define WINq 256
#define CFq 4
#define HDq 64
#define NTq (Bq * Sq)          // 32768 tokens
#define NBq (Sq / WINq)        // 32 windows
#define NCq (Sq / CFq)         // 2048 compressed steps per batch

// -------------------- scratch (device globals; no allocation allowed) -----
__device__ float g_cat[NTq * 2 * FDq];
__device__ float g_h  [NTq * Dq];
__device__ float g_mem[NTq * Dq];
__device__ float g_qkv[NTq * 3 * Dq];
__device__ float g_ap [NTq * Dq];
__device__ float g_a  [NTq * Dq];
__device__ float g_gu [NTq * 2 * Dq];
__device__ float g_c  [Bq * NCq * Dq];
__device__ float g_c2 [Bq * NCq * Dq];
__device__ float g_wc [CFq * Dq * Dq];         // conv weight^T [512][2048]
__device__ float g_wqkvT[Lq * 3 * Dq * Dq];    // per-layer [1536][512]
__device__ float g_bqkv [Lq * 3 * Dq];
__device__ float g_wguT [Lq * 2 * Dq * 2 * Dq];// per-layer [1024][1024]
__device__ float g_bgu  [Lq * 2 * Dq];
__device__ float g_woT  [Lq * Dq * Dq];        // per-layer [512][512]
__device__ float g_wembT[2 * FDq * Dq];        // [512][256]

// ==================== helpers =============================================
__device__ __forceinline__ uint32_t smem_u32(const void* p) {
    uint32_t a;
    asm("{ .reg .u64 t; cvta.to.shared.u64 t, %1; cvt.u32.u64 %0, t; }"
        : "=r"(a) : "l"(p));
    return a;
}
__device__ __forceinline__ uint32_t f2tf(float f) {
    uint32_t u;
    asm("cvt.rna.tf32.f32 %0, %1;" : "=r"(u) : "f"(f));
    return u;
}
__device__ __forceinline__ float roundtf(float f) {
    return __uint_as_float(f2tf(f));
}
__device__ __forceinline__ void mma_tf32(float* d, const uint32_t* a,
                                         const uint32_t* b) {
    asm volatile(
        "mma.sync.aligned.m16n8k8.row.col.f32.tf32.tf32.f32 "
        "{%0,%1,%2,%3}, {%4,%5,%6,%7}, {%8,%9}, {%0,%1,%2,%3};"
        : "+f"(d[0]), "+f"(d[1]), "+f"(d[2]), "+f"(d[3])
        : "r"(a[0]), "r"(a[1]), "r"(a[2]), "r"(a[3]), "r"(b[0]), "r"(b[1]));
}
__device__ __forceinline__ void cpa16(uint32_t dst, const float* src) {
    asm volatile("cp.async.cg.shared.global [%0], [%1], 16;"
                 :: "r"(dst), "l"(src));
}
__device__ __forceinline__ void ldsm4(uint32_t* r, uint32_t addr) {
    asm volatile("ldmatrix.sync.aligned.m8n8.x4.shared.b16 {%0,%1,%2,%3}, [%4];"
                 : "=r"(r[0]), "=r"(r[1]), "=r"(r[2]), "=r"(r[3]) : "r"(addr));
}
__device__ __forceinline__ float warp_sum(float v) {
#pragma unroll
    for (int o = 16; o > 0; o >>= 1)
        v += __shfl_xor_sync(0xffffffffu, v, o);
    return v;
}
#define CPA_COMMIT() asm volatile("cp.async.commit_group;" ::: "memory")
#define CPA_WAIT1()  asm volatile("cp.async.wait_group 1;" ::: "memory")

// ==================== tf32 tensor-core GEMM ===============================
// EXACT R10 configuration (best passing: 4608 us):
// 128x128 tile, 256 thr, 2 CTA/SM, K-chunk 32, 3 stages, single barrier.
#define ASTR 36
#define ST_W (128 * ASTR)
#define SMEM_TC (6 * ST_W * 4)     // 110592 bytes

__global__ __launch_bounds__(256, 2)
void gemm_tc_kernel(const float* __restrict__ A0, const float* __restrict__ A1,
                    int scChunks, int lda0, int lda1,
                    const float* __restrict__ BmT, int ldbt,
                    const float* __restrict__ bias,
                    float* __restrict__ C, int ldc, int nChunks, int roundOut) {
    extern __shared__ float smem[];
    uint32_t sbase = smem_u32(smem);

    int tid = threadIdx.x;
    int lane = tid & 31, wid = tid >> 5;
    int warpM = wid & 3, warpN = wid >> 2;
    int g = lane >> 2, c4 = lane & 3;
    int rowbase = blockIdx.y * 128;
    int colbase = blockIdx.x * 128;

    int rowA = warpM * 32 + (lane & 15);
    uint32_t aOff = (uint32_t)(rowA * ASTR + (lane >> 4) * 4) * 4;
    int rowB = warpN * 64 + ((lane >> 4) << 3) + (lane & 7);
    uint32_t bOff = (uint32_t)(rowB * ASTR + ((lane >> 3) & 1) * 4) * 4;

    float acc[2][8][4];
#pragma unroll
    for (int mi = 0; mi < 2; mi++)
#pragma unroll
        for (int nj = 0; nj < 8; nj++)
#pragma unroll
            for (int r = 0; r < 4; r++) acc[mi][nj][r] = 0.f;

#define ISSUE(ch) do { \
        int _st = (ch) % 3; \
        uint32_t _sa = sbase + (uint32_t)(_st * ST_W) * 4; \
        uint32_t _sb = sbase + (uint32_t)((3 + _st) * ST_W) * 4; \
        const float* Ap; int kc, lda; \
        if ((ch) < scChunks) { Ap = A0; kc = (ch); lda = lda0; } \
        else { Ap = A1; kc = (ch) - scChunks; lda = lda1; } \
        _Pragma("unroll") \
        for (int i = 0; i < 4; i++) { \
            int id = tid + i * 256; int r = id >> 3, sg = id & 7; \
            cpa16(_sa + (uint32_t)(r * ASTR + sg * 4) * 4, \
                  Ap + (size_t)(rowbase + r) * lda + kc * 32 + sg * 4); \
            cpa16(_sb + (uint32_t)(r * ASTR + sg * 4) * 4, \
                  BmT + (size_t)(colbase + r) * ldbt + (ch) * 32 + sg * 4); \
        } \
    } while (0)

    ISSUE(0); CPA_COMMIT();
    ISSUE(1); CPA_COMMIT();

    for (int ch = 0; ch < nChunks; ch++) {
        int st = ch % 3;
        CPA_WAIT1();
        __syncthreads();
        if (ch + 2 < nChunks) ISSUE(ch + 2);
        CPA_COMMIT();

        uint32_t aBase = sbase + (uint32_t)(st * ST_W) * 4 + aOff;
        uint32_t bBase = sbase + (uint32_t)((3 + st) * ST_W) * 4 + bOff;
#pragma unroll
        for (int kk = 0; kk < 4; kk++) {
            uint32_t af[2][4], bf[4][4];
            ldsm4(af[0], aBase + kk * 32);
            ldsm4(af[1], aBase + 16 * ASTR * 4 + kk * 32);
#pragma unroll
            for (int pr = 0; pr < 4; pr++)
                ldsm4(bf[pr], bBase + pr * 16 * ASTR * 4 + kk * 32);
#pragma unroll
            for (int mi = 0; mi < 2; mi++)
#pragma unroll
                for (int pr = 0; pr < 4; pr++) {
                    mma_tf32(acc[mi][2 * pr],     af[mi], &bf[pr][0]);
                    mma_tf32(acc[mi][2 * pr + 1], af[mi], &bf[pr][2]);
                }
        }
    }
#undef ISSUE

#pragma unroll
    for (int mi = 0; mi < 2; mi++) {
        int r0 = rowbase + warpM * 32 + mi * 16 + g;
#pragma unroll
        for (int nj = 0; nj < 8; nj++) {
            int col = colbase + warpN * 64 + nj * 8 + 2 * c4;
            float b0 = bias[col], b1 = bias[col + 1];
            float o0 = acc[mi][nj][0] + b0, o1 = acc[mi][nj][1] + b1;
            float o2 = acc[mi][nj][2] + b0, o3 = acc[mi][nj][3] + b1;
            if (roundOut) {
                o0 = roundtf(o0); o1 = roundtf(o1);
                o2 = roundtf(o2); o3 = roundtf(o3);
            }
            *(float2*)(C + (size_t)r0 * ldc + col) = make_float2(o0, o1);
            *(float2*)(C + (size_t)(r0 + 8) * ldc + col) = make_float2(o2, o3);
        }
    }
}

static inline void launch_tc(const float* A0, const float* A1, int sc,
                             int lda0, int lda1, const float* BmT, int ldbt,
                             const float* bias, float* C, int ldc,
                             int M, int N, int K, int roundOut) {
    dim3 grid(N / 128, M / 128);
    gemm_tc_kernel<<<grid, 256, SMEM_TC>>>(A0, A1, sc, lda0, lda1, BmT, ldbt,
                                           bias, C, ldc, K / 32, roundOut);
}

// ==================== tensor-core windowed attention ======================
// EXACT R10 version (256 threads, 3 K/V stages, single barrier per chunk).
#define KSTR 68
#define VSTR 72
#define PSTR 36
#define SMA_K(s) ((s) * 32 * KSTR)
#define SMA_VB   (3 * 32 * KSTR)
#define SMA_V(s) (SMA_VB + (s) * 32 * VSTR)
#define SMA_P    (3 * 32 * KSTR + 3 * 32 * VSTR)
#define SMEM_ATT ((SMA_P + 256 * PSTR) * 4)

__global__ __launch_bounds__(256)
void attn_tc_kernel(const float* __restrict__ qkv, float* __restrict__ out) {
    extern __shared__ float sm[];
    int blk = blockIdx.x, head = blockIdx.y, b = blockIdx.z;
    int tid = threadIdx.x, lane = tid & 31, w = tid >> 5;
    int g = lane >> 2, c4 = lane & 3;
    const int LD = 3 * Dq;
    const int qbase = b * Sq + blk * WINq;
    uint32_t sbase = smem_u32(sm);

    {
        const float4* src = (const float4*)(qkv + (size_t)(qbase + tid) * LD + head * HDq);
        float* dst = sm + tid * KSTR;
#pragma unroll
        for (int j = 0; j < 16; j++) *(float4*)(dst + j * 4) = src[j];
    }
    __syncthreads();
    uint32_t qf[2][8][4];
#pragma unroll
    for (int mi = 0; mi < 2; mi++) {
        int r = w * 32 + mi * 16 + g;
#pragma unroll
        for (int kt = 0; kt < 8; kt++) {
            qf[mi][kt][0] = __float_as_uint(sm[r * KSTR + kt * 8 + c4]);
            qf[mi][kt][1] = __float_as_uint(sm[(r + 8) * KSTR + kt * 8 + c4]);
            qf[mi][kt][2] = __float_as_uint(sm[r * KSTR + kt * 8 + c4 + 4]);
            qf[mi][kt][3] = __float_as_uint(sm[(r + 8) * KSTR + kt * 8 + c4 + 4]);
        }
    }
    __syncthreads();

    float o[2][8][4];
#pragma unroll
    for (int mi = 0; mi < 2; mi++)
#pragma unroll
        for (int nt = 0; nt < 8; nt++)
#pragma unroll
            for (int j = 0; j < 4; j++) o[mi][nt][j] = 0.f;
    float m_run[2][2] = {{-1e30f, -1e30f}, {-1e30f, -1e30f}};
    float l_run[2][2] = {{0.f, 0.f}, {0.f, 0.f}};

    const int ktok0 = b * Sq + (blk - 1) * WINq;
    const int c0 = (blk == 0) ? 8 : 0;

#define AISSUE(ci) do { \
        int _st = (ci) % 3; \
        int r = tid >> 3, sg = tid & 7; \
        const float* kv = qkv + (size_t)(ktok0 + (ci) * 32 + r) * LD + head * HDq; \
        uint32_t kd = sbase + (uint32_t)(SMA_K(_st) + r * KSTR) * 4; \
        uint32_t vd = sbase + (uint32_t)(SMA_V(_st) + r * VSTR) * 4; \
        cpa16(kd + sg * 16,        kv + Dq + sg * 4); \
        cpa16(kd + (sg + 8) * 16,  kv + Dq + (sg + 8) * 4); \
        cpa16(vd + sg * 16,        kv + 2 * Dq + sg * 4); \
        cpa16(vd + (sg + 8) * 16,  kv + 2 * Dq + (sg + 8) * 4); \
    } while (0)

    AISSUE(c0);     CPA_COMMIT();
    AISSUE(c0 + 1); CPA_COMMIT();

    float* Pt = sm + SMA_P;
    for (int ci = c0; ci < 16; ci++) {
        CPA_WAIT1();
        __syncthreads();
        if (ci + 2 < 16) AISSUE(ci + 2);
        CPA_COMMIT();
        const float* Kt = sm + SMA_K(ci % 3);
        const float* Vt = sm + SMA_V(ci % 3);

#pragma unroll
        for (int mi = 0; mi < 2; mi++) {
            float s[4][4];
#pragma unroll
            for (int nt = 0; nt < 4; nt++)
#pragma unroll
                for (int j = 0; j < 4; j++) s[nt][j] = 0.f;
#pragma unroll
            for (int kt = 0; kt < 8; kt++) {
                uint32_t bb[4][2];
#pragma unroll
                for (int nt = 0; nt < 4; nt++) {
                    bb[nt][0] = __float_as_uint(Kt[(nt * 8 + g) * KSTR + kt * 8 + c4]);
                    bb[nt][1] = __float_as_uint(Kt[(nt * 8 + g) * KSTR + kt * 8 + c4 + 4]);
                }
#pragma unroll
                for (int nt = 0; nt < 4; nt++)
                    mma_tf32(s[nt], qf[mi][kt], bb[nt]);
            }
#pragma unroll
            for (int nt = 0; nt < 4; nt++)
#pragma unroll
                for (int j = 0; j < 4; j++) s[nt][j] *= 0.125f;

            float ml0 = s[0][0], ml1 = s[0][2];
#pragma unroll
            for (int nt = 0; nt < 4; nt++) {
                ml0 = fmaxf(ml0, fmaxf(s[nt][0], s[nt][1]));
                ml1 = fmaxf(ml1, fmaxf(s[nt][2], s[nt][3]));
            }
            ml0 = fmaxf(ml0, __shfl_xor_sync(0xffffffffu, ml0, 1));
            ml0 = fmaxf(ml0, __shfl_xor_sync(0xffffffffu, ml0, 2));
            ml1 = fmaxf(ml1, __shfl_xor_sync(0xffffffffu, ml1, 1));
            ml1 = fmaxf(ml1, __shfl_xor_sync(0xffffffffu, ml1, 2));

            float mn0 = fmaxf(m_run[mi][0], ml0);
            float mn1 = fmaxf(m_run[mi][1], ml1);
            float sc0 = __expf(m_run[mi][0] - mn0);
            float sc1 = __expf(m_run[mi][1] - mn1);
            m_run[mi][0] = mn0; m_run[mi][1] = mn1;

            float ps0 = 0.f, ps1 = 0.f;
#pragma unroll
            for (int nt = 0; nt < 4; nt++) {
                s[nt][0] = roundtf(__expf(s[nt][0] - mn0)); ps0 += s[nt][0];
                s[nt][1] = roundtf(__expf(s[nt][1] - mn0)); ps0 += s[nt][1];
                s[nt][2] = roundtf(__expf(s[nt][2] - mn1)); ps1 += s[nt][2];
                s[nt][3] = roundtf(__expf(s[nt][3] - mn1)); ps1 += s[nt][3];
            }
            ps0 += __shfl_xor_sync(0xffffffffu, ps0, 1);
            ps0 += __shfl_xor_sync(0xffffffffu, ps0, 2);
            ps1 += __shfl_xor_sync(0xffffffffu, ps1, 1);
            ps1 += __shfl_xor_sync(0xffffffffu, ps1, 2);
            l_run[mi][0] = l_run[mi][0] * sc0 + ps0;
            l_run[mi][1] = l_run[mi][1] * sc1 + ps1;

#pragma unroll
            for (int nt = 0; nt < 8; nt++) {
                o[mi][nt][0] *= sc0; o[mi][nt][1] *= sc0;
                o[mi][nt][2] *= sc1; o[mi][nt][3] *= sc1;
            }
            int r = w * 32 + mi * 16 + g;
#pragma unroll
            for (int nt = 0; nt < 4; nt++) {
                *(float2*)&Pt[r * PSTR + nt * 8 + 2 * c4] = make_float2(s[nt][0], s[nt][1]);
                *(float2*)&Pt[(r + 8) * PSTR + nt * 8 + 2 * c4] = make_float2(s[nt][2], s[nt][3]);
            }
        }
        __syncwarp();

#pragma unroll
        for (int kt = 0; kt < 4; kt++) {
            uint32_t pa[2][4];
#pragma unroll
            for (int mi = 0; mi < 2; mi++) {
                int r = w * 32 + mi * 16 + g;
                pa[mi][0] = __float_as_uint(Pt[r * PSTR + kt * 8 + c4]);
                pa[mi][1] = __float_as_uint(Pt[(r + 8) * PSTR + kt * 8 + c4]);
                pa[mi][2] = __float_as_uint(Pt[r * PSTR + kt * 8 + c4 + 4]);
                pa[mi][3] = __float_as_uint(Pt[(r + 8) * PSTR + kt * 8 + c4 + 4]);
            }
#pragma unroll
            for (int nt = 0; nt < 8; nt++) {
                uint32_t bv[2];
                bv[0] = __float_as_uint(Vt[(kt * 8 + c4) * VSTR + nt * 8 + g]);
                bv[1] = __float_as_uint(Vt[(kt * 8 + c4 + 4) * VSTR + nt * 8 + g]);
                mma_tf32(o[0][nt], pa[0], bv);
                mma_tf32(o[1][nt], pa[1], bv);
            }
        }
    }
#undef AISSUE

#pragma unroll
    for (int mi = 0; mi < 2; mi++) {
        float inv0 = 1.f / l_run[mi][0];
        float inv1 = 1.f / l_run[mi][1];
        int r = qbase + w * 32 + mi * 16 + g;
#pragma unroll
        for (int nt = 0; nt < 8; nt++) {
            int col = head * HDq + nt * 8 + 2 * c4;
            *(float2*)&out[(size_t)r * Dq + col] =
                make_float2(roundtf(o[mi][nt][0] * inv0), roundtf(o[mi][nt][1] * inv0));
            *(float2*)&out[(size_t)(r + 8) * Dq + col] =
                make_float2(roundtf(o[mi][nt][2] * inv1), roundtf(o[mi][nt][3] * inv1));
        }
    }
}

// -------------------- single merged weight pre-pack -----------------------
// Replicates the 5 former pack kernels' exact index math on one linear id.
__global__ void pack_all_kernel(
    const float* __restrict__ Wq, const float* __restrict__ Wk,
    const float* __restrict__ Wv, const float* __restrict__ bq,
    const float* __restrict__ bk, const float* __restrict__ bv,
    const float* __restrict__ Wg, const float* __restrict__ Wu,
    const float* __restrict__ bg, const float* __restrict__ bu,
    const float* __restrict__ Wo, const float* __restrict__ W_emb,
    const float* __restrict__ conv_w,
    float* __restrict__ wqkvT, float* __restrict__ bqkv,
    float* __restrict__ wguT, float* __restrict__ bgu,
    float* __restrict__ woT, float* __restrict__ wembT,
    float* __restrict__ wcT) {
    int i = blockIdx.x * 256 + threadIdx.x;
    // pack3 (qkv)
    if (i < Lq * Dq * Dq) {
        int l = i >> 18;
        int r = i & (Dq * Dq - 1);
        int n = r >> 9, k = r & 511;
        size_t so = (size_t)l * Dq * Dq + (size_t)k * Dq + n;
        float* dst = wqkvT + (size_t)l * 3 * Dq * Dq;
        dst[(size_t)n * Dq + k] = roundtf(Wq[so]);
        dst[(size_t)(Dq + n) * Dq + k] = roundtf(Wk[so]);
        dst[(size_t)(2 * Dq + n) * Dq + k] = roundtf(Wv[so]);
    }
    if (i < Lq * Dq) {
        int l = i >> 9, n = i & 511;
        bqkv[l * 3 * Dq + n] = bq[l * Dq + n];
        bqkv[l * 3 * Dq + Dq + n] = bk[l * Dq + n];
        bqkv[l * 3 * Dq + 2 * Dq + n] = bv[l * Dq + n];
        bgu[l * 2 * Dq + n] = bg[l * Dq + n];
        bgu[l * 2 * Dq + Dq + n] = bu[l * Dq + n];
    }
    // pack2 (gate/update)
    if (i < Lq * 2 * Dq * Dq) {
        int l = i >> 19;
        int r = i & (2 * Dq * Dq - 1);
        int n = r >> 10, k = r & 1023;
        size_t so = (size_t)l * 2 * Dq * Dq + (size_t)k * Dq + n;
        float* dst = wguT + (size_t)l * 2 * Dq * 2 * Dq;
        dst[(size_t)n * 2 * Dq + k] = roundtf(Wg[so]);
        dst[(size_t)(Dq + n) * 2 * Dq + k] = roundtf(Wu[so]);
    }
    // packo
    if (i < Lq * Dq * Dq) {
        int l = i >> 18;
        int r = i & (Dq * Dq - 1);
        int n = r >> 9, k = r & 511;
        woT[(size_t)l * Dq * Dq + (size_t)n * Dq + k] =
            roundtf(Wo[(size_t)l * Dq * Dq + (size_t)k * Dq + n]);
    }
    // W_emb transpose (K=256, N=512)
    if (i < 2 * FDq * Dq) {
        int n = i / (2 * FDq), k = i - n * (2 * FDq);
        wembT[i] = roundtf(W_emb[(size_t)k * Dq + n]);
    }
    // conv weight
    if (i < CFq * Dq * Dq) {
        int o = i >> 11, r = i & 2047;
        int j = r >> 9, c = r & 511;
        wcT[i] = roundtf(conv_w[(size_t)o * (Dq * CFq) + c * CFq + j]);
    }
}

// -------------------- embedding: cat = [x@W_feat + b_feat, emb[ts]] -------
__global__ __launch_bounds__(128)
void build_cat_kernel(const float* __restrict__ x, const int* __restrict__ ts,
                      const float* __restrict__ Wf, const float* __restrict__ bf,
                      const float* __restrict__ emb, float* __restrict__ cat) {
    int t = blockIdx.x;
    int d = threadIdx.x;
    __shared__ float xr[Fq];
    if (d < Fq) xr[d] = x[t * Fq + d];
    __syncthreads();
    float s = bf[d];
#pragma unroll
    for (int i = 0; i < Fq; i++) s += xr[i] * Wf[i * FDq + d];
    cat[t * 2 * FDq + d] = roundtf(s);
    cat[t * 2 * FDq + FDq + d] = roundtf(emb[ts[t] * FDq + d]);
}

// -------------------- output projection (warp-per-row, smem W) ------------
// C[2048,32] = A[2048,512] @ W[512,32] + bias. 8 warps/block; W staged to
// smem transposed (pad 513) for conflict-free LDS.
#define OUT_SMEM (32 * 513 * 4)
__global__ __launch_bounds__(256)
void out_gemm_kernel(const float* __restrict__ A, const float* __restrict__ W,
                     const float* __restrict__ bias, float* __restrict__ C) {
    extern __shared__ float Wt[];   // [32][513]
    int tid = threadIdx.x, w = tid >> 5, lane = tid & 31;
    for (int i = tid; i < Dq * Fq; i += 256) {
        int k = i >> 5, n = i & 31;
        Wt[n * 513 + k] = W[i];
    }
    __syncthreads();

    int row = blockIdx.x * 8 + w;
    float a[16];
#pragma unroll
    for (int j = 0; j < 16; j++)
        a[j] = A[(size_t)row * Dq + lane + 32 * j];
#pragma unroll
    for (int n = 0; n < 32; n++) {
        float p = 0.f;
        const float* wn = Wt + n * 513;
#pragma unroll
        for (int j = 0; j < 16; j++) p += a[j] * wn[lane + 32 * j];
        p = warp_sum(p);
        if (lane == 0) C[(size_t)row * Fq + n] = p + bias[n];
    }
}

// -------------------- fused gate + memory + LayerNorm (warp/token) --------
__global__ __launch_bounds__(256)
void gate_ln_kernel(const float* __restrict__ a, const float* __restrict__ gu,
                    float* __restrict__ mem,
                    const float* __restrict__ g, const float* __restrict__ bta,
                    float* __restrict__ hout, int first) {
    int w = threadIdx.x >> 5, lane = threadIdx.x & 31;
    int t = blockIdx.x * 8 + w;
    size_t base = (size_t)t * Dq;
    size_t gbase = (size_t)t * 2 * Dq;

    float y[16];
    float sum = 0.f;
#pragma unroll
    for (int j = 0; j < 4; j++) {
        int d = (lane + 32 * j) * 4;
        float4 gg = *(const float4*)&gu[gbase + d];
        float4 uu = *(const float4*)&gu[gbase + Dq + d];
        float4 av = *(const float4*)&a[base + d];
        float4 mm = first ? make_float4(0.f, 0.f, 0.f, 0.f)
                          : *(const float4*)&mem[base + d];
        float g0 = 1.f / (1.f + __expf(-gg.x));
        float g1 = 1.f / (1.f + __expf(-gg.y));
        float g2 = 1.f / (1.f + __expf(-gg.z));
        float g3 = 1.f / (1.f + __expf(-gg.w));
        float nm0 = g0 * uu.x + (1.f - g0) * mm.x;
        float nm1 = g1 * uu.y + (1.f - g1) * mm.y;
        float nm2 = g2 * uu.z + (1.f - g2) * mm.z;
        float nm3 = g3 * uu.w + (1.f - g3) * mm.w;
        *(float4*)&mem[base + d] = make_float4(roundtf(nm0), roundtf(nm1),
                                               roundtf(nm2), roundtf(nm3));
        y[j * 4 + 0] = av.x + nm0;
        y[j * 4 + 1] = av.y + nm1;
        y[j * 4 + 2] = av.z + nm2;
        y[j * 4 + 3] = av.w + nm3;
        sum += y[j * 4] + y[j * 4 + 1] + y[j * 4 + 2] + y[j * 4 + 3];
    }
    float mean = warp_sum(sum) * (1.f / Dq);
    float vs = 0.f;
#pragma unroll
    for (int i = 0; i < 16; i++) {
        float dv = y[i] - mean;
        vs += dv * dv;
    }
    float rs = rsqrtf(warp_sum(vs) * (1.f / Dq) + 1e-5f);
#pragma unroll
    for (int j = 0; j < 4; j++) {
        int d = (lane + 32 * j) * 4;
        float4 gv = *(const float4*)&g[d];
        float4 bv = *(const float4*)&bta[d];
        float4 ov;
        ov.x = roundtf((y[j * 4 + 0] - mean) * rs * gv.x + bv.x);
        ov.y = roundtf((y[j * 4 + 1] - mean) * rs * gv.y + bv.y);
        ov.z = roundtf((y[j * 4 + 2] - mean) * rs * gv.z + bv.z);
        ov.w = roundtf((y[j * 4 + 3] - mean) * rs * gv.w + bv.w);
        *(float4*)&hout[base + d] = ov;
    }
}

// -------------------- double LayerNorm (warp/token) -----------------------
__global__ __launch_bounds__(256)
void double_ln_kernel(const float* __restrict__ c, const float* __restrict__ cg,
                      const float* __restrict__ cb, const float* __restrict__ og,
                      const float* __restrict__ ob, float* __restrict__ out) {
    int w = threadIdx.x >> 5, lane = threadIdx.x & 31;
    int t = blockIdx.x * 8 + w;
    size_t base = (size_t)t * Dq;

    float y[16];
    float sum = 0.f;
#pragma unroll
    for (int j = 0; j < 4; j++) {
        int d = (lane + 32 * j) * 4;
        float4 v = *(const float4*)&c[base + d];
        y[j * 4 + 0] = v.x; y[j * 4 + 1] = v.y;
        y[j * 4 + 2] = v.z; y[j * 4 + 3] = v.w;
        sum += v.x + v.y + v.z + v.w;
    }
    float mean = warp_sum(sum) * (1.f / Dq);
    float vs = 0.f;
#pragma unroll
    for (int i = 0; i < 16; i++) {
        float dv = y[i] - mean;
        vs += dv * dv;
    }
    float rs = rsqrtf(warp_sum(vs) * (1.f / Dq) + 1e-5f);

    float z[16];
    float sum2 = 0.f;
#pragma unroll
    for (int j = 0; j < 4; j++) {
        int d = (lane + 32 * j) * 4;
        float4 gv = *(const float4*)&cg[d];
        float4 bv = *(const float4*)&cb[d];
        z[j * 4 + 0] = (y[j * 4 + 0] - mean) * rs * gv.x + bv.x;
        z[j * 4 + 1] = (y[j * 4 + 1] - mean) * rs * gv.y + bv.y;
        z[j * 4 + 2] = (y[j * 4 + 2] - mean) * rs * gv.z + bv.z;
        z[j * 4 + 3] = (y[j * 4 + 3] - mean) * rs * gv.w + bv.w;
        sum2 += z[j * 4] + z[j * 4 + 1] + z[j * 4 + 2] + z[j * 4 + 3];
    }
    float mean2 = warp_sum(sum2) * (1.f / Dq);
    float vs2 = 0.f;
#pragma unroll
    for (int i = 0; i < 16; i++) {
        float dv = z[i] - mean2;
        vs2 += dv * dv;
    }
    float rs2 = rsqrtf(warp_sum(vs2) * (1.f / Dq) + 1e-5f);
#pragma unroll
    for (int j = 0; j < 4; j++) {
        int d = (lane + 32 * j) * 4;
        float4 gv = *(const float4*)&og[d];
        float4 bv = *(const float4*)&ob[d];
        float4 ov;
        ov.x = roundtf((z[j * 4 + 0] - mean2) * rs2 * gv.x + bv.x);
        ov.y = roundtf((z[j * 4 + 1] - mean2) * rs2 * gv.y + bv.y);
        ov.z = roundtf((z[j * 4 + 2] - mean2) * rs2 * gv.z + bv.z);
        ov.w = roundtf((z[j * 4 + 3] - mean2) * rs2 * gv.w + bv.w);
        *(float4*)&out[base + d] = ov;
    }
}

// ==========================================================================
extern "C" void kernel_launch(void* const* d_in, const int* in_sizes, int n_in,
                              void* d_out, int out_size) {
    const float* x       = (const float*)d_in[0];
    const int*   ts      = (const int*)d_in[1];
    const float* W_feat  = (const float*)d_in[2];
    const float* b_feat  = (const float*)d_in[3];
    const float* emb     = (const float*)d_in[4];
    const float* W_emb   = (const float*)d_in[5];
    const float* b_emb   = (const float*)d_in[6];
    const float* Wq      = (const float*)d_in[7];
    const float* bq      = (const float*)d_in[8];
    const float* Wk      = (const float*)d_in[9];
    const float* bk      = (const float*)d_in[10];
    const float* Wv      = (const float*)d_in[11];
    const float* bv      = (const float*)d_in[12];
    const float* Wo      = (const float*)d_in[13];
    const float* bo      = (const float*)d_in[14];
    const float* Wg      = (const float*)d_in[15];
    const float* bg      = (const float*)d_in[16];
    const float* Wu      = (const float*)d_in[17];
    const float* bu      = (const float*)d_in[18];
    const float* ln_g    = (const float*)d_in[19];
    const float* ln_b    = (const float*)d_in[20];
    const float* conv_w  = (const float*)d_in[21];
    const float* conv_b  = (const float*)d_in[22];
    const float* cn_g    = (const float*)d_in[23];
    const float* cn_b    = (const float*)d_in[24];
    const float* on_g    = (const float*)d_in[25];
    const float* on_b    = (const float*)d_in[26];
    const float* W_out   = (const float*)d_in[27];
    const float* b_out   = (const float*)d_in[28];
    float* out = (float*)d_out;

    float *cat, *h, *mem, *qkv, *ap, *a, *gu, *c, *c2, *wc;
    float *wqkvT, *bqkv, *wguT, *bgu, *woT, *wembT;
    cudaGetSymbolAddress((void**)&cat, g_cat);
    cudaGetSymbolAddress((void**)&h,   g_h);
    cudaGetSymbolAddress((void**)&mem, g_mem);
    cudaGetSymbolAddress((void**)&qkv, g_qkv);
    cudaGetSymbolAddress((void**)&ap,  g_ap);
    cudaGetSymbolAddress((void**)&a,   g_a);
    cudaGetSymbolAddress((void**)&gu,  g_gu);
    cudaGetSymbolAddress((void**)&c,   g_c);
    cudaGetSymbolAddress((void**)&c2,  g_c2);
    cudaGetSymbolAddress((void**)&wc,  g_wc);
    cudaGetSymbolAddress((void**)&wqkvT, g_wqkvT);
    cudaGetSymbolAddress((void**)&bqkv,  g_bqkv);
    cudaGetSymbolAddress((void**)&wguT,  g_wguT);
    cudaGetSymbolAddress((void**)&bgu,   g_bgu);
    cudaGetSymbolAddress((void**)&woT,   g_woT);
    cudaGetSymbolAddress((void**)&wembT, g_wembT);

    static int smem_set = 0;
    if (!smem_set) {
        cudaFuncSetAttribute(gemm_tc_kernel,
                             cudaFuncAttributeMaxDynamicSharedMemorySize, SMEM_TC);
        cudaFuncSetAttribute(attn_tc_kernel,
                             cudaFuncAttributeMaxDynamicSharedMemorySize, SMEM_ATT);
        cudaFuncSetAttribute(out_gemm_kernel,
                             cudaFuncAttributeMaxDynamicSharedMemorySize, OUT_SMEM);
        smem_set = 1;
    }

    // 0. merged weight pre-pack (one launch covers all segments)
    pack_all_kernel<<<(Lq * 2 * Dq * Dq + 255) / 256, 256>>>(
        Wq, Wk, Wv, bq, bk, bv, Wg, Wu, bg, bu, Wo, W_emb, conv_w,
        wqkvT, bqkv, wguT, bgu, woT, wembT, wc);

    // 1. embedding
    build_cat_kernel<<<NTq, 128>>>(x, ts, W_feat, b_feat, emb, cat);
    launch_tc(cat, cat, 8, 2 * FDq, 2 * FDq, wembT, 2 * FDq, b_emb, h, Dq,
              NTq, Dq, 2 * FDq, 1);

    // 2. layers (mem implicitly zero in layer 0)
    for (int l = 0; l < Lq; l++) {
        launch_tc(h, h, 16, Dq, Dq, wqkvT + (size_t)l * 3 * Dq * Dq, Dq,
                  bqkv + l * 3 * Dq, qkv, 3 * Dq, NTq, 3 * Dq, Dq, 1);

        attn_tc_kernel<<<dim3(NBq, Hq, Bq), 256, SMEM_ATT>>>(qkv, ap);

        launch_tc(ap, ap, 16, Dq, Dq, woT + (size_t)l * Dq * Dq, Dq,
                  bo + l * Dq, a, Dq, NTq, Dq, Dq, 1);

        if (l == 0)
            launch_tc(a, a, 16, Dq, Dq, wguT + (size_t)l * 2 * Dq * 2 * Dq, 2 * Dq,
                      bgu + l * 2 * Dq, gu, 2 * Dq, NTq, 2 * Dq, Dq, 0);
        else
            launch_tc(a, mem, 16, Dq, Dq, wguT + (size_t)l * 2 * Dq * 2 * Dq, 2 * Dq,
                      bgu + l * 2 * Dq, gu, 2 * Dq, NTq, 2 * Dq, 2 * Dq, 0);

        gate_ln_kernel<<<NTq / 8, 256>>>(a, gu, mem, ln_g + l * Dq,
                                         ln_b + l * Dq, h, l == 0);
    }

    // 3. temporal compression (conv as GEMM; weight transposed [512][2048])
    launch_tc(h, h, 64, CFq * Dq, CFq * Dq, wc, CFq * Dq, conv_b, c, Dq,
              Bq * NCq, Dq, CFq * Dq, 0);

    // 4. double LayerNorm
    double_ln_kernel<<<Bq * NCq / 8, 256>>>(c, cn_g, cn_b, on_g, on_b, c2);

    // 5. output projection (warp-per-row)
    out_gemm_kernel<<<Bq * NCq / 8, 256, OUT_SMEM>>>(c2, W_out, b_out, out);
}

// round 15
// speedup vs baseline: 1.1496x; 1.0490x over previous
#include <cuda_runtime.h>
#include <cuda_bf16.h>
#include <cstdint>

// Problem constants
#define Bq 4
#define Sq 8192
#define Fq 32
#define Dq 512
#define Hq 8
#define Lq 4
#define FDq 128
#define WINq 256
#define CFq 4
#define HDq 64
#define NTq (Bq * Sq)          // 32768 tokens
#define NBq (Sq / WINq)        // 32 windows
#define NCq (Sq / CFq)         // 2048 compressed steps per batch

// -------------------- scratch (device globals; no allocation allowed) -----
__device__ float g_cat[NTq * 2 * FDq];
__device__ float g_h  [NTq * Dq];
__device__ float g_mem[NTq * Dq];
__device__ float g_qkv[NTq * 3 * Dq];
__device__ float g_ap [NTq * Dq];
__device__ float g_a  [NTq * Dq];
__device__ float g_gu [NTq * 2 * Dq];
__device__ float g_c  [Bq * NCq * Dq];
__device__ float g_c2 [Bq * NCq * Dq];
__device__ float g_wc [CFq * Dq * Dq];         // conv weight^T [512][2048]
__device__ float g_wqkvT[Lq * 3 * Dq * Dq];    // per-layer [1536][512]
__device__ float g_bqkv [Lq * 3 * Dq];
__device__ float g_wguT [Lq * 2 * Dq * 2 * Dq];// per-layer [1024][1024]
__device__ float g_bgu  [Lq * 2 * Dq];
__device__ float g_woT  [Lq * Dq * Dq];        // per-layer [512][512]
__device__ float g_wembT[2 * FDq * Dq];        // [512][256]

// ==================== helpers =============================================
__device__ __forceinline__ uint32_t smem_u32(const void* p) {
    uint32_t a;
    asm("{ .reg .u64 t; cvta.to.shared.u64 t, %1; cvt.u32.u64 %0, t; }"
        : "=r"(a) : "l"(p));
    return a;
}
__device__ __forceinline__ uint32_t f2tf(float f) {
    uint32_t u;
    asm("cvt.rna.tf32.f32 %0, %1;" : "=r"(u) : "f"(f));
    return u;
}
__device__ __forceinline__ float roundtf(float f) {
    return __uint_as_float(f2tf(f));
}
__device__ __forceinline__ void mma_tf32(float* d, const uint32_t* a,
                                         const uint32_t* b) {
    asm volatile(
        "mma.sync.aligned.m16n8k8.row.col.f32.tf32.tf32.f32 "
        "{%0,%1,%2,%3}, {%4,%5,%6,%7}, {%8,%9}, {%0,%1,%2,%3};"
        : "+f"(d[0]), "+f"(d[1]), "+f"(d[2]), "+f"(d[3])
        : "r"(a[0]), "r"(a[1]), "r"(a[2]), "r"(a[3]), "r"(b[0]), "r"(b[1]));
}
__device__ __forceinline__ void cpa16(uint32_t dst, const float* src) {
    asm volatile("cp.async.cg.shared.global [%0], [%1], 16;"
                 :: "r"(dst), "l"(src));
}
__device__ __forceinline__ void ldsm4(uint32_t* r, uint32_t addr) {
    asm volatile("ldmatrix.sync.aligned.m8n8.x4.shared.b16 {%0,%1,%2,%3}, [%4];"
                 : "=r"(r[0]), "=r"(r[1]), "=r"(r[2]), "=r"(r[3]) : "r"(addr));
}
__device__ __forceinline__ float warp_sum(float v) {
#pragma unroll
    for (int o = 16; o > 0; o >>= 1)
        v += __shfl_xor_sync(0xffffffffu, v, o);
    return v;
}
#define CPA_COMMIT() asm volatile("cp.async.commit_group;" ::: "memory")
#define CPA_WAIT1()  asm volatile("cp.async.wait_group 1;" ::: "memory")

// ==================== tf32 tensor-core GEMM ===============================
// R10/R14 config (best passing) + ISSUE deferred past kk=0 compute so mma
// starts immediately after the barrier (tensor pipe fills sooner).
#define ASTR 36
#define ST_W (128 * ASTR)
#define SMEM_TC (6 * ST_W * 4)     // 110592 bytes

__global__ __launch_bounds__(256, 2)
void gemm_tc_kernel(const float* __restrict__ A0, const float* __restrict__ A1,
                    int scChunks, int lda0, int lda1,
                    const float* __restrict__ BmT, int ldbt,
                    const float* __restrict__ bias,
                    float* __restrict__ C, int ldc, int nChunks, int roundOut) {
    extern __shared__ float smem[];
    uint32_t sbase = smem_u32(smem);

    int tid = threadIdx.x;
    int lane = tid & 31, wid = tid >> 5;
    int warpM = wid & 3, warpN = wid >> 2;
    int g = lane >> 2, c4 = lane & 3;
    int rowbase = blockIdx.y * 128;
    int colbase = blockIdx.x * 128;

    int rowA = warpM * 32 + (lane & 15);
    uint32_t aOff = (uint32_t)(rowA * ASTR + (lane >> 4) * 4) * 4;
    int rowB = warpN * 64 + ((lane >> 4) << 3) + (lane & 7);
    uint32_t bOff = (uint32_t)(rowB * ASTR + ((lane >> 3) & 1) * 4) * 4;

    float acc[2][8][4];
#pragma unroll
    for (int mi = 0; mi < 2; mi++)
#pragma unroll
        for (int nj = 0; nj < 8; nj++)
#pragma unroll
            for (int r = 0; r < 4; r++) acc[mi][nj][r] = 0.f;

#define ISSUE(ch) do { \
        int _st = (ch) % 3; \
        uint32_t _sa = sbase + (uint32_t)(_st * ST_W) * 4; \
        uint32_t _sb = sbase + (uint32_t)((3 + _st) * ST_W) * 4; \
        const float* Ap; int kc, lda; \
        if ((ch) < scChunks) { Ap = A0; kc = (ch); lda = lda0; } \
        else { Ap = A1; kc = (ch) - scChunks; lda = lda1; } \
        _Pragma("unroll") \
        for (int i = 0; i < 4; i++) { \
            int id = tid + i * 256; int r = id >> 3, sg = id & 7; \
            cpa16(_sa + (uint32_t)(r * ASTR + sg * 4) * 4, \
                  Ap + (size_t)(rowbase + r) * lda + kc * 32 + sg * 4); \
            cpa16(_sb + (uint32_t)(r * ASTR + sg * 4) * 4, \
                  BmT + (size_t)(colbase + r) * ldbt + (ch) * 32 + sg * 4); \
        } \
    } while (0)

#define COMPUTE_KK(kk) do { \
        uint32_t af[2][4], bf[4][4]; \
        ldsm4(af[0], aBase + (kk) * 32); \
        ldsm4(af[1], aBase + 16 * ASTR * 4 + (kk) * 32); \
        _Pragma("unroll") \
        for (int pr = 0; pr < 4; pr++) \
            ldsm4(bf[pr], bBase + pr * 16 * ASTR * 4 + (kk) * 32); \
        _Pragma("unroll") \
        for (int mi = 0; mi < 2; mi++) \
            _Pragma("unroll") \
            for (int pr = 0; pr < 4; pr++) { \
                mma_tf32(acc[mi][2 * pr],     af[mi], &bf[pr][0]); \
                mma_tf32(acc[mi][2 * pr + 1], af[mi], &bf[pr][2]); \
            } \
    } while (0)

    ISSUE(0); CPA_COMMIT();
    ISSUE(1); CPA_COMMIT();

    for (int ch = 0; ch < nChunks; ch++) {
        int st = ch % 3;
        CPA_WAIT1();
        __syncthreads();           // frees stage (ch-1)%3 for ISSUE below

        uint32_t aBase = sbase + (uint32_t)(st * ST_W) * 4 + aOff;
        uint32_t bBase = sbase + (uint32_t)((3 + st) * ST_W) * 4 + bOff;

        COMPUTE_KK(0);             // start tensor pipe immediately
        if (ch + 2 < nChunks) ISSUE(ch + 2);   // writes stage (ch-1)%3 — safe
        CPA_COMMIT();
        COMPUTE_KK(1);
        COMPUTE_KK(2);
        COMPUTE_KK(3);
    }
#undef COMPUTE_KK
#undef ISSUE

#pragma unroll
    for (int mi = 0; mi < 2; mi++) {
        int r0 = rowbase + warpM * 32 + mi * 16 + g;
#pragma unroll
        for (int nj = 0; nj < 8; nj++) {
            int col = colbase + warpN * 64 + nj * 8 + 2 * c4;
            float b0 = bias[col], b1 = bias[col + 1];
            float o0 = acc[mi][nj][0] + b0, o1 = acc[mi][nj][1] + b1;
            float o2 = acc[mi][nj][2] + b0, o3 = acc[mi][nj][3] + b1;
            if (roundOut) {
                o0 = roundtf(o0); o1 = roundtf(o1);
                o2 = roundtf(o2); o3 = roundtf(o3);
            }
            *(float2*)(C + (size_t)r0 * ldc + col) = make_float2(o0, o1);
            *(float2*)(C + (size_t)(r0 + 8) * ldc + col) = make_float2(o2, o3);
        }
    }
}

static inline void launch_tc(const float* A0, const float* A1, int sc,
                             int lda0, int lda1, const float* BmT, int ldbt,
                             const float* bias, float* C, int ldc,
                             int M, int N, int K, int roundOut) {
    dim3 grid(N / 128, M / 128);
    gemm_tc_kernel<<<grid, 256, SMEM_TC>>>(A0, A1, sc, lda0, lda1, BmT, ldbt,
                                           bias, C, ldc, K / 32, roundOut);
}

// ==================== tensor-core windowed attention ======================
// EXACT R10/R14 version (256 threads, 3 K/V stages, single barrier/chunk).
#define KSTR 68
#define VSTR 72
#define PSTR 36
#define SMA_K(s) ((s) * 32 * KSTR)
#define SMA_VB   (3 * 32 * KSTR)
#define SMA_V(s) (SMA_VB + (s) * 32 * VSTR)
#define SMA_P    (3 * 32 * KSTR + 3 * 32 * VSTR)
#define SMEM_ATT ((SMA_P + 256 * PSTR) * 4)

__global__ __launch_bounds__(256)
void attn_tc_kernel(const float* __restrict__ qkv, float* __restrict__ out) {
    extern __shared__ float sm[];
    int blk = blockIdx.x, head = blockIdx.y, b = blockIdx.z;
    int tid = threadIdx.x, lane = tid & 31, w = tid >> 5;
    int g = lane >> 2, c4 = lane & 3;
    const int LD = 3 * Dq;
    const int qbase = b * Sq + blk * WINq;
    uint32_t sbase = smem_u32(sm);

    {
        const float4* src = (const float4*)(qkv + (size_t)(qbase + tid) * LD + head * HDq);
        float* dst = sm + tid * KSTR;
#pragma unroll
        for (int j = 0; j < 16; j++) *(float4*)(dst + j * 4) = src[j];
    }
    __syncthreads();
    uint32_t qf[2][8][4];
#pragma unroll
    for (int mi = 0; mi < 2; mi++) {
        int r = w * 32 + mi * 16 + g;
#pragma unroll
        for (int kt = 0; kt < 8; kt++) {
            qf[mi][kt][0] = __float_as_uint(sm[r * KSTR + kt * 8 + c4]);
            qf[mi][kt][1] = __float_as_uint(sm[(r + 8) * KSTR + kt * 8 + c4]);
            qf[mi][kt][2] = __float_as_uint(sm[r * KSTR + kt * 8 + c4 + 4]);
            qf[mi][kt][3] = __float_as_uint(sm[(r + 8) * KSTR + kt * 8 + c4 + 4]);
        }
    }
    __syncthreads();

    float o[2][8][4];
#pragma unroll
    for (int mi = 0; mi < 2; mi++)
#pragma unroll
        for (int nt = 0; nt < 8; nt++)
#pragma unroll
            for (int j = 0; j < 4; j++) o[mi][nt][j] = 0.f;
    float m_run[2][2] = {{-1e30f, -1e30f}, {-1e30f, -1e30f}};
    float l_run[2][2] = {{0.f, 0.f}, {0.f, 0.f}};

    const int ktok0 = b * Sq + (blk - 1) * WINq;
    const int c0 = (blk == 0) ? 8 : 0;

#define AISSUE(ci) do { \
        int _st = (ci) % 3; \
        int r = tid >> 3, sg = tid & 7; \
        const float* kv = qkv + (size_t)(ktok0 + (ci) * 32 + r) * LD + head * HDq; \
        uint32_t kd = sbase + (uint32_t)(SMA_K(_st) + r * KSTR) * 4; \
        uint32_t vd = sbase + (uint32_t)(SMA_V(_st) + r * VSTR) * 4; \
        cpa16(kd + sg * 16,        kv + Dq + sg * 4); \
        cpa16(kd + (sg + 8) * 16,  kv + Dq + (sg + 8) * 4); \
        cpa16(vd + sg * 16,        kv + 2 * Dq + sg * 4); \
        cpa16(vd + (sg + 8) * 16,  kv + 2 * Dq + (sg + 8) * 4); \
    } while (0)

    AISSUE(c0);     CPA_COMMIT();
    AISSUE(c0 + 1); CPA_COMMIT();

    float* Pt = sm + SMA_P;
    for (int ci = c0; ci < 16; ci++) {
        CPA_WAIT1();
        __syncthreads();
        if (ci + 2 < 16) AISSUE(ci + 2);
        CPA_COMMIT();
        const float* Kt = sm + SMA_K(ci % 3);
        const float* Vt = sm + SMA_V(ci % 3);

#pragma unroll
        for (int mi = 0; mi < 2; mi++) {
            float s[4][4];
#pragma unroll
            for (int nt = 0; nt < 4; nt++)
#pragma unroll
                for (int j = 0; j < 4; j++) s[nt][j] = 0.f;
#pragma unroll
            for (int kt = 0; kt < 8; kt++) {
                uint32_t bb[4][2];
#pragma unroll
                for (int nt = 0; nt < 4; nt++) {
                    bb[nt][0] = __float_as_uint(Kt[(nt * 8 + g) * KSTR + kt * 8 + c4]);
                    bb[nt][1] = __float_as_uint(Kt[(nt * 8 + g) * KSTR + kt * 8 + c4 + 4]);
                }
#pragma unroll
                for (int nt = 0; nt < 4; nt++)
                    mma_tf32(s[nt], qf[mi][kt], bb[nt]);
            }
#pragma unroll
            for (int nt = 0; nt < 4; nt++)
#pragma unroll
                for (int j = 0; j < 4; j++) s[nt][j] *= 0.125f;

            float ml0 = s[0][0], ml1 = s[0][2];
#pragma unroll
            for (int nt = 0; nt < 4; nt++) {
                ml0 = fmaxf(ml0, fmaxf(s[nt][0], s[nt][1]));
                ml1 = fmaxf(ml1, fmaxf(s[nt][2], s[nt][3]));
            }
            ml0 = fmaxf(ml0, __shfl_xor_sync(0xffffffffu, ml0, 1));
            ml0 = fmaxf(ml0, __shfl_xor_sync(0xffffffffu, ml0, 2));
            ml1 = fmaxf(ml1, __shfl_xor_sync(0xffffffffu, ml1, 1));
            ml1 = fmaxf(ml1, __shfl_xor_sync(0xffffffffu, ml1, 2));

            float mn0 = fmaxf(m_run[mi][0], ml0);
            float mn1 = fmaxf(m_run[mi][1], ml1);
            float sc0 = __expf(m_run[mi][0] - mn0);
            float sc1 = __expf(m_run[mi][1] - mn1);
            m_run[mi][0] = mn0; m_run[mi][1] = mn1;

            float ps0 = 0.f, ps1 = 0.f;
#pragma unroll
            for (int nt = 0; nt < 4; nt++) {
                s[nt][0] = roundtf(__expf(s[nt][0] - mn0)); ps0 += s[nt][0];
                s[nt][1] = roundtf(__expf(s[nt][1] - mn0)); ps0 += s[nt][1];
                s[nt][2] = roundtf(__expf(s[nt][2] - mn1)); ps1 += s[nt][2];
                s[nt][3] = roundtf(__expf(s[nt][3] - mn1)); ps1 += s[nt][3];
            }
            ps0 += __shfl_xor_sync(0xffffffffu, ps0, 1);
            ps0 += __shfl_xor_sync(0xffffffffu, ps0, 2);
            ps1 += __shfl_xor_sync(0xffffffffu, ps1, 1);
            ps1 += __shfl_xor_sync(0xffffffffu, ps1, 2);
            l_run[mi][0] = l_run[mi][0] * sc0 + ps0;
            l_run[mi][1] = l_run[mi][1] * sc1 + ps1;

#pragma unroll
            for (int nt = 0; nt < 8; nt++) {
                o[mi][nt][0] *= sc0; o[mi][nt][1] *= sc0;
                o[mi][nt][2] *= sc1; o[mi][nt][3] *= sc1;
            }
            int r = w * 32 + mi * 16 + g;
#pragma unroll
            for (int nt = 0; nt < 4; nt++) {
                *(float2*)&Pt[r * PSTR + nt * 8 + 2 * c4] = make_float2(s[nt][0], s[nt][1]);
                *(float2*)&Pt[(r + 8) * PSTR + nt * 8 + 2 * c4] = make_float2(s[nt][2], s[nt][3]);
            }
        }
        __syncwarp();

#pragma unroll
        for (int kt = 0; kt < 4; kt++) {
            uint32_t pa[2][4];
#pragma unroll
            for (int mi = 0; mi < 2; mi++) {
                int r = w * 32 + mi * 16 + g;
                pa[mi][0] = __float_as_uint(Pt[r * PSTR + kt * 8 + c4]);
                pa[mi][1] = __float_as_uint(Pt[(r + 8) * PSTR + kt * 8 + c4]);
                pa[mi][2] = __float_as_uint(Pt[r * PSTR + kt * 8 + c4 + 4]);
                pa[mi][3] = __float_as_uint(Pt[(r + 8) * PSTR + kt * 8 + c4 + 4]);
            }
#pragma unroll
            for (int nt = 0; nt < 8; nt++) {
                uint32_t bv[2];
                bv[0] = __float_as_uint(Vt[(kt * 8 + c4) * VSTR + nt * 8 + g]);
                bv[1] = __float_as_uint(Vt[(kt * 8 + c4 + 4) * VSTR + nt * 8 + g]);
                mma_tf32(o[0][nt], pa[0], bv);
                mma_tf32(o[1][nt], pa[1], bv);
            }
        }
    }
#undef AISSUE

#pragma unroll
    for (int mi = 0; mi < 2; mi++) {
        float inv0 = 1.f / l_run[mi][0];
        float inv1 = 1.f / l_run[mi][1];
        int r = qbase + w * 32 + mi * 16 + g;
#pragma unroll
        for (int nt = 0; nt < 8; nt++) {
            int col = head * HDq + nt * 8 + 2 * c4;
            *(float2*)&out[(size_t)r * Dq + col] =
                make_float2(roundtf(o[mi][nt][0] * inv0), roundtf(o[mi][nt][1] * inv0));
            *(float2*)&out[(size_t)(r + 8) * Dq + col] =
                make_float2(roundtf(o[mi][nt][2] * inv1), roundtf(o[mi][nt][3] * inv1));
        }
    }
}

// -------------------- single merged weight pre-pack -----------------------
__global__ void pack_all_kernel(
    const float* __restrict__ Wq, const float* __restrict__ Wk,
    const float* __restrict__ Wv, const float* __restrict__ bq,
    const float* __restrict__ bk, const float* __restrict__ bv,
    const float* __restrict__ Wg, const float* __restrict__ Wu,
    const float* __restrict__ bg, const float* __restrict__ bu,
    const float* __restrict__ Wo, const float* __restrict__ W_emb,
    const float* __restrict__ conv_w,
    float* __restrict__ wqkvT, float* __restrict__ bqkv,
    float* __restrict__ wguT, float* __restrict__ bgu,
    float* __restrict__ woT, float* __restrict__ wembT,
    float* __restrict__ wcT) {
    int i = blockIdx.x * 256 + threadIdx.x;
    if (i < Lq * Dq * Dq) {
        int l = i >> 18;
        int r = i & (Dq * Dq - 1);
        int n = r >> 9, k = r & 511;
        size_t so = (size_t)l * Dq * Dq + (size_t)k * Dq + n;
        float* dst = wqkvT + (size_t)l * 3 * Dq * Dq;
        dst[(size_t)n * Dq + k] = roundtf(Wq[so]);
        dst[(size_t)(Dq + n) * Dq + k] = roundtf(Wk[so]);
        dst[(size_t)(2 * Dq + n) * Dq + k] = roundtf(Wv[so]);
    }
    if (i < Lq * Dq) {
        int l = i >> 9, n = i & 511;
        bqkv[l * 3 * Dq + n] = bq[l * Dq + n];
        bqkv[l * 3 * Dq + Dq + n] = bk[l * Dq + n];
        bqkv[l * 3 * Dq + 2 * Dq + n] = bv[l * Dq + n];
        bgu[l * 2 * Dq + n] = bg[l * Dq + n];
        bgu[l * 2 * Dq + Dq + n] = bu[l * Dq + n];
    }
    if (i < Lq * 2 * Dq * Dq) {
        int l = i >> 19;
        int r = i & (2 * Dq * Dq - 1);
        int n = r >> 10, k = r & 1023;
        size_t so = (size_t)l * 2 * Dq * Dq + (size_t)k * Dq + n;
        float* dst = wguT + (size_t)l * 2 * Dq * 2 * Dq;
        dst[(size_t)n * 2 * Dq + k] = roundtf(Wg[so]);
        dst[(size_t)(Dq + n) * 2 * Dq + k] = roundtf(Wu[so]);
    }
    if (i < Lq * Dq * Dq) {
        int l = i >> 18;
        int r = i & (Dq * Dq - 1);
        int n = r >> 9, k = r & 511;
        woT[(size_t)l * Dq * Dq + (size_t)n * Dq + k] =
            roundtf(Wo[(size_t)l * Dq * Dq + (size_t)k * Dq + n]);
    }
    if (i < 2 * FDq * Dq) {
        int n = i / (2 * FDq), k = i - n * (2 * FDq);
        wembT[i] = roundtf(W_emb[(size_t)k * Dq + n]);
    }
    if (i < CFq * Dq * Dq) {
        int o = i >> 11, r = i & 2047;
        int j = r >> 9, c = r & 511;
        wcT[i] = roundtf(conv_w[(size_t)o * (Dq * CFq) + c * CFq + j]);
    }
}

// -------------------- embedding: cat = [x@W_feat + b_feat, emb[ts]] -------
__global__ __launch_bounds__(128)
void build_cat_kernel(const float* __restrict__ x, const int* __restrict__ ts,
                      const float* __restrict__ Wf, const float* __restrict__ bf,
                      const float* __restrict__ emb, float* __restrict__ cat) {
    int t = blockIdx.x;
    int d = threadIdx.x;
    __shared__ float xr[Fq];
    if (d < Fq) xr[d] = x[t * Fq + d];
    __syncthreads();
    float s = bf[d];
#pragma unroll
    for (int i = 0; i < Fq; i++) s += xr[i] * Wf[i * FDq + d];
    cat[t * 2 * FDq + d] = roundtf(s);
    cat[t * 2 * FDq + FDq + d] = roundtf(emb[ts[t] * FDq + d]);
}

// -------------------- output projection (warp-per-row, smem W) ------------
#define OUT_SMEM (32 * 513 * 4)
__global__ __launch_bounds__(256)
void out_gemm_kernel(const float* __restrict__ A, const float* __restrict__ W,
                     const float* __restrict__ bias, float* __restrict__ C) {
    extern __shared__ float Wt[];   // [32][513]
    int tid = threadIdx.x, w = tid >> 5, lane = tid & 31;
    for (int i = tid; i < Dq * Fq; i += 256) {
        int k = i >> 5, n = i & 31;
        Wt[n * 513 + k] = W[i];
    }
    __syncthreads();

    int row = blockIdx.x * 8 + w;
    float a[16];
#pragma unroll
    for (int j = 0; j < 16; j++)
        a[j] = A[(size_t)row * Dq + lane + 32 * j];
#pragma unroll
    for (int n = 0; n < 32; n++) {
        float p = 0.f;
        const float* wn = Wt + n * 513;
#pragma unroll
        for (int j = 0; j < 16; j++) p += a[j] * wn[lane + 32 * j];
        p = warp_sum(p);
        if (lane == 0) C[(size_t)row * Fq + n] = p + bias[n];
    }
}

// -------------------- fused gate + memory + LayerNorm (warp/token) --------
__global__ __launch_bounds__(256)
void gate_ln_kernel(const float* __restrict__ a, const float* __restrict__ gu,
                    float* __restrict__ mem,
                    const float* __restrict__ g, const float* __restrict__ bta,
                    float* __restrict__ hout, int first) {
    int w = threadIdx.x >> 5, lane = threadIdx.x & 31;
    int t = blockIdx.x * 8 + w;
    size_t base = (size_t)t * Dq;
    size_t gbase = (size_t)t * 2 * Dq;

    float y[16];
    float sum = 0.f;
#pragma unroll
    for (int j = 0; j < 4; j++) {
        int d = (lane + 32 * j) * 4;
        float4 gg = *(const float4*)&gu[gbase + d];
        float4 uu = *(const float4*)&gu[gbase + Dq + d];
        float4 av = *(const float4*)&a[base + d];
        float4 mm = first ? make_float4(0.f, 0.f, 0.f, 0.f)
                          : *(const float4*)&mem[base + d];
        float g0 = 1.f / (1.f + __expf(-gg.x));
        float g1 = 1.f / (1.f + __expf(-gg.y));
        float g2 = 1.f / (1.f + __expf(-gg.z));
        float g3 = 1.f / (1.f + __expf(-gg.w));
        float nm0 = g0 * uu.x + (1.f - g0) * mm.x;
        float nm1 = g1 * uu.y + (1.f - g1) * mm.y;
        float nm2 = g2 * uu.z + (1.f - g2) * mm.z;
        float nm3 = g3 * uu.w + (1.f - g3) * mm.w;
        *(float4*)&mem[base + d] = make_float4(roundtf(nm0), roundtf(nm1),
                                               roundtf(nm2), roundtf(nm3));
        y[j * 4 + 0] = av.x + nm0;
        y[j * 4 + 1] = av.y + nm1;
        y[j * 4 + 2] = av.z + nm2;
        y[j * 4 + 3] = av.w + nm3;
        sum += y[j * 4] + y[j * 4 + 1] + y[j * 4 + 2] + y[j * 4 + 3];
    }
    float mean = warp_sum(sum) * (1.f / Dq);
    float vs = 0.f;
#pragma unroll
    for (int i = 0; i < 16; i++) {
        float dv = y[i] - mean;
        vs += dv * dv;
    }
    float rs = rsqrtf(warp_sum(vs) * (1.f / Dq) + 1e-5f);
#pragma unroll
    for (int j = 0; j < 4; j++) {
        int d = (lane + 32 * j) * 4;
        float4 gv = *(const float4*)&g[d];
        float4 bv = *(const float4*)&bta[d];
        float4 ov;
        ov.x = roundtf((y[j * 4 + 0] - mean) * rs * gv.x + bv.x);
        ov.y = roundtf((y[j * 4 + 1] - mean) * rs * gv.y + bv.y);
        ov.z = roundtf((y[j * 4 + 2] - mean) * rs * gv.z + bv.z);
        ov.w = roundtf((y[j * 4 + 3] - mean) * rs * gv.w + bv.w);
        *(float4*)&hout[base + d] = ov;
    }
}

// -------------------- double LayerNorm (warp/token) -----------------------
__global__ __launch_bounds__(256)
void double_ln_kernel(const float* __restrict__ c, const float* __restrict__ cg,
                      const float* __restrict__ cb, const float* __restrict__ og,
                      const float* __restrict__ ob, float* __restrict__ out) {
    int w = threadIdx.x >> 5, lane = threadIdx.x & 31;
    int t = blockIdx.x * 8 + w;
    size_t base = (size_t)t * Dq;

    float y[16];
    float sum = 0.f;
#pragma unroll
    for (int j = 0; j < 4; j++) {
        int d = (lane + 32 * j) * 4;
        float4 v = *(const float4*)&c[base + d];
        y[j * 4 + 0] = v.x; y[j * 4 + 1] = v.y;
        y[j * 4 + 2] = v.z; y[j * 4 + 3] = v.w;
        sum += v.x + v.y + v.z + v.w;
    }
    float mean = warp_sum(sum) * (1.f / Dq);
    float vs = 0.f;
#pragma unroll
    for (int i = 0; i < 16; i++) {
        float dv = y[i] - mean;
        vs += dv * dv;
    }
    float rs = rsqrtf(warp_sum(vs) * (1.f / Dq) + 1e-5f);

    float z[16];
    float sum2 = 0.f;
#pragma unroll
    for (int j = 0; j < 4; j++) {
        int d = (lane + 32 * j) * 4;
        float4 gv = *(const float4*)&cg[d];
        float4 bv = *(const float4*)&cb[d];
        z[j * 4 + 0] = (y[j * 4 + 0] - mean) * rs * gv.x + bv.x;
        z[j * 4 + 1] = (y[j * 4 + 1] - mean) * rs * gv.y + bv.y;
        z[j * 4 + 2] = (y[j * 4 + 2] - mean) * rs * gv.z + bv.z;
        z[j * 4 + 3] = (y[j * 4 + 3] - mean) * rs * gv.w + bv.w;
        sum2 += z[j * 4] + z[j * 4 + 1] + z[j * 4 + 2] + z[j * 4 + 3];
    }
    float mean2 = warp_sum(sum2) * (1.f / Dq);
    float vs2 = 0.f;
#pragma unroll
    for (int i = 0; i < 16; i++) {
        float dv = z[i] - mean2;
        vs2 += dv * dv;
    }
    float rs2 = rsqrtf(warp_sum(vs2) * (1.f / Dq) + 1e-5f);
#pragma unroll
    for (int j = 0; j < 4; j++) {
        int d = (lane + 32 * j) * 4;
        float4 gv = *(const float4*)&og[d];
        float4 bv = *(const float4*)&ob[d];
        float4 ov;
        ov.x = roundtf((z[j * 4 + 0] - mean2) * rs2 * gv.x + bv.x);
        ov.y = roundtf((z[j * 4 + 1] - mean2) * rs2 * gv.y + bv.y);
        ov.z = roundtf((z[j * 4 + 2] - mean2) * rs2 * gv.z + bv.z);
        ov.w = roundtf((z[j * 4 + 3] - mean2) * rs2 * gv.w + bv.w);
        *(float4*)&out[base + d] = ov;
    }
}

// ==========================================================================
extern "C" void kernel_launch(void* const* d_in, const int* in_sizes, int n_in,
                              void* d_out, int out_size) {
    const float* x       = (const float*)d_in[0];
    const int*   ts      = (const int*)d_in[1];
    const float* W_feat  = (const float*)d_in[2];
    const float* b_feat  = (const float*)d_in[3];
    const float* emb     = (const float*)d_in[4];
    const float* W_emb   = (const float*)d_in[5];
    const float* b_emb   = (const float*)d_in[6];
    const float* Wq      = (const float*)d_in[7];
    const float* bq      = (const float*)d_in[8];
    const float* Wk      = (const float*)d_in[9];
    const float* bk      = (const float*)d_in[10];
    const float* Wv      = (const float*)d_in[11];
    const float* bv      = (const float*)d_in[12];
    const float* Wo      = (const float*)d_in[13];
    const float* bo      = (const float*)d_in[14];
    const float* Wg      = (const float*)d_in[15];
    const float* bg      = (const float*)d_in[16];
    const float* Wu      = (const float*)d_in[17];
    const float* bu      = (const float*)d_in[18];
    const float* ln_g    = (const float*)d_in[19];
    const float* ln_b    = (const float*)d_in[20];
    const float* conv_w  = (const float*)d_in[21];
    const float* conv_b  = (const float*)d_in[22];
    const float* cn_g    = (const float*)d_in[23];
    const float* cn_b    = (const float*)d_in[24];
    const float* on_g    = (const float*)d_in[25];
    const float* on_b    = (const float*)d_in[26];
    const float* W_out   = (const float*)d_in[27];
    const float* b_out   = (const float*)d_in[28];
    float* out = (float*)d_out;

    float *cat, *h, *mem, *qkv, *ap, *a, *gu, *c, *c2, *wc;
    float *wqkvT, *bqkv, *wguT, *bgu, *woT, *wembT;
    cudaGetSymbolAddress((void**)&cat, g_cat);
    cudaGetSymbolAddress((void**)&h,   g_h);
    cudaGetSymbolAddress((void**)&mem, g_mem);
    cudaGetSymbolAddress((void**)&qkv, g_qkv);
    cudaGetSymbolAddress((void**)&ap,  g_ap);
    cudaGetSymbolAddress((void**)&a,   g_a);
    cudaGetSymbolAddress((void**)&gu,  g_gu);
    cudaGetSymbolAddress((void**)&c,   g_c);
    cudaGetSymbolAddress((void**)&c2,  g_c2);
    cudaGetSymbolAddress((void**)&wc,  g_wc);
    cudaGetSymbolAddress((void**)&wqkvT, g_wqkvT);
    cudaGetSymbolAddress((void**)&bqkv,  g_bqkv);
    cudaGetSymbolAddress((void**)&wguT,  g_wguT);
    cudaGetSymbolAddress((void**)&bgu,   g_bgu);
    cudaGetSymbolAddress((void**)&woT,   g_woT);
    cudaGetSymbolAddress((void**)&wembT, g_wembT);

    static int smem_set = 0;
    if (!smem_set) {
        cudaFuncSetAttribute(gemm_tc_kernel,
                             cudaFuncAttributeMaxDynamicSharedMemorySize, SMEM_TC);
        cudaFuncSetAttribute(attn_tc_kernel,
                             cudaFuncAttributeMaxDynamicSharedMemorySize, SMEM_ATT);
        cudaFuncSetAttribute(out_gemm_kernel,
                             cudaFuncAttributeMaxDynamicSharedMemorySize, OUT_SMEM);
        smem_set = 1;
    }

    // 0. merged weight pre-pack (one launch covers all segments)
    pack_all_kernel<<<(Lq * 2 * Dq * Dq + 255) / 256, 256>>>(
        Wq, Wk, Wv, bq, bk, bv, Wg, Wu, bg, bu, Wo, W_emb, conv_w,
        wqkvT, bqkv, wguT, bgu, woT, wembT, wc);

    // 1. embedding
    build_cat_kernel<<<NTq, 128>>>(x, ts, W_feat, b_feat, emb, cat);
    launch_tc(cat, cat, 8, 2 * FDq, 2 * FDq, wembT, 2 * FDq, b_emb, h, Dq,
              NTq, Dq, 2 * FDq, 1);

    // 2. layers (mem implicitly zero in layer 0)
    for (int l = 0; l < Lq; l++) {
        launch_tc(h, h, 16, Dq, Dq, wqkvT + (size_t)l * 3 * Dq * Dq, Dq,
                  bqkv + l * 3 * Dq, qkv, 3 * Dq, NTq, 3 * Dq, Dq, 1);

        attn_tc_kernel<<<dim3(NBq, Hq, Bq), 256, SMEM_ATT>>>(qkv, ap);

        launch_tc(ap, ap, 16, Dq, Dq, woT + (size_t)l * Dq * Dq, Dq,
                  bo + l * Dq, a, Dq, NTq, Dq, Dq, 1);

        if (l == 0)
            launch_tc(a, a, 16, Dq, Dq, wguT + (size_t)l * 2 * Dq * 2 * Dq, 2 * Dq,
                      bgu + l * 2 * Dq, gu, 2 * Dq, NTq, 2 * Dq, Dq, 0);
        else
            launch_tc(a, mem, 16, Dq, Dq, wguT + (size_t)l * 2 * Dq * 2 * Dq, 2 * Dq,
                      bgu + l * 2 * Dq, gu, 2 * Dq, NTq, 2 * Dq, 2 * Dq, 0);

        gate_ln_kernel<<<NTq / 8, 256>>>(a, gu, mem, ln_g + l * Dq,
                                         ln_b + l * Dq, h, l == 0);
    }

    // 3. temporal compression (conv as GEMM; weight transposed [512][2048])
    launch_tc(h, h, 64, CFq * Dq, CFq * Dq, wc, CFq * Dq, conv_b, c, Dq,
              Bq * NCq, Dq, CFq * Dq, 0);

    // 4. double LayerNorm
    double_ln_kernel<<<Bq * NCq / 8, 256>>>(c, cn_g, cn_b, on_g, on_b, c2);

    // 5. output projection (warp-per-row)
    out_gemm_kernel<<<Bq * NCq / 8, 256, OUT_SMEM>>>(c2, W_out, b_out, out);
}

// round 16
// speedup vs baseline: 1.1681x; 1.0161x over previous
#include <cuda_runtime.h>
#include <cuda_bf16.h>
#include <cstdint>

// Problem constants
#define Bq 4
#define Sq 8192
#define Fq 32
#define Dq 512
#define Hq 8
#define Lq 4
#define FDq 128
#define WINq 256
#define CFq 4
#define HDq 64
#define NTq (Bq * Sq)          // 32768 tokens
#define NBq (Sq / WINq)        // 32 windows
#define NCq (Sq / CFq)         // 2048 compressed steps per batch

// -------------------- scratch (device globals; no allocation allowed) -----
__device__ float g_cat[NTq * 2 * FDq];
__device__ float g_h  [NTq * Dq];
__device__ float g_mem[NTq * Dq];
__device__ float g_qkv[NTq * 3 * Dq];
__device__ float g_ap [NTq * Dq];
__device__ float g_a  [NTq * Dq];
__device__ float g_gu [NTq * 2 * Dq];
__device__ float g_c  [Bq * NCq * Dq];
__device__ float g_c2 [Bq * NCq * Dq];
__device__ float g_wc [CFq * Dq * Dq];         // conv weight^T [512][2048]
__device__ float g_wqkvT[Lq * 3 * Dq * Dq];    // per-layer [1536][512]
__device__ float g_bqkv [Lq * 3 * Dq];
__device__ float g_wguT [Lq * 2 * Dq * 2 * Dq];// per-layer [1024][1024]
__device__ float g_bgu  [Lq * 2 * Dq];
__device__ float g_woT  [Lq * Dq * Dq];        // per-layer [512][512]
__device__ float g_wembT[2 * FDq * Dq];        // [512][256]

// ==================== helpers =============================================
__device__ __forceinline__ uint32_t smem_u32(const void* p) {
    uint32_t a;
    asm("{ .reg .u64 t; cvta.to.shared.u64 t, %1; cvt.u32.u64 %0, t; }"
        : "=r"(a) : "l"(p));
    return a;
}
__device__ __forceinline__ uint32_t f2tf(float f) {
    uint32_t u;
    asm("cvt.rna.tf32.f32 %0, %1;" : "=r"(u) : "f"(f));
    return u;
}
__device__ __forceinline__ float roundtf(float f) {
    return __uint_as_float(f2tf(f));
}
__device__ __forceinline__ void mma_tf32(float* d, const uint32_t* a,
                                         const uint32_t* b) {
    asm volatile(
        "mma.sync.aligned.m16n8k8.row.col.f32.tf32.tf32.f32 "
        "{%0,%1,%2,%3}, {%4,%5,%6,%7}, {%8,%9}, {%0,%1,%2,%3};"
        : "+f"(d[0]), "+f"(d[1]), "+f"(d[2]), "+f"(d[3])
        : "r"(a[0]), "r"(a[1]), "r"(a[2]), "r"(a[3]), "r"(b[0]), "r"(b[1]));
}
__device__ __forceinline__ void cpa16(uint32_t dst, const float* src) {
    asm volatile("cp.async.cg.shared.global [%0], [%1], 16;"
                 :: "r"(dst), "l"(src));
}
__device__ __forceinline__ void ldsm4(uint32_t* r, uint32_t addr) {
    asm volatile("ldmatrix.sync.aligned.m8n8.x4.shared.b16 {%0,%1,%2,%3}, [%4];"
                 : "=r"(r[0]), "=r"(r[1]), "=r"(r[2]), "=r"(r[3]) : "r"(addr));
}
__device__ __forceinline__ float warp_sum(float v) {
#pragma unroll
    for (int o = 16; o > 0; o >>= 1)
        v += __shfl_xor_sync(0xffffffffu, v, o);
    return v;
}
#define CPA_COMMIT() asm volatile("cp.async.commit_group;" ::: "memory")
#define CPA_WAIT1()  asm volatile("cp.async.wait_group 1;" ::: "memory")

// ==================== tf32 tensor-core GEMM ===============================
// R15 config + ISSUE split into A-half (after kk=0) and B-half (after kk=1)
// to spread cp.async issue bursts across mma blocks. Numerics identical.
#define ASTR 36
#define ST_W (128 * ASTR)
#define SMEM_TC (6 * ST_W * 4)     // 110592 bytes

__global__ __launch_bounds__(256, 2)
void gemm_tc_kernel(const float* __restrict__ A0, const float* __restrict__ A1,
                    int scChunks, int lda0, int lda1,
                    const float* __restrict__ BmT, int ldbt,
                    const float* __restrict__ bias,
                    float* __restrict__ C, int ldc, int nChunks, int roundOut) {
    extern __shared__ float smem[];
    uint32_t sbase = smem_u32(smem);

    int tid = threadIdx.x;
    int lane = tid & 31, wid = tid >> 5;
    int warpM = wid & 3, warpN = wid >> 2;
    int g = lane >> 2, c4 = lane & 3;
    int rowbase = blockIdx.y * 128;
    int colbase = blockIdx.x * 128;

    int rowA = warpM * 32 + (lane & 15);
    uint32_t aOff = (uint32_t)(rowA * ASTR + (lane >> 4) * 4) * 4;
    int rowB = warpN * 64 + ((lane >> 4) << 3) + (lane & 7);
    uint32_t bOff = (uint32_t)(rowB * ASTR + ((lane >> 3) & 1) * 4) * 4;

    float acc[2][8][4];
#pragma unroll
    for (int mi = 0; mi < 2; mi++)
#pragma unroll
        for (int nj = 0; nj < 8; nj++)
#pragma unroll
            for (int r = 0; r < 4; r++) acc[mi][nj][r] = 0.f;

#define ISSUE_A(ch) do { \
        int _st = (ch) % 3; \
        uint32_t _sa = sbase + (uint32_t)(_st * ST_W) * 4; \
        const float* Ap; int kc, lda; \
        if ((ch) < scChunks) { Ap = A0; kc = (ch); lda = lda0; } \
        else { Ap = A1; kc = (ch) - scChunks; lda = lda1; } \
        _Pragma("unroll") \
        for (int i = 0; i < 4; i++) { \
            int id = tid + i * 256; int r = id >> 3, sg = id & 7; \
            cpa16(_sa + (uint32_t)(r * ASTR + sg * 4) * 4, \
                  Ap + (size_t)(rowbase + r) * lda + kc * 32 + sg * 4); \
        } \
    } while (0)
#define ISSUE_B(ch) do { \
        int _st = (ch) % 3; \
        uint32_t _sb = sbase + (uint32_t)((3 + _st) * ST_W) * 4; \
        _Pragma("unroll") \
        for (int i = 0; i < 4; i++) { \
            int id = tid + i * 256; int r = id >> 3, sg = id & 7; \
            cpa16(_sb + (uint32_t)(r * ASTR + sg * 4) * 4, \
                  BmT + (size_t)(colbase + r) * ldbt + (ch) * 32 + sg * 4); \
        } \
    } while (0)

#define COMPUTE_KK(kk) do { \
        uint32_t af[2][4], bf[4][4]; \
        ldsm4(af[0], aBase + (kk) * 32); \
        ldsm4(af[1], aBase + 16 * ASTR * 4 + (kk) * 32); \
        _Pragma("unroll") \
        for (int pr = 0; pr < 4; pr++) \
            ldsm4(bf[pr], bBase + pr * 16 * ASTR * 4 + (kk) * 32); \
        _Pragma("unroll") \
        for (int mi = 0; mi < 2; mi++) \
            _Pragma("unroll") \
            for (int pr = 0; pr < 4; pr++) { \
                mma_tf32(acc[mi][2 * pr],     af[mi], &bf[pr][0]); \
                mma_tf32(acc[mi][2 * pr + 1], af[mi], &bf[pr][2]); \
            } \
    } while (0)

    ISSUE_A(0); ISSUE_B(0); CPA_COMMIT();
    ISSUE_A(1); ISSUE_B(1); CPA_COMMIT();

    for (int ch = 0; ch < nChunks; ch++) {
        int st = ch % 3;
        CPA_WAIT1();
        __syncthreads();           // frees stage (ch-1)%3 for the issues below

        uint32_t aBase = sbase + (uint32_t)(st * ST_W) * 4 + aOff;
        uint32_t bBase = sbase + (uint32_t)((3 + st) * ST_W) * 4 + bOff;

        COMPUTE_KK(0);
        if (ch + 2 < nChunks) ISSUE_A(ch + 2);
        COMPUTE_KK(1);
        if (ch + 2 < nChunks) ISSUE_B(ch + 2);
        CPA_COMMIT();
        COMPUTE_KK(2);
        COMPUTE_KK(3);
    }
#undef COMPUTE_KK
#undef ISSUE_A
#undef ISSUE_B

#pragma unroll
    for (int mi = 0; mi < 2; mi++) {
        int r0 = rowbase + warpM * 32 + mi * 16 + g;
#pragma unroll
        for (int nj = 0; nj < 8; nj++) {
            int col = colbase + warpN * 64 + nj * 8 + 2 * c4;
            float b0 = bias[col], b1 = bias[col + 1];
            float o0 = acc[mi][nj][0] + b0, o1 = acc[mi][nj][1] + b1;
            float o2 = acc[mi][nj][2] + b0, o3 = acc[mi][nj][3] + b1;
            if (roundOut) {
                o0 = roundtf(o0); o1 = roundtf(o1);
                o2 = roundtf(o2); o3 = roundtf(o3);
            }
            *(float2*)(C + (size_t)r0 * ldc + col) = make_float2(o0, o1);
            *(float2*)(C + (size_t)(r0 + 8) * ldc + col) = make_float2(o2, o3);
        }
    }
}

static inline void launch_tc(const float* A0, const float* A1, int sc,
                             int lda0, int lda1, const float* BmT, int ldbt,
                             const float* bias, float* C, int ldc,
                             int M, int N, int K, int roundOut) {
    dim3 grid(N / 128, M / 128);
    gemm_tc_kernel<<<grid, 256, SMEM_TC>>>(A0, A1, sc, lda0, lda1, BmT, ldbt,
                                           bias, C, ldc, K / 32, roundOut);
}

// ==================== tensor-core windowed attention ======================
// R14 structure + AISSUE deferred past the mi=0 S/softmax block (stage
// (ci-1)%3 freed by top barrier; compute reads stage ci%3 — disjoint).
#define KSTR 68
#define VSTR 72
#define PSTR 36
#define SMA_K(s) ((s) * 32 * KSTR)
#define SMA_VB   (3 * 32 * KSTR)
#define SMA_V(s) (SMA_VB + (s) * 32 * VSTR)
#define SMA_P    (3 * 32 * KSTR + 3 * 32 * VSTR)
#define SMEM_ATT ((SMA_P + 256 * PSTR) * 4)

__global__ __launch_bounds__(256)
void attn_tc_kernel(const float* __restrict__ qkv, float* __restrict__ out) {
    extern __shared__ float sm[];
    int blk = blockIdx.x, head = blockIdx.y, b = blockIdx.z;
    int tid = threadIdx.x, lane = tid & 31, w = tid >> 5;
    int g = lane >> 2, c4 = lane & 3;
    const int LD = 3 * Dq;
    const int qbase = b * Sq + blk * WINq;
    uint32_t sbase = smem_u32(sm);

    {
        const float4* src = (const float4*)(qkv + (size_t)(qbase + tid) * LD + head * HDq);
        float* dst = sm + tid * KSTR;
#pragma unroll
        for (int j = 0; j < 16; j++) *(float4*)(dst + j * 4) = src[j];
    }
    __syncthreads();
    uint32_t qf[2][8][4];
#pragma unroll
    for (int mi = 0; mi < 2; mi++) {
        int r = w * 32 + mi * 16 + g;
#pragma unroll
        for (int kt = 0; kt < 8; kt++) {
            qf[mi][kt][0] = __float_as_uint(sm[r * KSTR + kt * 8 + c4]);
            qf[mi][kt][1] = __float_as_uint(sm[(r + 8) * KSTR + kt * 8 + c4]);
            qf[mi][kt][2] = __float_as_uint(sm[r * KSTR + kt * 8 + c4 + 4]);
            qf[mi][kt][3] = __float_as_uint(sm[(r + 8) * KSTR + kt * 8 + c4 + 4]);
        }
    }
    __syncthreads();

    float o[2][8][4];
#pragma unroll
    for (int mi = 0; mi < 2; mi++)
#pragma unroll
        for (int nt = 0; nt < 8; nt++)
#pragma unroll
            for (int j = 0; j < 4; j++) o[mi][nt][j] = 0.f;
    float m_run[2][2] = {{-1e30f, -1e30f}, {-1e30f, -1e30f}};
    float l_run[2][2] = {{0.f, 0.f}, {0.f, 0.f}};

    const int ktok0 = b * Sq + (blk - 1) * WINq;
    const int c0 = (blk == 0) ? 8 : 0;

#define AISSUE(ci) do { \
        int _st = (ci) % 3; \
        int r = tid >> 3, sg = tid & 7; \
        const float* kv = qkv + (size_t)(ktok0 + (ci) * 32 + r) * LD + head * HDq; \
        uint32_t kd = sbase + (uint32_t)(SMA_K(_st) + r * KSTR) * 4; \
        uint32_t vd = sbase + (uint32_t)(SMA_V(_st) + r * VSTR) * 4; \
        cpa16(kd + sg * 16,        kv + Dq + sg * 4); \
        cpa16(kd + (sg + 8) * 16,  kv + Dq + (sg + 8) * 4); \
        cpa16(vd + sg * 16,        kv + 2 * Dq + sg * 4); \
        cpa16(vd + (sg + 8) * 16,  kv + 2 * Dq + (sg + 8) * 4); \
    } while (0)

    AISSUE(c0);     CPA_COMMIT();
    AISSUE(c0 + 1); CPA_COMMIT();

    float* Pt = sm + SMA_P;
    for (int ci = c0; ci < 16; ci++) {
        CPA_WAIT1();
        __syncthreads();
        const float* Kt = sm + SMA_K(ci % 3);
        const float* Vt = sm + SMA_V(ci % 3);

#pragma unroll
        for (int mi = 0; mi < 2; mi++) {
            float s[4][4];
#pragma unroll
            for (int nt = 0; nt < 4; nt++)
#pragma unroll
                for (int j = 0; j < 4; j++) s[nt][j] = 0.f;
#pragma unroll
            for (int kt = 0; kt < 8; kt++) {
                uint32_t bb[4][2];
#pragma unroll
                for (int nt = 0; nt < 4; nt++) {
                    bb[nt][0] = __float_as_uint(Kt[(nt * 8 + g) * KSTR + kt * 8 + c4]);
                    bb[nt][1] = __float_as_uint(Kt[(nt * 8 + g) * KSTR + kt * 8 + c4 + 4]);
                }
#pragma unroll
                for (int nt = 0; nt < 4; nt++)
                    mma_tf32(s[nt], qf[mi][kt], bb[nt]);
            }
            // defer next-chunk loads until after the first S-mma block
            if (mi == 0) {
                if (ci + 2 < 16) AISSUE(ci + 2);
                CPA_COMMIT();
            }
#pragma unroll
            for (int nt = 0; nt < 4; nt++)
#pragma unroll
                for (int j = 0; j < 4; j++) s[nt][j] *= 0.125f;

            float ml0 = s[0][0], ml1 = s[0][2];
#pragma unroll
            for (int nt = 0; nt < 4; nt++) {
                ml0 = fmaxf(ml0, fmaxf(s[nt][0], s[nt][1]));
                ml1 = fmaxf(ml1, fmaxf(s[nt][2], s[nt][3]));
            }
            ml0 = fmaxf(ml0, __shfl_xor_sync(0xffffffffu, ml0, 1));
            ml0 = fmaxf(ml0, __shfl_xor_sync(0xffffffffu, ml0, 2));
            ml1 = fmaxf(ml1, __shfl_xor_sync(0xffffffffu, ml1, 1));
            ml1 = fmaxf(ml1, __shfl_xor_sync(0xffffffffu, ml1, 2));

            float mn0 = fmaxf(m_run[mi][0], ml0);
            float mn1 = fmaxf(m_run[mi][1], ml1);
            float sc0 = __expf(m_run[mi][0] - mn0);
            float sc1 = __expf(m_run[mi][1] - mn1);
            m_run[mi][0] = mn0; m_run[mi][1] = mn1;

            float ps0 = 0.f, ps1 = 0.f;
#pragma unroll
            for (int nt = 0; nt < 4; nt++) {
                s[nt][0] = roundtf(__expf(s[nt][0] - mn0)); ps0 += s[nt][0];
                s[nt][1] = roundtf(__expf(s[nt][1] - mn0)); ps0 += s[nt][1];
                s[nt][2] = roundtf(__expf(s[nt][2] - mn1)); ps1 += s[nt][2];
                s[nt][3] = roundtf(__expf(s[nt][3] - mn1)); ps1 += s[nt][3];
            }
            ps0 += __shfl_xor_sync(0xffffffffu, ps0, 1);
            ps0 += __shfl_xor_sync(0xffffffffu, ps0, 2);
            ps1 += __shfl_xor_sync(0xffffffffu, ps1, 1);
            ps1 += __shfl_xor_sync(0xffffffffu, ps1, 2);
            l_run[mi][0] = l_run[mi][0] * sc0 + ps0;
            l_run[mi][1] = l_run[mi][1] * sc1 + ps1;

#pragma unroll
            for (int nt = 0; nt < 8; nt++) {
                o[mi][nt][0] *= sc0; o[mi][nt][1] *= sc0;
                o[mi][nt][2] *= sc1; o[mi][nt][3] *= sc1;
            }
            int r = w * 32 + mi * 16 + g;
#pragma unroll
            for (int nt = 0; nt < 4; nt++) {
                *(float2*)&Pt[r * PSTR + nt * 8 + 2 * c4] = make_float2(s[nt][0], s[nt][1]);
                *(float2*)&Pt[(r + 8) * PSTR + nt * 8 + 2 * c4] = make_float2(s[nt][2], s[nt][3]);
            }
        }
        __syncwarp();

#pragma unroll
        for (int kt = 0; kt < 4; kt++) {
            uint32_t pa[2][4];
#pragma unroll
            for (int mi = 0; mi < 2; mi++) {
                int r = w * 32 + mi * 16 + g;
                pa[mi][0] = __float_as_uint(Pt[r * PSTR + kt * 8 + c4]);
                pa[mi][1] = __float_as_uint(Pt[(r + 8) * PSTR + kt * 8 + c4]);
                pa[mi][2] = __float_as_uint(Pt[r * PSTR + kt * 8 + c4 + 4]);
                pa[mi][3] = __float_as_uint(Pt[(r + 8) * PSTR + kt * 8 + c4 + 4]);
            }
#pragma unroll
            for (int nt = 0; nt < 8; nt++) {
                uint32_t bv[2];
                bv[0] = __float_as_uint(Vt[(kt * 8 + c4) * VSTR + nt * 8 + g]);
                bv[1] = __float_as_uint(Vt[(kt * 8 + c4 + 4) * VSTR + nt * 8 + g]);
                mma_tf32(o[0][nt], pa[0], bv);
                mma_tf32(o[1][nt], pa[1], bv);
            }
        }
    }
#undef AISSUE

#pragma unroll
    for (int mi = 0; mi < 2; mi++) {
        float inv0 = 1.f / l_run[mi][0];
        float inv1 = 1.f / l_run[mi][1];
        int r = qbase + w * 32 + mi * 16 + g;
#pragma unroll
        for (int nt = 0; nt < 8; nt++) {
            int col = head * HDq + nt * 8 + 2 * c4;
            *(float2*)&out[(size_t)r * Dq + col] =
                make_float2(roundtf(o[mi][nt][0] * inv0), roundtf(o[mi][nt][1] * inv0));
            *(float2*)&out[(size_t)(r + 8) * Dq + col] =
                make_float2(roundtf(o[mi][nt][2] * inv1), roundtf(o[mi][nt][3] * inv1));
        }
    }
}

// -------------------- single merged weight pre-pack -----------------------
__global__ void pack_all_kernel(
    const float* __restrict__ Wq, const float* __restrict__ Wk,
    const float* __restrict__ Wv, const float* __restrict__ bq,
    const float* __restrict__ bk, const float* __restrict__ bv,
    const float* __restrict__ Wg, const float* __restrict__ Wu,
    const float* __restrict__ bg, const float* __restrict__ bu,
    const float* __restrict__ Wo, const float* __restrict__ W_emb,
    const float* __restrict__ conv_w,
    float* __restrict__ wqkvT, float* __restrict__ bqkv,
    float* __restrict__ wguT, float* __restrict__ bgu,
    float* __restrict__ woT, float* __restrict__ wembT,
    float* __restrict__ wcT) {
    int i = blockIdx.x * 256 + threadIdx.x;
    if (i < Lq * Dq * Dq) {
        int l = i >> 18;
        int r = i & (Dq * Dq - 1);
        int n = r >> 9, k = r & 511;
        size_t so = (size_t)l * Dq * Dq + (size_t)k * Dq + n;
        float* dst = wqkvT + (size_t)l * 3 * Dq * Dq;
        dst[(size_t)n * Dq + k] = roundtf(Wq[so]);
        dst[(size_t)(Dq + n) * Dq + k] = roundtf(Wk[so]);
        dst[(size_t)(2 * Dq + n) * Dq + k] = roundtf(Wv[so]);
    }
    if (i < Lq * Dq) {
        int l = i >> 9, n = i & 511;
        bqkv[l * 3 * Dq + n] = bq[l * Dq + n];
        bqkv[l * 3 * Dq + Dq + n] = bk[l * Dq + n];
        bqkv[l * 3 * Dq + 2 * Dq + n] = bv[l * Dq + n];
        bgu[l * 2 * Dq + n] = bg[l * Dq + n];
        bgu[l * 2 * Dq + Dq + n] = bu[l * Dq + n];
    }
    if (i < Lq * 2 * Dq * Dq) {
        int l = i >> 19;
        int r = i & (2 * Dq * Dq - 1);
        int n = r >> 10, k = r & 1023;
        size_t so = (size_t)l * 2 * Dq * Dq + (size_t)k * Dq + n;
        float* dst = wguT + (size_t)l * 2 * Dq * 2 * Dq;
        dst[(size_t)n * 2 * Dq + k] = roundtf(Wg[so]);
        dst[(size_t)(Dq + n) * 2 * Dq + k] = roundtf(Wu[so]);
    }
    if (i < Lq * Dq * Dq) {
        int l = i >> 18;
        int r = i & (Dq * Dq - 1);
        int n = r >> 9, k = r & 511;
        woT[(size_t)l * Dq * Dq + (size_t)n * Dq + k] =
            roundtf(Wo[(size_t)l * Dq * Dq + (size_t)k * Dq + n]);
    }
    if (i < 2 * FDq * Dq) {
        int n = i / (2 * FDq), k = i - n * (2 * FDq);
        wembT[i] = roundtf(W_emb[(size_t)k * Dq + n]);
    }
    if (i < CFq * Dq * Dq) {
        int o = i >> 11, r = i & 2047;
        int j = r >> 9, c = r & 511;
        wcT[i] = roundtf(conv_w[(size_t)o * (Dq * CFq) + c * CFq + j]);
    }
}

// -------------------- embedding: cat = [x@W_feat + b_feat, emb[ts]] -------
__global__ __launch_bounds__(128)
void build_cat_kernel(const float* __restrict__ x, const int* __restrict__ ts,
                      const float* __restrict__ Wf, const float* __restrict__ bf,
                      const float* __restrict__ emb, float* __restrict__ cat) {
    int t = blockIdx.x;
    int d = threadIdx.x;
    __shared__ float xr[Fq];
    if (d < Fq) xr[d] = x[t * Fq + d];
    __syncthreads();
    float s = bf[d];
#pragma unroll
    for (int i = 0; i < Fq; i++) s += xr[i] * Wf[i * FDq + d];
    cat[t * 2 * FDq + d] = roundtf(s);
    cat[t * 2 * FDq + FDq + d] = roundtf(emb[ts[t] * FDq + d]);
}

// -------------------- output projection (warp-per-row, smem W) ------------
#define OUT_SMEM (32 * 513 * 4)
__global__ __launch_bounds__(256)
void out_gemm_kernel(const float* __restrict__ A, const float* __restrict__ W,
                     const float* __restrict__ bias, float* __restrict__ C) {
    extern __shared__ float Wt[];   // [32][513]
    int tid = threadIdx.x, w = tid >> 5, lane = tid & 31;
    for (int i = tid; i < Dq * Fq; i += 256) {
        int k = i >> 5, n = i & 31;
        Wt[n * 513 + k] = W[i];
    }
    __syncthreads();

    int row = blockIdx.x * 8 + w;
    float a[16];
#pragma unroll
    for (int j = 0; j < 16; j++)
        a[j] = A[(size_t)row * Dq + lane + 32 * j];
#pragma unroll
    for (int n = 0; n < 32; n++) {
        float p = 0.f;
        const float* wn = Wt + n * 513;
#pragma unroll
        for (int j = 0; j < 16; j++) p += a[j] * wn[lane + 32 * j];
        p = warp_sum(p);
        if (lane == 0) C[(size_t)row * Fq + n] = p + bias[n];
    }
}

// -------------------- fused gate + memory + LayerNorm (warp/token) --------
__global__ __launch_bounds__(256)
void gate_ln_kernel(const float* __restrict__ a, const float* __restrict__ gu,
                    float* __restrict__ mem,
                    const float* __restrict__ g, const float* __restrict__ bta,
                    float* __restrict__ hout, int first) {
    int w = threadIdx.x >> 5, lane = threadIdx.x & 31;
    int t = blockIdx.x * 8 + w;
    size_t base = (size_t)t * Dq;
    size_t gbase = (size_t)t * 2 * Dq;

    float y[16];
    float sum = 0.f;
#pragma unroll
    for (int j = 0; j < 4; j++) {
        int d = (lane + 32 * j) * 4;
        float4 gg = *(const float4*)&gu[gbase + d];
        float4 uu = *(const float4*)&gu[gbase + Dq + d];
        float4 av = *(const float4*)&a[base + d];
        float4 mm = first ? make_float4(0.f, 0.f, 0.f, 0.f)
                          : *(const float4*)&mem[base + d];
        float g0 = 1.f / (1.f + __expf(-gg.x));
        float g1 = 1.f / (1.f + __expf(-gg.y));
        float g2 = 1.f / (1.f + __expf(-gg.z));
        float g3 = 1.f / (1.f + __expf(-gg.w));
        float nm0 = g0 * uu.x + (1.f - g0) * mm.x;
        float nm1 = g1 * uu.y + (1.f - g1) * mm.y;
        float nm2 = g2 * uu.z + (1.f - g2) * mm.z;
        float nm3 = g3 * uu.w + (1.f - g3) * mm.w;
        *(float4*)&mem[base + d] = make_float4(roundtf(nm0), roundtf(nm1),
                                               roundtf(nm2), roundtf(nm3));
        y[j * 4 + 0] = av.x + nm0;
        y[j * 4 + 1] = av.y + nm1;
        y[j * 4 + 2] = av.z + nm2;
        y[j * 4 + 3] = av.w + nm3;
        sum += y[j * 4] + y[j * 4 + 1] + y[j * 4 + 2] + y[j * 4 + 3];
    }
    float mean = warp_sum(sum) * (1.f / Dq);
    float vs = 0.f;
#pragma unroll
    for (int i = 0; i < 16; i++) {
        float dv = y[i] - mean;
        vs += dv * dv;
    }
    float rs = rsqrtf(warp_sum(vs) * (1.f / Dq) + 1e-5f);
#pragma unroll
    for (int j = 0; j < 4; j++) {
        int d = (lane + 32 * j) * 4;
        float4 gv = *(const float4*)&g[d];
        float4 bv = *(const float4*)&bta[d];
        float4 ov;
        ov.x = roundtf((y[j * 4 + 0] - mean) * rs * gv.x + bv.x);
        ov.y = roundtf((y[j * 4 + 1] - mean) * rs * gv.y + bv.y);
        ov.z = roundtf((y[j * 4 + 2] - mean) * rs * gv.z + bv.z);
        ov.w = roundtf((y[j * 4 + 3] - mean) * rs * gv.w + bv.w);
        *(float4*)&hout[base + d] = ov;
    }
}

// -------------------- double LayerNorm (warp/token) -----------------------
__global__ __launch_bounds__(256)
void double_ln_kernel(const float* __restrict__ c, const float* __restrict__ cg,
                      const float* __restrict__ cb, const float* __restrict__ og,
                      const float* __restrict__ ob, float* __restrict__ out) {
    int w = threadIdx.x >> 5, lane = threadIdx.x & 31;
    int t = blockIdx.x * 8 + w;
    size_t base = (size_t)t * Dq;

    float y[16];
    float sum = 0.f;
#pragma unroll
    for (int j = 0; j < 4; j++) {
        int d = (lane + 32 * j) * 4;
        float4 v = *(const float4*)&c[base + d];
        y[j * 4 + 0] = v.x; y[j * 4 + 1] = v.y;
        y[j * 4 + 2] = v.z; y[j * 4 + 3] = v.w;
        sum += v.x + v.y + v.z + v.w;
    }
    float mean = warp_sum(sum) * (1.f / Dq);
    float vs = 0.f;
#pragma unroll
    for (int i = 0; i < 16; i++) {
        float dv = y[i] - mean;
        vs += dv * dv;
    }
    float rs = rsqrtf(warp_sum(vs) * (1.f / Dq) + 1e-5f);

    float z[16];
    float sum2 = 0.f;
#pragma unroll
    for (int j = 0; j < 4; j++) {
        int d = (lane + 32 * j) * 4;
        float4 gv = *(const float4*)&cg[d];
        float4 bv = *(const float4*)&cb[d];
        z[j * 4 + 0] = (y[j * 4 + 0] - mean) * rs * gv.x + bv.x;
        z[j * 4 + 1] = (y[j * 4 + 1] - mean) * rs * gv.y + bv.y;
        z[j * 4 + 2] = (y[j * 4 + 2] - mean) * rs * gv.z + bv.z;
        z[j * 4 + 3] = (y[j * 4 + 3] - mean) * rs * gv.w + bv.w;
        sum2 += z[j * 4] + z[j * 4 + 1] + z[j * 4 + 2] + z[j * 4 + 3];
    }
    float mean2 = warp_sum(sum2) * (1.f / Dq);
    float vs2 = 0.f;
#pragma unroll
    for (int i = 0; i < 16; i++) {
        float dv = z[i] - mean2;
        vs2 += dv * dv;
    }
    float rs2 = rsqrtf(warp_sum(vs2) * (1.f / Dq) + 1e-5f);
#pragma unroll
    for (int j = 0; j < 4; j++) {
        int d = (lane + 32 * j) * 4;
        float4 gv = *(const float4*)&og[d];
        float4 bv = *(const float4*)&ob[d];
        float4 ov;
        ov.x = roundtf((z[j * 4 + 0] - mean2) * rs2 * gv.x + bv.x);
        ov.y = roundtf((z[j * 4 + 1] - mean2) * rs2 * gv.y + bv.y);
        ov.z = roundtf((z[j * 4 + 2] - mean2) * rs2 * gv.z + bv.z);
        ov.w = roundtf((z[j * 4 + 3] - mean2) * rs2 * gv.w + bv.w);
        *(float4*)&out[base + d] = ov;
    }
}

// ==========================================================================
extern "C" void kernel_launch(void* const* d_in, const int* in_sizes, int n_in,
                              void* d_out, int out_size) {
    const float* x       = (const float*)d_in[0];
    const int*   ts      = (const int*)d_in[1];
    const float* W_feat  = (const float*)d_in[2];
    const float* b_feat  = (const float*)d_in[3];
    const float* emb     = (const float*)d_in[4];
    const float* W_emb   = (const float*)d_in[5];
    const float* b_emb   = (const float*)d_in[6];
    const float* Wq      = (const float*)d_in[7];
    const float* bq      = (const float*)d_in[8];
    const float* Wk      = (const float*)d_in[9];
    const float* bk      = (const float*)d_in[10];
    const float* Wv      = (const float*)d_in[11];
    const float* bv      = (const float*)d_in[12];
    const float* Wo      = (const float*)d_in[13];
    const float* bo      = (const float*)d_in[14];
    const float* Wg      = (const float*)d_in[15];
    const float* bg      = (const float*)d_in[16];
    const float* Wu      = (const float*)d_in[17];
    const float* bu      = (const float*)d_in[18];
    const float* ln_g    = (const float*)d_in[19];
    const float* ln_b    = (const float*)d_in[20];
    const float* conv_w  = (const float*)d_in[21];
    const float* conv_b  = (const float*)d_in[22];
    const float* cn_g    = (const float*)d_in[23];
    const float* cn_b    = (const float*)d_in[24];
    const float* on_g    = (const float*)d_in[25];
    const float* on_b    = (const float*)d_in[26];
    const float* W_out   = (const float*)d_in[27];
    const float* b_out   = (const float*)d_in[28];
    float* out = (float*)d_out;

    float *cat, *h, *mem, *qkv, *ap, *a, *gu, *c, *c2, *wc;
    float *wqkvT, *bqkv, *wguT, *bgu, *woT, *wembT;
    cudaGetSymbolAddress((void**)&cat, g_cat);
    cudaGetSymbolAddress((void**)&h,   g_h);
    cudaGetSymbolAddress((void**)&mem, g_mem);
    cudaGetSymbolAddress((void**)&qkv, g_qkv);
    cudaGetSymbolAddress((void**)&ap,  g_ap);
    cudaGetSymbolAddress((void**)&a,   g_a);
    cudaGetSymbolAddress((void**)&gu,  g_gu);
    cudaGetSymbolAddress((void**)&c,   g_c);
    cudaGetSymbolAddress((void**)&c2,  g_c2);
    cudaGetSymbolAddress((void**)&wc,  g_wc);
    cudaGetSymbolAddress((void**)&wqkvT, g_wqkvT);
    cudaGetSymbolAddress((void**)&bqkv,  g_bqkv);
    cudaGetSymbolAddress((void**)&wguT,  g_wguT);
    cudaGetSymbolAddress((void**)&bgu,   g_bgu);
    cudaGetSymbolAddress((void**)&woT,   g_woT);
    cudaGetSymbolAddress((void**)&wembT, g_wembT);

    static int smem_set = 0;
    if (!smem_set) {
        cudaFuncSetAttribute(gemm_tc_kernel,
                             cudaFuncAttributeMaxDynamicSharedMemorySize, SMEM_TC);
        cudaFuncSetAttribute(attn_tc_kernel,
                             cudaFuncAttributeMaxDynamicSharedMemorySize, SMEM_ATT);
        cudaFuncSetAttribute(out_gemm_kernel,
                             cudaFuncAttributeMaxDynamicSharedMemorySize, OUT_SMEM);
        smem_set = 1;
    }

    // 0. merged weight pre-pack (one launch covers all segments)
    pack_all_kernel<<<(Lq * 2 * Dq * Dq + 255) / 256, 256>>>(
        Wq, Wk, Wv, bq, bk, bv, Wg, Wu, bg, bu, Wo, W_emb, conv_w,
        wqkvT, bqkv, wguT, bgu, woT, wembT, wc);

    // 1. embedding
    build_cat_kernel<<<NTq, 128>>>(x, ts, W_feat, b_feat, emb, cat);
    launch_tc(cat, cat, 8, 2 * FDq, 2 * FDq, wembT, 2 * FDq, b_emb, h, Dq,
              NTq, Dq, 2 * FDq, 1);

    // 2. layers (mem implicitly zero in layer 0)
    for (int l = 0; l < Lq; l++) {
        launch_tc(h, h, 16, Dq, Dq, wqkvT + (size_t)l * 3 * Dq * Dq, Dq,
                  bqkv + l * 3 * Dq, qkv, 3 * Dq, NTq, 3 * Dq, Dq, 1);

        attn_tc_kernel<<<dim3(NBq, Hq, Bq), 256, SMEM_ATT>>>(qkv, ap);

        launch_tc(ap, ap, 16, Dq, Dq, woT + (size_t)l * Dq * Dq, Dq,
                  bo + l * Dq, a, Dq, NTq, Dq, Dq, 1);

        if (l == 0)
            launch_tc(a, a, 16, Dq, Dq, wguT + (size_t)l * 2 * Dq * 2 * Dq, 2 * Dq,
                      bgu + l * 2 * Dq, gu, 2 * Dq, NTq, 2 * Dq, Dq, 0);
        else
            launch_tc(a, mem, 16, Dq, Dq, wguT + (size_t)l * 2 * Dq * 2 * Dq, 2 * Dq,
                      bgu + l * 2 * Dq, gu, 2 * Dq, NTq, 2 * Dq, 2 * Dq, 0);

        gate_ln_kernel<<<NTq / 8, 256>>>(a, gu, mem, ln_g + l * Dq,
                                         ln_b + l * Dq, h, l == 0);
    }

    // 3. temporal compression (conv as GEMM; weight transposed [512][2048])
    launch_tc(h, h, 64, CFq * Dq, CFq * Dq, wc, CFq * Dq, conv_b, c, Dq,
              Bq * NCq, Dq, CFq * Dq, 0);

    // 4. double LayerNorm
    double_ln_kernel<<<Bq * NCq / 8, 256>>>(c, cn_g, cn_b, on_g, on_b, c2);

    // 5. output projection (warp-per-row)
    out_gemm_kernel<<<Bq * NCq / 8, 256, OUT_SMEM>>>(c2, W_out, b_out, out);
}

// round 17
// speedup vs baseline: 1.1944x; 1.0225x over previous
#include <cuda_runtime.h>
#include <cuda_bf16.h>
#include <cstdint>

// Problem constants
#define Bq 4
#define Sq 8192
#define Fq 32
#define Dq 512
#define Hq 8
#define Lq 4
#define FDq 128
#define WINq 256
#define CFq 4
#define HDq 64
#define NTq (Bq * Sq)          // 32768 tokens
#define NBq (Sq / WINq)        // 32 windows
#define NCq (Sq / CFq)         // 2048 compressed steps per batch

// -------------------- scratch (device globals; no allocation allowed) -----
__device__ float g_cat[NTq * 2 * FDq];
__device__ float g_h  [NTq * Dq];
__device__ float g_mem[NTq * Dq];
__device__ float g_qkv[NTq * 3 * Dq];
__device__ float g_ap [NTq * Dq];
__device__ float g_a  [NTq * Dq];
__device__ float g_gu [NTq * 2 * Dq];
__device__ float g_c  [Bq * NCq * Dq];
__device__ float g_c2 [Bq * NCq * Dq];
__device__ float g_wc [CFq * Dq * Dq];         // conv weight^T [512][2048]
__device__ float g_wqkvT[Lq * 3 * Dq * Dq];    // per-layer [1536][512]
__device__ float g_bqkv [Lq * 3 * Dq];
__device__ float g_wguT [Lq * 2 * Dq * 2 * Dq];// per-layer [1024][1024]
__device__ float g_bgu  [Lq * 2 * Dq];
__device__ float g_woT  [Lq * Dq * Dq];        // per-layer [512][512]
__device__ float g_wembT[2 * FDq * Dq];        // [512][256]

// ==================== helpers =============================================
__device__ __forceinline__ uint32_t smem_u32(const void* p) {
    uint32_t a;
    asm("{ .reg .u64 t; cvta.to.shared.u64 t, %1; cvt.u32.u64 %0, t; }"
        : "=r"(a) : "l"(p));
    return a;
}
__device__ __forceinline__ uint32_t f2tf(float f) {
    uint32_t u;
    asm("cvt.rna.tf32.f32 %0, %1;" : "=r"(u) : "f"(f));
    return u;
}
__device__ __forceinline__ float roundtf(float f) {
    return __uint_as_float(f2tf(f));
}
__device__ __forceinline__ void mma_tf32(float* d, const uint32_t* a,
                                         const uint32_t* b) {
    asm volatile(
        "mma.sync.aligned.m16n8k8.row.col.f32.tf32.tf32.f32 "
        "{%0,%1,%2,%3}, {%4,%5,%6,%7}, {%8,%9}, {%0,%1,%2,%3};"
        : "+f"(d[0]), "+f"(d[1]), "+f"(d[2]), "+f"(d[3])
        : "r"(a[0]), "r"(a[1]), "r"(a[2]), "r"(a[3]), "r"(b[0]), "r"(b[1]));
}
__device__ __forceinline__ void cpa16(uint32_t dst, const float* src) {
    asm volatile("cp.async.cg.shared.global [%0], [%1], 16;"
                 :: "r"(dst), "l"(src));
}
__device__ __forceinline__ void ldsm4(uint32_t* r, uint32_t addr) {
    asm volatile("ldmatrix.sync.aligned.m8n8.x4.shared.b16 {%0,%1,%2,%3}, [%4];"
                 : "=r"(r[0]), "=r"(r[1]), "=r"(r[2]), "=r"(r[3]) : "r"(addr));
}
__device__ __forceinline__ float warp_sum(float v) {
#pragma unroll
    for (int o = 16; o > 0; o >>= 1)
        v += __shfl_xor_sync(0xffffffffu, v, o);
    return v;
}
#define CPA_COMMIT() asm volatile("cp.async.commit_group;" ::: "memory")
#define CPA_WAIT0()  asm volatile("cp.async.wait_group 0;" ::: "memory")
#define CPA_WAIT1()  asm volatile("cp.async.wait_group 1;" ::: "memory")
#define CPA_WAIT2()  asm volatile("cp.async.wait_group 2;" ::: "memory")

// ==================== tf32 tensor-core GEMM ===============================
// R16 config + split A/B commit groups (A's DMA starts right after kk=0);
// top-of-loop wait becomes wait_group 2 (wait_group 0 on the last chunk).
// Numerics identical.
#define ASTR 36
#define ST_W (128 * ASTR)
#define SMEM_TC (6 * ST_W * 4)     // 110592 bytes

__global__ __launch_bounds__(256, 2)
void gemm_tc_kernel(const float* __restrict__ A0, const float* __restrict__ A1,
                    int scChunks, int lda0, int lda1,
                    const float* __restrict__ BmT, int ldbt,
                    const float* __restrict__ bias,
                    float* __restrict__ C, int ldc, int nChunks, int roundOut) {
    extern __shared__ float smem[];
    uint32_t sbase = smem_u32(smem);

    int tid = threadIdx.x;
    int lane = tid & 31, wid = tid >> 5;
    int warpM = wid & 3, warpN = wid >> 2;
    int g = lane >> 2, c4 = lane & 3;
    int rowbase = blockIdx.y * 128;
    int colbase = blockIdx.x * 128;

    int rowA = warpM * 32 + (lane & 15);
    uint32_t aOff = (uint32_t)(rowA * ASTR + (lane >> 4) * 4) * 4;
    int rowB = warpN * 64 + ((lane >> 4) << 3) + (lane & 7);
    uint32_t bOff = (uint32_t)(rowB * ASTR + ((lane >> 3) & 1) * 4) * 4;

    float acc[2][8][4];
#pragma unroll
    for (int mi = 0; mi < 2; mi++)
#pragma unroll
        for (int nj = 0; nj < 8; nj++)
#pragma unroll
            for (int r = 0; r < 4; r++) acc[mi][nj][r] = 0.f;

#define ISSUE_A(ch) do { \
        int _st = (ch) % 3; \
        uint32_t _sa = sbase + (uint32_t)(_st * ST_W) * 4; \
        const float* Ap; int kc, lda; \
        if ((ch) < scChunks) { Ap = A0; kc = (ch); lda = lda0; } \
        else { Ap = A1; kc = (ch) - scChunks; lda = lda1; } \
        _Pragma("unroll") \
        for (int i = 0; i < 4; i++) { \
            int id = tid + i * 256; int r = id >> 3, sg = id & 7; \
            cpa16(_sa + (uint32_t)(r * ASTR + sg * 4) * 4, \
                  Ap + (size_t)(rowbase + r) * lda + kc * 32 + sg * 4); \
        } \
    } while (0)
#define ISSUE_B(ch) do { \
        int _st = (ch) % 3; \
        uint32_t _sb = sbase + (uint32_t)((3 + _st) * ST_W) * 4; \
        _Pragma("unroll") \
        for (int i = 0; i < 4; i++) { \
            int id = tid + i * 256; int r = id >> 3, sg = id & 7; \
            cpa16(_sb + (uint32_t)(r * ASTR + sg * 4) * 4, \
                  BmT + (size_t)(colbase + r) * ldbt + (ch) * 32 + sg * 4); \
        } \
    } while (0)

#define COMPUTE_KK(kk) do { \
        uint32_t af[2][4], bf[4][4]; \
        ldsm4(af[0], aBase + (kk) * 32); \
        ldsm4(af[1], aBase + 16 * ASTR * 4 + (kk) * 32); \
        _Pragma("unroll") \
        for (int pr = 0; pr < 4; pr++) \
            ldsm4(bf[pr], bBase + pr * 16 * ASTR * 4 + (kk) * 32); \
        _Pragma("unroll") \
        for (int mi = 0; mi < 2; mi++) \
            _Pragma("unroll") \
            for (int pr = 0; pr < 4; pr++) { \
                mma_tf32(acc[mi][2 * pr],     af[mi], &bf[pr][0]); \
                mma_tf32(acc[mi][2 * pr + 1], af[mi], &bf[pr][2]); \
            } \
    } while (0)

    // prologue: 2 chunks in flight, one group per A/B half (4 groups)
    ISSUE_A(0); CPA_COMMIT();
    ISSUE_B(0); CPA_COMMIT();
    ISSUE_A(1); CPA_COMMIT();
    ISSUE_B(1); CPA_COMMIT();

    for (int ch = 0; ch < nChunks; ch++) {
        int st = ch % 3;
        if (ch + 1 < nChunks) CPA_WAIT2();   // A(ch),B(ch) resident
        else                  CPA_WAIT0();   // tail: drain everything
        __syncthreads();           // frees stage (ch-1)%3 for the issues below

        uint32_t aBase = sbase + (uint32_t)(st * ST_W) * 4 + aOff;
        uint32_t bBase = sbase + (uint32_t)((3 + st) * ST_W) * 4 + bOff;

        COMPUTE_KK(0);
        if (ch + 2 < nChunks) { ISSUE_A(ch + 2); CPA_COMMIT(); }
        COMPUTE_KK(1);
        if (ch + 2 < nChunks) { ISSUE_B(ch + 2); CPA_COMMIT(); }
        COMPUTE_KK(2);
        COMPUTE_KK(3);
    }
#undef COMPUTE_KK
#undef ISSUE_A
#undef ISSUE_B

#pragma unroll
    for (int mi = 0; mi < 2; mi++) {
        int r0 = rowbase + warpM * 32 + mi * 16 + g;
#pragma unroll
        for (int nj = 0; nj < 8; nj++) {
            int col = colbase + warpN * 64 + nj * 8 + 2 * c4;
            float b0 = bias[col], b1 = bias[col + 1];
            float o0 = acc[mi][nj][0] + b0, o1 = acc[mi][nj][1] + b1;
            float o2 = acc[mi][nj][2] + b0, o3 = acc[mi][nj][3] + b1;
            if (roundOut) {
                o0 = roundtf(o0); o1 = roundtf(o1);
                o2 = roundtf(o2); o3 = roundtf(o3);
            }
            *(float2*)(C + (size_t)r0 * ldc + col) = make_float2(o0, o1);
            *(float2*)(C + (size_t)(r0 + 8) * ldc + col) = make_float2(o2, o3);
        }
    }
}

static inline void launch_tc(const float* A0, const float* A1, int sc,
                             int lda0, int lda1, const float* BmT, int ldbt,
                             const float* bias, float* C, int ldc,
                             int M, int N, int K, int roundOut) {
    dim3 grid(N / 128, M / 128);
    gemm_tc_kernel<<<grid, 256, SMEM_TC>>>(A0, A1, sc, lda0, lda1, BmT, ldbt,
                                           bias, C, ldc, K / 32, roundOut);
}

// ==================== tensor-core windowed attention ======================
// R16 structure; Q staging now via cp.async (no LDG->reg->STS round trip).
#define KSTR 68
#define VSTR 72
#define PSTR 36
#define SMA_K(s) ((s) * 32 * KSTR)
#define SMA_VB   (3 * 32 * KSTR)
#define SMA_V(s) (SMA_VB + (s) * 32 * VSTR)
#define SMA_P    (3 * 32 * KSTR + 3 * 32 * VSTR)
#define SMEM_ATT ((SMA_P + 256 * PSTR) * 4)

__global__ __launch_bounds__(256)
void attn_tc_kernel(const float* __restrict__ qkv, float* __restrict__ out) {
    extern __shared__ float sm[];
    int blk = blockIdx.x, head = blockIdx.y, b = blockIdx.z;
    int tid = threadIdx.x, lane = tid & 31, w = tid >> 5;
    int g = lane >> 2, c4 = lane & 3;
    const int LD = 3 * Dq;
    const int qbase = b * Sq + blk * WINq;
    uint32_t sbase = smem_u32(sm);

    // ---- stage Q via cp.async (row tid, 64 floats) ----
    {
        const float* src = qkv + (size_t)(qbase + tid) * LD + head * HDq;
        uint32_t dst = sbase + (uint32_t)(tid * KSTR) * 4;
#pragma unroll
        for (int j = 0; j < 16; j++) cpa16(dst + j * 16, src + j * 4);
        CPA_COMMIT();
        CPA_WAIT0();
    }
    __syncthreads();
    uint32_t qf[2][8][4];
#pragma unroll
    for (int mi = 0; mi < 2; mi++) {
        int r = w * 32 + mi * 16 + g;
#pragma unroll
        for (int kt = 0; kt < 8; kt++) {
            qf[mi][kt][0] = __float_as_uint(sm[r * KSTR + kt * 8 + c4]);
            qf[mi][kt][1] = __float_as_uint(sm[(r + 8) * KSTR + kt * 8 + c4]);
            qf[mi][kt][2] = __float_as_uint(sm[r * KSTR + kt * 8 + c4 + 4]);
            qf[mi][kt][3] = __float_as_uint(sm[(r + 8) * KSTR + kt * 8 + c4 + 4]);
        }
    }
    __syncthreads();

    float o[2][8][4];
#pragma unroll
    for (int mi = 0; mi < 2; mi++)
#pragma unroll
        for (int nt = 0; nt < 8; nt++)
#pragma unroll
            for (int j = 0; j < 4; j++) o[mi][nt][j] = 0.f;
    float m_run[2][2] = {{-1e30f, -1e30f}, {-1e30f, -1e30f}};
    float l_run[2][2] = {{0.f, 0.f}, {0.f, 0.f}};

    const int ktok0 = b * Sq + (blk - 1) * WINq;
    const int c0 = (blk == 0) ? 8 : 0;

#define AISSUE(ci) do { \
        int _st = (ci) % 3; \
        int r = tid >> 3, sg = tid & 7; \
        const float* kv = qkv + (size_t)(ktok0 + (ci) * 32 + r) * LD + head * HDq; \
        uint32_t kd = sbase + (uint32_t)(SMA_K(_st) + r * KSTR) * 4; \
        uint32_t vd = sbase + (uint32_t)(SMA_V(_st) + r * VSTR) * 4; \
        cpa16(kd + sg * 16,        kv + Dq + sg * 4); \
        cpa16(kd + (sg + 8) * 16,  kv + Dq + (sg + 8) * 4); \
        cpa16(vd + sg * 16,        kv + 2 * Dq + sg * 4); \
        cpa16(vd + (sg + 8) * 16,  kv + 2 * Dq + (sg + 8) * 4); \
    } while (0)

    AISSUE(c0);     CPA_COMMIT();
    AISSUE(c0 + 1); CPA_COMMIT();

    float* Pt = sm + SMA_P;
    for (int ci = c0; ci < 16; ci++) {
        CPA_WAIT1();
        __syncthreads();
        const float* Kt = sm + SMA_K(ci % 3);
        const float* Vt = sm + SMA_V(ci % 3);

#pragma unroll
        for (int mi = 0; mi < 2; mi++) {
            float s[4][4];
#pragma unroll
            for (int nt = 0; nt < 4; nt++)
#pragma unroll
                for (int j = 0; j < 4; j++) s[nt][j] = 0.f;
#pragma unroll
            for (int kt = 0; kt < 8; kt++) {
                uint32_t bb[4][2];
#pragma unroll
                for (int nt = 0; nt < 4; nt++) {
                    bb[nt][0] = __float_as_uint(Kt[(nt * 8 + g) * KSTR + kt * 8 + c4]);
                    bb[nt][1] = __float_as_uint(Kt[(nt * 8 + g) * KSTR + kt * 8 + c4 + 4]);
                }
#pragma unroll
                for (int nt = 0; nt < 4; nt++)
                    mma_tf32(s[nt], qf[mi][kt], bb[nt]);
            }
            // defer next-chunk loads into the mma-result dependency stall
            if (mi == 0) {
                if (ci + 2 < 16) AISSUE(ci + 2);
                CPA_COMMIT();
            }
#pragma unroll
            for (int nt = 0; nt < 4; nt++)
#pragma unroll
                for (int j = 0; j < 4; j++) s[nt][j] *= 0.125f;

            float ml0 = s[0][0], ml1 = s[0][2];
#pragma unroll
            for (int nt = 0; nt < 4; nt++) {
                ml0 = fmaxf(ml0, fmaxf(s[nt][0], s[nt][1]));
                ml1 = fmaxf(ml1, fmaxf(s[nt][2], s[nt][3]));
            }
            ml0 = fmaxf(ml0, __shfl_xor_sync(0xffffffffu, ml0, 1));
            ml0 = fmaxf(ml0, __shfl_xor_sync(0xffffffffu, ml0, 2));
            ml1 = fmaxf(ml1, __shfl_xor_sync(0xffffffffu, ml1, 1));
            ml1 = fmaxf(ml1, __shfl_xor_sync(0xffffffffu, ml1, 2));

            float mn0 = fmaxf(m_run[mi][0], ml0);
            float mn1 = fmaxf(m_run[mi][1], ml1);
            float sc0 = __expf(m_run[mi][0] - mn0);
            float sc1 = __expf(m_run[mi][1] - mn1);
            m_run[mi][0] = mn0; m_run[mi][1] = mn1;

            float ps0 = 0.f, ps1 = 0.f;
#pragma unroll
            for (int nt = 0; nt < 4; nt++) {
                s[nt][0] = roundtf(__expf(s[nt][0] - mn0)); ps0 += s[nt][0];
                s[nt][1] = roundtf(__expf(s[nt][1] - mn0)); ps0 += s[nt][1];
                s[nt][2] = roundtf(__expf(s[nt][2] - mn1)); ps1 += s[nt][2];
                s[nt][3] = roundtf(__expf(s[nt][3] - mn1)); ps1 += s[nt][3];
            }
            ps0 += __shfl_xor_sync(0xffffffffu, ps0, 1);
            ps0 += __shfl_xor_sync(0xffffffffu, ps0, 2);
            ps1 += __shfl_xor_sync(0xffffffffu, ps1, 1);
            ps1 += __shfl_xor_sync(0xffffffffu, ps1, 2);
            l_run[mi][0] = l_run[mi][0] * sc0 + ps0;
            l_run[mi][1] = l_run[mi][1] * sc1 + ps1;

#pragma unroll
            for (int nt = 0; nt < 8; nt++) {
                o[mi][nt][0] *= sc0; o[mi][nt][1] *= sc0;
                o[mi][nt][2] *= sc1; o[mi][nt][3] *= sc1;
            }
            int r = w * 32 + mi * 16 + g;
#pragma unroll
            for (int nt = 0; nt < 4; nt++) {
                *(float2*)&Pt[r * PSTR + nt * 8 + 2 * c4] = make_float2(s[nt][0], s[nt][1]);
                *(float2*)&Pt[(r + 8) * PSTR + nt * 8 + 2 * c4] = make_float2(s[nt][2], s[nt][3]);
            }
        }
        __syncwarp();

#pragma unroll
        for (int kt = 0; kt < 4; kt++) {
            uint32_t pa[2][4];
#pragma unroll
            for (int mi = 0; mi < 2; mi++) {
                int r = w * 32 + mi * 16 + g;
                pa[mi][0] = __float_as_uint(Pt[r * PSTR + kt * 8 + c4]);
                pa[mi][1] = __float_as_uint(Pt[(r + 8) * PSTR + kt * 8 + c4]);
                pa[mi][2] = __float_as_uint(Pt[r * PSTR + kt * 8 + c4 + 4]);
                pa[mi][3] = __float_as_uint(Pt[(r + 8) * PSTR + kt * 8 + c4 + 4]);
            }
#pragma unroll
            for (int nt = 0; nt < 8; nt++) {
                uint32_t bv[2];
                bv[0] = __float_as_uint(Vt[(kt * 8 + c4) * VSTR + nt * 8 + g]);
                bv[1] = __float_as_uint(Vt[(kt * 8 + c4 + 4) * VSTR + nt * 8 + g]);
                mma_tf32(o[0][nt], pa[0], bv);
                mma_tf32(o[1][nt], pa[1], bv);
            }
        }
    }
#undef AISSUE

#pragma unroll
    for (int mi = 0; mi < 2; mi++) {
        float inv0 = 1.f / l_run[mi][0];
        float inv1 = 1.f / l_run[mi][1];
        int r = qbase + w * 32 + mi * 16 + g;
#pragma unroll
        for (int nt = 0; nt < 8; nt++) {
            int col = head * HDq + nt * 8 + 2 * c4;
            *(float2*)&out[(size_t)r * Dq + col] =
                make_float2(roundtf(o[mi][nt][0] * inv0), roundtf(o[mi][nt][1] * inv0));
            *(float2*)&out[(size_t)(r + 8) * Dq + col] =
                make_float2(roundtf(o[mi][nt][2] * inv1), roundtf(o[mi][nt][3] * inv1));
        }
    }
}

// -------------------- single merged weight pre-pack -----------------------
__global__ void pack_all_kernel(
    const float* __restrict__ Wq, const float* __restrict__ Wk,
    const float* __restrict__ Wv, const float* __restrict__ bq,
    const float* __restrict__ bk, const float* __restrict__ bv,
    const float* __restrict__ Wg, const float* __restrict__ Wu,
    const float* __restrict__ bg, const float* __restrict__ bu,
    const float* __restrict__ Wo, const float* __restrict__ W_emb,
    const float* __restrict__ conv_w,
    float* __restrict__ wqkvT, float* __restrict__ bqkv,
    float* __restrict__ wguT, float* __restrict__ bgu,
    float* __restrict__ woT, float* __restrict__ wembT,
    float* __restrict__ wcT) {
    int i = blockIdx.x * 256 + threadIdx.x;
    if (i < Lq * Dq * Dq) {
        int l = i >> 18;
        int r = i & (Dq * Dq - 1);
        int n = r >> 9, k = r & 511;
        size_t so = (size_t)l * Dq * Dq + (size_t)k * Dq + n;
        float* dst = wqkvT + (size_t)l * 3 * Dq * Dq;
        dst[(size_t)n * Dq + k] = roundtf(Wq[so]);
        dst[(size_t)(Dq + n) * Dq + k] = roundtf(Wk[so]);
        dst[(size_t)(2 * Dq + n) * Dq + k] = roundtf(Wv[so]);
    }
    if (i < Lq * Dq) {
        int l = i >> 9, n = i & 511;
        bqkv[l * 3 * Dq + n] = bq[l * Dq + n];
        bqkv[l * 3 * Dq + Dq + n] = bk[l * Dq + n];
        bqkv[l * 3 * Dq + 2 * Dq + n] = bv[l * Dq + n];
        bgu[l * 2 * Dq + n] = bg[l * Dq + n];
        bgu[l * 2 * Dq + Dq + n] = bu[l * Dq + n];
    }
    if (i < Lq * 2 * Dq * Dq) {
        int l = i >> 19;
        int r = i & (2 * Dq * Dq - 1);
        int n = r >> 10, k = r & 1023;
        size_t so = (size_t)l * 2 * Dq * Dq + (size_t)k * Dq + n;
        float* dst = wguT + (size_t)l * 2 * Dq * 2 * Dq;
        dst[(size_t)n * 2 * Dq + k] = roundtf(Wg[so]);
        dst[(size_t)(Dq + n) * 2 * Dq + k] = roundtf(Wu[so]);
    }
    if (i < Lq * Dq * Dq) {
        int l = i >> 18;
        int r = i & (Dq * Dq - 1);
        int n = r >> 9, k = r & 511;
        woT[(size_t)l * Dq * Dq + (size_t)n * Dq + k] =
            roundtf(Wo[(size_t)l * Dq * Dq + (size_t)k * Dq + n]);
    }
    if (i < 2 * FDq * Dq) {
        int n = i / (2 * FDq), k = i - n * (2 * FDq);
        wembT[i] = roundtf(W_emb[(size_t)k * Dq + n]);
    }
    if (i < CFq * Dq * Dq) {
        int o = i >> 11, r = i & 2047;
        int j = r >> 9, c = r & 511;
        wcT[i] = roundtf(conv_w[(size_t)o * (Dq * CFq) + c * CFq + j]);
    }
}

// -------------------- embedding: cat = [x@W_feat + b_feat, emb[ts]] -------
__global__ __launch_bounds__(128)
void build_cat_kernel(const float* __restrict__ x, const int* __restrict__ ts,
                      const float* __restrict__ Wf, const float* __restrict__ bf,
                      const float* __restrict__ emb, float* __restrict__ cat) {
    int t = blockIdx.x;
    int d = threadIdx.x;
    __shared__ float xr[Fq];
    if (d < Fq) xr[d] = x[t * Fq + d];
    __syncthreads();
    float s = bf[d];
#pragma unroll
    for (int i = 0; i < Fq; i++) s += xr[i] * Wf[i * FDq + d];
    cat[t * 2 * FDq + d] = roundtf(s);
    cat[t * 2 * FDq + FDq + d] = roundtf(emb[ts[t] * FDq + d]);
}

// -------------------- output projection (warp-per-row, smem W) ------------
#define OUT_SMEM (32 * 513 * 4)
__global__ __launch_bounds__(256)
void out_gemm_kernel(const float* __restrict__ A, const float* __restrict__ W,
                     const float* __restrict__ bias, float* __restrict__ C) {
    extern __shared__ float Wt[];   // [32][513]
    int tid = threadIdx.x, w = tid >> 5, lane = tid & 31;
    for (int i = tid; i < Dq * Fq; i += 256) {
        int k = i >> 5, n = i & 31;
        Wt[n * 513 + k] = W[i];
    }
    __syncthreads();

    int row = blockIdx.x * 8 + w;
    float a[16];
#pragma unroll
    for (int j = 0; j < 16; j++)
        a[j] = A[(size_t)row * Dq + lane + 32 * j];
#pragma unroll
    for (int n = 0; n < 32; n++) {
        float p = 0.f;
        const float* wn = Wt + n * 513;
#pragma unroll
        for (int j = 0; j < 16; j++) p += a[j] * wn[lane + 32 * j];
        p = warp_sum(p);
        if (lane == 0) C[(size_t)row * Fq + n] = p + bias[n];
    }
}

// -------------------- fused gate + memory + LayerNorm (warp/token) --------
__global__ __launch_bounds__(256)
void gate_ln_kernel(const float* __restrict__ a, const float* __restrict__ gu,
                    float* __restrict__ mem,
                    const float* __restrict__ g, const float* __restrict__ bta,
                    float* __restrict__ hout, int first) {
    int w = threadIdx.x >> 5, lane = threadIdx.x & 31;
    int t = blockIdx.x * 8 + w;
    size_t base = (size_t)t * Dq;
    size_t gbase = (size_t)t * 2 * Dq;

    float y[16];
    float sum = 0.f;
#pragma unroll
    for (int j = 0; j < 4; j++) {
        int d = (lane + 32 * j) * 4;
        float4 gg = *(const float4*)&gu[gbase + d];
        float4 uu = *(const float4*)&gu[gbase + Dq + d];
        float4 av = *(const float4*)&a[base + d];
        float4 mm = first ? make_float4(0.f, 0.f, 0.f, 0.f)
                          : *(const float4*)&mem[base + d];
        float g0 = 1.f / (1.f + __expf(-gg.x));
        float g1 = 1.f / (1.f + __expf(-gg.y));
        float g2 = 1.f / (1.f + __expf(-gg.z));
        float g3 = 1.f / (1.f + __expf(-gg.w));
        float nm0 = g0 * uu.x + (1.f - g0) * mm.x;
        float nm1 = g1 * uu.y + (1.f - g1) * mm.y;
        float nm2 = g2 * uu.z + (1.f - g2) * mm.z;
        float nm3 = g3 * uu.w + (1.f - g3) * mm.w;
        *(float4*)&mem[base + d] = make_float4(roundtf(nm0), roundtf(nm1),
                                               roundtf(nm2), roundtf(nm3));
        y[j * 4 + 0] = av.x + nm0;
        y[j * 4 + 1] = av.y + nm1;
        y[j * 4 + 2] = av.z + nm2;
        y[j * 4 + 3] = av.w + nm3;
        sum += y[j * 4] + y[j * 4 + 1] + y[j * 4 + 2] + y[j * 4 + 3];
    }
    float mean = warp_sum(sum) * (1.f / Dq);
    float vs = 0.f;
#pragma unroll
    for (int i = 0; i < 16; i++) {
        float dv = y[i] - mean;
        vs += dv * dv;
    }
    float rs = rsqrtf(warp_sum(vs) * (1.f / Dq) + 1e-5f);
#pragma unroll
    for (int j = 0; j < 4; j++) {
        int d = (lane + 32 * j) * 4;
        float4 gv = *(const float4*)&g[d];
        float4 bv = *(const float4*)&bta[d];
        float4 ov;
        ov.x = roundtf((y[j * 4 + 0] - mean) * rs * gv.x + bv.x);
        ov.y = roundtf((y[j * 4 + 1] - mean) * rs * gv.y + bv.y);
        ov.z = roundtf((y[j * 4 + 2] - mean) * rs * gv.z + bv.z);
        ov.w = roundtf((y[j * 4 + 3] - mean) * rs * gv.w + bv.w);
        *(float4*)&hout[base + d] = ov;
    }
}

// -------------------- double LayerNorm (warp/token) -----------------------
__global__ __launch_bounds__(256)
void double_ln_kernel(const float* __restrict__ c, const float* __restrict__ cg,
                      const float* __restrict__ cb, const float* __restrict__ og,
                      const float* __restrict__ ob, float* __restrict__ out) {
    int w = threadIdx.x >> 5, lane = threadIdx.x & 31;
    int t = blockIdx.x * 8 + w;
    size_t base = (size_t)t * Dq;

    float y[16];
    float sum = 0.f;
#pragma unroll
    for (int j = 0; j < 4; j++) {
        int d = (lane + 32 * j) * 4;
        float4 v = *(const float4*)&c[base + d];
        y[j * 4 + 0] = v.x; y[j * 4 + 1] = v.y;
        y[j * 4 + 2] = v.z; y[j * 4 + 3] = v.w;
        sum += v.x + v.y + v.z + v.w;
    }
    float mean = warp_sum(sum) * (1.f / Dq);
    float vs = 0.f;
#pragma unroll
    for (int i = 0; i < 16; i++) {
        float dv = y[i] - mean;
        vs += dv * dv;
    }
    float rs = rsqrtf(warp_sum(vs) * (1.f / Dq) + 1e-5f);

    float z[16];
    float sum2 = 0.f;
#pragma unroll
    for (int j = 0; j < 4; j++) {
        int d = (lane + 32 * j) * 4;
        float4 gv = *(const float4*)&cg[d];
        float4 bv = *(const float4*)&cb[d];
        z[j * 4 + 0] = (y[j * 4 + 0] - mean) * rs * gv.x + bv.x;
        z[j * 4 + 1] = (y[j * 4 + 1] - mean) * rs * gv.y + bv.y;
        z[j * 4 + 2] = (y[j * 4 + 2] - mean) * rs * gv.z + bv.z;
        z[j * 4 + 3] = (y[j * 4 + 3] - mean) * rs * gv.w + bv.w;
        sum2 += z[j * 4] + z[j * 4 + 1] + z[j * 4 + 2] + z[j * 4 + 3];
    }
    float mean2 = warp_sum(sum2) * (1.f / Dq);
    float vs2 = 0.f;
#pragma unroll
    for (int i = 0; i < 16; i++) {
        float dv = z[i] - mean2;
        vs2 += dv * dv;
    }
    float rs2 = rsqrtf(warp_sum(vs2) * (1.f / Dq) + 1e-5f);
#pragma unroll
    for (int j = 0; j < 4; j++) {
        int d = (lane + 32 * j) * 4;
        float4 gv = *(const float4*)&og[d];
        float4 bv = *(const float4*)&ob[d];
        float4 ov;
        ov.x = roundtf((z[j * 4 + 0] - mean2) * rs2 * gv.x + bv.x);
        ov.y = roundtf((z[j * 4 + 1] - mean2) * rs2 * gv.y + bv.y);
        ov.z = roundtf((z[j * 4 + 2] - mean2) * rs2 * gv.z + bv.z);
        ov.w = roundtf((z[j * 4 + 3] - mean2) * rs2 * gv.w + bv.w);
        *(float4*)&out[base + d] = ov;
    }
}

// ==========================================================================
extern "C" void kernel_launch(void* const* d_in, const int* in_sizes, int n_in,
                              void* d_out, int out_size) {
    const float* x       = (const float*)d_in[0];
    const int*   ts      = (const int*)d_in[1];
    const float* W_feat  = (const float*)d_in[2];
    const float* b_feat  = (const float*)d_in[3];
    const float* emb     = (const float*)d_in[4];
    const float* W_emb   = (const float*)d_in[5];
    const float* b_emb   = (const float*)d_in[6];
    const float* Wq      = (const float*)d_in[7];
    const float* bq      = (const float*)d_in[8];
    const float* Wk      = (const float*)d_in[9];
    const float* bk      = (const float*)d_in[10];
    const float* Wv      = (const float*)d_in[11];
    const float* bv      = (const float*)d_in[12];
    const float* Wo      = (const float*)d_in[13];
    const float* bo      = (const float*)d_in[14];
    const float* Wg      = (const float*)d_in[15];
    const float* bg      = (const float*)d_in[16];
    const float* Wu      = (const float*)d_in[17];
    const float* bu      = (const float*)d_in[18];
    const float* ln_g    = (const float*)d_in[19];
    const float* ln_b    = (const float*)d_in[20];
    const float* conv_w  = (const float*)d_in[21];
    const float* conv_b  = (const float*)d_in[22];
    const float* cn_g    = (const float*)d_in[23];
    const float* cn_b    = (const float*)d_in[24];
    const float* on_g    = (const float*)d_in[25];
    const float* on_b    = (const float*)d_in[26];
    const float* W_out   = (const float*)d_in[27];
    const float* b_out   = (const float*)d_in[28];
    float* out = (float*)d_out;

    float *cat, *h, *mem, *qkv, *ap, *a, *gu, *c, *c2, *wc;
    float *wqkvT, *bqkv, *wguT, *bgu, *woT, *wembT;
    cudaGetSymbolAddress((void**)&cat, g_cat);
    cudaGetSymbolAddress((void**)&h,   g_h);
    cudaGetSymbolAddress((void**)&mem, g_mem);
    cudaGetSymbolAddress((void**)&qkv, g_qkv);
    cudaGetSymbolAddress((void**)&ap,  g_ap);
    cudaGetSymbolAddress((void**)&a,   g_a);
    cudaGetSymbolAddress((void**)&gu,  g_gu);
    cudaGetSymbolAddress((void**)&c,   g_c);
    cudaGetSymbolAddress((void**)&c2,  g_c2);
    cudaGetSymbolAddress((void**)&wc,  g_wc);
    cudaGetSymbolAddress((void**)&wqkvT, g_wqkvT);
    cudaGetSymbolAddress((void**)&bqkv,  g_bqkv);
    cudaGetSymbolAddress((void**)&wguT,  g_wguT);
    cudaGetSymbolAddress((void**)&bgu,   g_bgu);
    cudaGetSymbolAddress((void**)&woT,   g_woT);
    cudaGetSymbolAddress((void**)&wembT, g_wembT);

    static int smem_set = 0;
    if (!smem_set) {
        cudaFuncSetAttribute(gemm_tc_kernel,
                             cudaFuncAttributeMaxDynamicSharedMemorySize, SMEM_TC);
        cudaFuncSetAttribute(attn_tc_kernel,
                             cudaFuncAttributeMaxDynamicSharedMemorySize, SMEM_ATT);
        cudaFuncSetAttribute(out_gemm_kernel,
                             cudaFuncAttributeMaxDynamicSharedMemorySize, OUT_SMEM);
        smem_set = 1;
    }

    // 0. merged weight pre-pack (one launch covers all segments)
    pack_all_kernel<<<(Lq * 2 * Dq * Dq + 255) / 256, 256>>>(
        Wq, Wk, Wv, bq, bk, bv, Wg, Wu, bg, bu, Wo, W_emb, conv_w,
        wqkvT, bqkv, wguT, bgu, woT, wembT, wc);

    // 1. embedding
    build_cat_kernel<<<NTq, 128>>>(x, ts, W_feat, b_feat, emb, cat);
    launch_tc(cat, cat, 8, 2 * FDq, 2 * FDq, wembT, 2 * FDq, b_emb, h, Dq,
              NTq, Dq, 2 * FDq, 1);

    // 2. layers (mem implicitly zero in layer 0)
    for (int l = 0; l < Lq; l++) {
        launch_tc(h, h, 16, Dq, Dq, wqkvT + (size_t)l * 3 * Dq * Dq, Dq,
                  bqkv + l * 3 * Dq, qkv, 3 * Dq, NTq, 3 * Dq, Dq, 1);

        attn_tc_kernel<<<dim3(NBq, Hq, Bq), 256, SMEM_ATT>>>(qkv, ap);

        launch_tc(ap, ap, 16, Dq, Dq, woT + (size_t)l * Dq * Dq, Dq,
                  bo + l * Dq, a, Dq, NTq, Dq, Dq, 1);

        if (l == 0)
            launch_tc(a, a, 16, Dq, Dq, wguT + (size_t)l * 2 * Dq * 2 * Dq, 2 * Dq,
                      bgu + l * 2 * Dq, gu, 2 * Dq, NTq, 2 * Dq, Dq, 0);
        else
            launch_tc(a, mem, 16, Dq, Dq, wguT + (size_t)l * 2 * Dq * 2 * Dq, 2 * Dq,
                      bgu + l * 2 * Dq, gu, 2 * Dq, NTq, 2 * Dq, 2 * Dq, 0);

        gate_ln_kernel<<<NTq / 8, 256>>>(a, gu, mem, ln_g + l * Dq,
                                         ln_b + l * Dq, h, l == 0);
    }

    // 3. temporal compression (conv as GEMM; weight transposed [512][2048])
    launch_tc(h, h, 64, CFq * Dq, CFq * Dq, wc, CFq * Dq, conv_b, c, Dq,
              Bq * NCq, Dq, CFq * Dq, 0);

    // 4. double LayerNorm
    double_ln_kernel<<<Bq * NCq / 8, 256>>>(c, cn_g, cn_b, on_g, on_b, c2);

    // 5. output projection (warp-per-row)
    out_gemm_kernel<<<Bq * NCq / 8, 256, OUT_SMEM>>>(c2, W_out, b_out, out);
}